// round 5
// baseline (speedup 1.0000x reference)
#include <cuda_runtime.h>
#include <cuda_bf16.h>
#include <math.h>
#include <stdint.h>

// ---------------- problem constants ----------------
#define NN    50000
#define HH    128
#define EE    1000000
#define FF1   147
#define FF2   21
#define GG    512
#define EPSV  1e-5f

// ---------------- device scratch (no allocs allowed) ----------------
__device__ float g_xh  [NN*HH];
__device__ float g_agg1[NN*HH];
__device__ float g_agg2[NN*HH];
__device__ float g_tmp [NN*HH];
__device__ float g_h1  [NN*HH];
__device__ float g_h2  [NN*HH];
__device__ float g_hA  [NN*HH];
__device__ float g_hB  [NN*HH];
__device__ float g_gsum[GG*HH];
__device__ float g_gvar[GG*HH];
__device__ float g_gcnt[GG];

// ================= warp-MMA helpers (baseline PTX, sm_80+) =================
__device__ __forceinline__ void mma_bf16(float d[4], const uint32_t a[4], const uint32_t b[2]) {
    asm volatile(
        "mma.sync.aligned.m16n8k16.row.col.f32.bf16.bf16.f32 "
        "{%0,%1,%2,%3}, {%4,%5,%6,%7}, {%8,%9}, {%0,%1,%2,%3};"
        : "+f"(d[0]), "+f"(d[1]), "+f"(d[2]), "+f"(d[3])
        : "r"(a[0]), "r"(a[1]), "r"(a[2]), "r"(a[3]), "r"(b[0]), "r"(b[1]));
}

__device__ __forceinline__ void split_bf16(float f, __nv_bfloat16& h, __nv_bfloat16& l) {
    h = __float2bfloat16_rn(f);
    l = __float2bfloat16_rn(f - __bfloat162float(h));
}

__device__ __forceinline__ void split_pack2(float f0, float f1, uint32_t& hi, uint32_t& lo) {
    __nv_bfloat16 h0, l0, h1, l1;
    split_bf16(f0, h0, l0);
    split_bf16(f1, h1, l1);
    hi = (uint32_t)__bfloat16_as_ushort(h0) | ((uint32_t)__bfloat16_as_ushort(h1) << 16);
    lo = (uint32_t)__bfloat16_as_ushort(l0) | ((uint32_t)__bfloat16_as_ushort(l1) << 16);
}

// load A-style fragment (16x16) from row-major bf16 smem [row][k], stride = elements
__device__ __forceinline__ void ldfrag4(const __nv_bfloat16* base, int stride,
                                        int row, int ko, int g, int tq, uint32_t a[4]) {
    a[0] = *reinterpret_cast<const uint32_t*>(&base[(row + g    ) * stride + ko     + tq*2]);
    a[1] = *reinterpret_cast<const uint32_t*>(&base[(row + g + 8) * stride + ko     + tq*2]);
    a[2] = *reinterpret_cast<const uint32_t*>(&base[(row + g    ) * stride + ko + 8 + tq*2]);
    a[3] = *reinterpret_cast<const uint32_t*>(&base[(row + g + 8) * stride + ko + 8 + tq*2]);
}
// load B fragment (16x8) from W^T stored row-major [n][k]
__device__ __forceinline__ void ldfrag2(const __nv_bfloat16* base, int stride,
                                        int n0, int ko, int g, int tq, uint32_t b[2]) {
    b[0] = *reinterpret_cast<const uint32_t*>(&base[(n0 + g) * stride + ko     + tq*2]);
    b[1] = *reinterpret_cast<const uint32_t*>(&base[(n0 + g) * stride + ko + 8 + tq*2]);
}

// ---------------- smem layout per F ----------------
template<int F> struct EL {
    static constexpr int KP  = (F + 15) & ~15;
    static constexpr int SA  = KP + 8;                 // bf16 elems per row (A, W1T)
    static constexpr int W1H = 0;
    static constexpr int W1L = W1H + 64 * SA * 2;
    static constexpr int W2H = W1L + 64 * SA * 2;
    static constexpr int W2L = W2H + 128 * 72 * 2;
    static constexpr int MIH = W2L + 128 * 72 * 2;
    static constexpr int MIL = MIH + 128 * 72 * 2;
    static constexpr int A1H = MIL + 128 * 72 * 2;
    static constexpr int A1L = A1H + 128 * SA * 2;
    static constexpr int ENDA = A1L + 128 * SA * 2;
    static constexpr bool REUSE = (2 * 128 * SA * 2) >= (128 * 132 * 4);
    static constexpr int OT  = REUSE ? A1H : ENDA;     // o_tile may alias A (A dead after GEMM1)
    static constexpr int IDX = REUSE ? ENDA : (OT + 128 * 132 * 4);
    static constexpr int TOT = IDX + 1024;
};

// ================= fused edge kernel (persistent, 128 edges/tile) =================
// mid[128,64] = feat_tile[128,F] @ w1[F,64]   (split-bf16 3-term HMMA)
// o[128,128]  = mid @ w2[64,128]              (split-bf16 3-term HMMA)
// agg[dst[e],c] += o[e,c] * xh[src[e],c]
template<int F>
__global__ void __launch_bounds__(256) edge_fused(
    const float* __restrict__ feat, const float* __restrict__ w1,
    const float* __restrict__ w2,   const float* __restrict__ xh,
    const int* __restrict__ src,    const int* __restrict__ dst,
    float* __restrict__ agg, int ntiles)
{
    using L = EL<F>;
    extern __shared__ char smem[];
    __nv_bfloat16* w1h = (__nv_bfloat16*)(smem + L::W1H);
    __nv_bfloat16* w1l = (__nv_bfloat16*)(smem + L::W1L);
    __nv_bfloat16* w2h = (__nv_bfloat16*)(smem + L::W2H);
    __nv_bfloat16* w2l = (__nv_bfloat16*)(smem + L::W2L);
    __nv_bfloat16* mih = (__nv_bfloat16*)(smem + L::MIH);
    __nv_bfloat16* mil = (__nv_bfloat16*)(smem + L::MIL);
    __nv_bfloat16* a1h = (__nv_bfloat16*)(smem + L::A1H);
    __nv_bfloat16* a1l = (__nv_bfloat16*)(smem + L::A1L);
    float*         ot  = (float*)        (smem + L::OT);
    int*           sidx= (int*)          (smem + L::IDX);   // [0..127]=src, [128..255]=dst

    const int tid  = threadIdx.x;
    const int wid  = tid >> 5, lane = tid & 31;
    const int g    = lane >> 2, tq = lane & 3;

    // zero everything once (weight pads must be 0; A pads re-zeroed every tile below)
    for (int i = tid; i < L::TOT / 4; i += 256)
        reinterpret_cast<uint32_t*>(smem)[i] = 0;
    __syncthreads();

    // stage weights transposed + split. w1 gmem [F][64], w2 gmem [64][128]
    for (int i = tid; i < F * 64; i += 256) {
        int k = i >> 6, n = i & 63;
        __nv_bfloat16 h, l; split_bf16(w1[i], h, l);
        w1h[n * L::SA + k] = h;  w1l[n * L::SA + k] = l;
    }
    for (int i = tid; i < 64 * 128; i += 256) {
        int k = i >> 7, n = i & 127;
        __nv_bfloat16 h, l; split_bf16(w2[i], h, l);
        w2h[n * 72 + k] = h;  w2l[n * 72 + k] = l;
    }
    __syncthreads();

    const int wm = wid & 3;          // warp M index (0..3) -> rows wm*32..+31
    const int wn = wid >> 2;         // warp N index (0..1)

    for (int t = blockIdx.x; t < ntiles; t += gridDim.x) {
        const int e0  = t * 128;
        const int cnt = min(128, EE - e0);

        // ---- stage A tile split over the FULL padded K extent ----
        // k in [F, KP) written as 0 every tile: when o_tile aliases this region
        // (F=147), GEMM2's stores clobber the pads; re-zeroing here restores the
        // invariant GEMM1 relies on. (Root cause of the R4 NaN.)
        {
            const float* fb = feat + (size_t)e0 * F;
            for (int i = tid; i < cnt * L::KP; i += 256) {
                int e = i / L::KP, k = i - e * L::KP;
                float v = (k < F) ? fb[e * F + k] : 0.f;
                __nv_bfloat16 h, l; split_bf16(v, h, l);
                a1h[e * L::SA + k] = h;  a1l[e * L::SA + k] = l;
            }
            if (tid < cnt) { sidx[tid] = src[e0 + tid]; sidx[128 + tid] = dst[e0 + tid]; }
        }
        __syncthreads();

        // ---- GEMM1: [128, KP] x [KP, 64] -> mid ----
        {
            const int mo = wm * 32, no = wn * 32;
            float acc[2][4][4];
            #pragma unroll
            for (int a = 0; a < 2; ++a)
                #pragma unroll
                for (int b = 0; b < 4; ++b)
                    #pragma unroll
                    for (int c = 0; c < 4; ++c) acc[a][b][c] = 0.f;

            #pragma unroll
            for (int ko = 0; ko < L::KP; ko += 16) {
                uint32_t Ah[2][4], Al[2][4];
                #pragma unroll
                for (int mt = 0; mt < 2; ++mt) {
                    ldfrag4(a1h, L::SA, mo + mt*16, ko, g, tq, Ah[mt]);
                    ldfrag4(a1l, L::SA, mo + mt*16, ko, g, tq, Al[mt]);
                }
                #pragma unroll
                for (int nt = 0; nt < 4; ++nt) {
                    uint32_t Bh[2], Bl[2];
                    ldfrag2(w1h, L::SA, no + nt*8, ko, g, tq, Bh);
                    ldfrag2(w1l, L::SA, no + nt*8, ko, g, tq, Bl);
                    #pragma unroll
                    for (int mt = 0; mt < 2; ++mt) {
                        mma_bf16(acc[mt][nt], Ah[mt], Bh);
                        mma_bf16(acc[mt][nt], Ah[mt], Bl);
                        mma_bf16(acc[mt][nt], Al[mt], Bh);
                    }
                }
            }
            // split-store mid
            #pragma unroll
            for (int mt = 0; mt < 2; ++mt)
                #pragma unroll
                for (int nt = 0; nt < 4; ++nt) {
                    int r0 = mo + mt*16 + g, col = no + nt*8 + tq*2;
                    uint32_t hi, lo;
                    split_pack2(acc[mt][nt][0], acc[mt][nt][1], hi, lo);
                    *reinterpret_cast<uint32_t*>(&mih[r0*72 + col]) = hi;
                    *reinterpret_cast<uint32_t*>(&mil[r0*72 + col]) = lo;
                    split_pack2(acc[mt][nt][2], acc[mt][nt][3], hi, lo);
                    *reinterpret_cast<uint32_t*>(&mih[(r0+8)*72 + col]) = hi;
                    *reinterpret_cast<uint32_t*>(&mil[(r0+8)*72 + col]) = lo;
                }
        }
        __syncthreads();

        // ---- GEMM2: [128, 64] x [64, 128] -> o ----
        {
            const int mo = wm * 32, no = wn * 64;
            float acc[2][8][4];
            #pragma unroll
            for (int a = 0; a < 2; ++a)
                #pragma unroll
                for (int b = 0; b < 8; ++b)
                    #pragma unroll
                    for (int c = 0; c < 4; ++c) acc[a][b][c] = 0.f;

            #pragma unroll
            for (int ko = 0; ko < 64; ko += 16) {
                uint32_t Ah[2][4], Al[2][4];
                #pragma unroll
                for (int mt = 0; mt < 2; ++mt) {
                    ldfrag4(mih, 72, mo + mt*16, ko, g, tq, Ah[mt]);
                    ldfrag4(mil, 72, mo + mt*16, ko, g, tq, Al[mt]);
                }
                #pragma unroll
                for (int nt = 0; nt < 8; ++nt) {
                    uint32_t Bh[2], Bl[2];
                    ldfrag2(w2h, 72, no + nt*8, ko, g, tq, Bh);
                    ldfrag2(w2l, 72, no + nt*8, ko, g, tq, Bl);
                    #pragma unroll
                    for (int mt = 0; mt < 2; ++mt) {
                        mma_bf16(acc[mt][nt], Ah[mt], Bh);
                        mma_bf16(acc[mt][nt], Ah[mt], Bl);
                        mma_bf16(acc[mt][nt], Al[mt], Bh);
                    }
                }
            }
            // store o tile (f32, stride 132)
            #pragma unroll
            for (int mt = 0; mt < 2; ++mt)
                #pragma unroll
                for (int nt = 0; nt < 8; ++nt) {
                    int r0 = mo + mt*16 + g, col = no + nt*8 + tq*2;
                    *reinterpret_cast<float2*>(&ot[r0*132 + col]) =
                        make_float2(acc[mt][nt][0], acc[mt][nt][1]);
                    *reinterpret_cast<float2*>(&ot[(r0+8)*132 + col]) =
                        make_float2(acc[mt][nt][2], acc[mt][nt][3]);
                }
        }
        __syncthreads();

        // ---- epilogue: gather xh[src], scatter-atomic into agg[dst] ----
        {
            const int c = tid & 127, eh = tid >> 7;
            for (int e = eh; e < cnt; e += 2) {
                int s = sidx[e], d = sidx[128 + e];
                float v = ot[e * 132 + c] * xh[(size_t)s * 128 + c];
                atomicAdd(&agg[(size_t)d * 128 + c], v);
            }
        }
        __syncthreads();
    }
}

// ---------------- zero init ----------------
__global__ void zero_bufs_kernel() {
    int idx = blockIdx.x * blockDim.x + threadIdx.x;
    if (idx < NN*HH) { g_agg1[idx] = 0.f; g_agg2[idx] = 0.f; }
    if (idx < GG*HH) { g_gsum[idx] = 0.f; g_gvar[idx] = 0.f; }
    if (idx < GG)    { g_gcnt[idx] = 0.f; }
}

// ---------------- generic node GEMM (proven FFMA path) ----------------
template<bool HAS_A2, bool ACT, bool HAS_RES>
__global__ void __launch_bounds__(256) node_gemm(
    const float* __restrict__ A,  const float* __restrict__ W,
    const float* __restrict__ A2, const float* __restrict__ W2,
    const float* __restrict__ bias, const float* __restrict__ res,
    float* __restrict__ out, int nrows)
{
    extern __shared__ float sm[];
    float* sW  = sm;
    float* sW2 = HAS_A2 ? sm + 16384 : (float*)0;
    float* rT  = sm + (HAS_A2 ? 32768 : 16384);
    float* rT2 = HAS_A2 ? rT + 128*20 : (float*)0;

    const int tid = threadIdx.x;
    for (int i = tid; i < 16384; i += 256) {
        sW[i] = W[i];
        if (HAS_A2) sW2[i] = W2[i];
    }
    const int row_base = blockIdx.x * 16;
    for (int idx = tid; idx < 16*128; idx += 256) {
        int node = idx >> 7, k = idx & 127;
        int r = row_base + node;
        rT[k*20 + node] = (r < nrows) ? A[(size_t)r*128 + k] : 0.f;
        if (HAS_A2) rT2[k*20 + node] = (r < nrows) ? A2[(size_t)r*128 + k] : 0.f;
    }
    __syncthreads();

    const int c = tid & 127;
    const int g = tid >> 7;
    float acc[8] = {0,0,0,0,0,0,0,0};

    #pragma unroll 4
    for (int k = 0; k < 128; ++k) {
        float w = sW[k*128 + c];
        float4 a0 = *reinterpret_cast<const float4*>(&rT[k*20 + g*8]);
        float4 a1 = *reinterpret_cast<const float4*>(&rT[k*20 + g*8 + 4]);
        acc[0] += a0.x*w; acc[1] += a0.y*w; acc[2] += a0.z*w; acc[3] += a0.w*w;
        acc[4] += a1.x*w; acc[5] += a1.y*w; acc[6] += a1.z*w; acc[7] += a1.w*w;
        if (HAS_A2) {
            float w2 = sW2[k*128 + c];
            float4 b0 = *reinterpret_cast<const float4*>(&rT2[k*20 + g*8]);
            float4 b1 = *reinterpret_cast<const float4*>(&rT2[k*20 + g*8 + 4]);
            acc[0] += b0.x*w2; acc[1] += b0.y*w2; acc[2] += b0.z*w2; acc[3] += b0.w*w2;
            acc[4] += b1.x*w2; acc[5] += b1.y*w2; acc[6] += b1.z*w2; acc[7] += b1.w*w2;
        }
    }

    const float bv = bias[c];
    #pragma unroll
    for (int i = 0; i < 8; ++i) {
        int r = row_base + g*8 + i;
        if (r < nrows) {
            float v = acc[i] + bv;
            if (ACT) v = v / (1.f + expf(-v));
            if (HAS_RES) v += res[(size_t)r*128 + c];
            out[(size_t)r*128 + c] = v;
        }
    }
}

// ---------------- GraphNorm kernels ----------------
__global__ void gn_accum(const float* __restrict__ h, const int* __restrict__ batch) {
    int idx = blockIdx.x * blockDim.x + threadIdx.x;
    if (idx >= NN*HH) return;
    int n = idx >> 7, c = idx & 127;
    int b = batch[n];
    atomicAdd(&g_gsum[b*128 + c], h[idx]);
    if (c == 0) atomicAdd(&g_gcnt[b], 1.f);
}
__global__ void gn_mean() {
    int idx = blockIdx.x * blockDim.x + threadIdx.x;
    if (idx >= GG*HH) return;
    int g = idx >> 7;
    g_gsum[idx] /= fmaxf(g_gcnt[g], 1.f);
}
__global__ void gn_center(const float* __restrict__ h, const int* __restrict__ batch,
                          const float* __restrict__ ms, float* __restrict__ out) {
    int idx = blockIdx.x * blockDim.x + threadIdx.x;
    if (idx >= NN*HH) return;
    int n = idx >> 7, c = idx & 127;
    int b = batch[n];
    float o = h[idx] - g_gsum[b*128 + c] * ms[c];
    out[idx] = o;
    atomicAdd(&g_gvar[b*128 + c], o*o);
}
__global__ void gn_inv() {
    int idx = blockIdx.x * blockDim.x + threadIdx.x;
    if (idx >= GG*HH) return;
    int g = idx >> 7;
    g_gvar[idx] = rsqrtf(g_gvar[idx] / fmaxf(g_gcnt[g], 1.f) + EPSV);
}
__global__ void gn_apply(const float* __restrict__ cent, const int* __restrict__ batch,
                         const float* __restrict__ nw, const float* __restrict__ nb,
                         float* __restrict__ out) {
    int idx = blockIdx.x * blockDim.x + threadIdx.x;
    if (idx >= NN*HH) return;
    int n = idx >> 7, c = idx & 127;
    int b = batch[n];
    out[idx] = nw[c] * cent[idx] * g_gvar[b*128 + c] + nb[c];
}

// ---------------- host launcher ----------------
static inline void set_smem(const void* f, int bytes) {
    cudaFuncSetAttribute(f, cudaFuncAttributeMaxDynamicSharedMemorySize, bytes);
}

extern "C" void kernel_launch(void* const* d_in, const int* in_sizes, int n_in,
                              void* d_out, int out_size) {
    (void)in_sizes; (void)n_in; (void)out_size;

    const float* x          = (const float*)d_in[0];
    const float* feature1   = (const float*)d_in[1];
    const float* feature2   = (const float*)d_in[2];
    const int*   edge_index = (const int*)  d_in[3];
    const int*   batch      = (const int*)  d_in[4];
    const float* lin_w      = (const float*)d_in[5];
    const float* lin_b      = (const float*)d_in[6];
    const float* f1_w1      = (const float*)d_in[7];
    const float* f1_w2      = (const float*)d_in[8];
    const float* f2_w1      = (const float*)d_in[9];
    const float* f2_w2      = (const float*)d_in[10];
    const float* c1_rel_w   = (const float*)d_in[11];
    const float* c1_rel_b   = (const float*)d_in[12];
    const float* c1_root_w  = (const float*)d_in[13];
    const float* c2_rel_w   = (const float*)d_in[14];
    const float* c2_rel_b   = (const float*)d_in[15];
    const float* c2_root_w  = (const float*)d_in[16];
    const float* lin1_w     = (const float*)d_in[17];
    const float* lin1_b     = (const float*)d_in[18];
    const float* lin2_w     = (const float*)d_in[19];
    const float* lin2_b     = (const float*)d_in[20];
    const float* lincat_w   = (const float*)d_in[21];
    const float* lincat_b   = (const float*)d_in[22];
    const float* norm_w     = (const float*)d_in[23];
    const float* norm_b     = (const float*)d_in[24];
    const float* norm_ms    = (const float*)d_in[25];
    const float* lins_w     = (const float*)d_in[26];
    const float* lins_b     = (const float*)d_in[27];
    const float* final_w    = (const float*)d_in[28];
    const float* final_b    = (const float*)d_in[29];
    float* out = (float*)d_out;

    const int* src = edge_index;
    const int* dst = edge_index + EE;

    float *xh, *agg1, *agg2, *tmp, *h1, *h2, *hA, *hB;
    cudaGetSymbolAddress((void**)&xh,   g_xh);
    cudaGetSymbolAddress((void**)&agg1, g_agg1);
    cudaGetSymbolAddress((void**)&agg2, g_agg2);
    cudaGetSymbolAddress((void**)&tmp,  g_tmp);
    cudaGetSymbolAddress((void**)&h1,   g_h1);
    cudaGetSymbolAddress((void**)&h2,   g_h2);
    cudaGetSymbolAddress((void**)&hA,   g_hA);
    cudaGetSymbolAddress((void**)&hB,   g_hB);

    const int NG1 = (16384 + 128*20) * 4;
    const int NG2 = (32768 + 2*128*20) * 4;

    set_smem((const void*)node_gemm<false,true ,false>, NG1);
    set_smem((const void*)node_gemm<false,true ,true >, NG1);
    set_smem((const void*)node_gemm<false,false,false>, NG1);
    set_smem((const void*)node_gemm<true ,false,false>, NG2);
    set_smem((const void*)node_gemm<true ,false,true >, NG2);
    set_smem((const void*)edge_fused<FF1>, EL<FF1>::TOT);
    set_smem((const void*)edge_fused<FF2>, EL<FF2>::TOT);

    const int NG_GRID = (NN + 15) / 16;
    const int EL_GRID = (NN*HH + 255) / 256;
    const int GH_GRID = (GG*HH + 255) / 256;
    const int NT      = (EE + 127) / 128;   // 7813

    // 0) zero accumulators
    zero_bufs_kernel<<<EL_GRID, 256>>>();

    // 1) xh = swish(x @ lin_w + lin_b)
    node_gemm<false,true,false><<<NG_GRID, 256, NG1>>>(
        x, lin_w, nullptr, nullptr, lin_b, nullptr, xh, NN);

    // 2) fused edge messages via HMMA tensor cores
    edge_fused<FF1><<<148, 256, EL<FF1>::TOT>>>(feature1, f1_w1, f1_w2, xh, src, dst, agg1, NT);
    edge_fused<FF2><<<148, 256, EL<FF2>::TOT>>>(feature2, f2_w1, f2_w2, xh, src, dst, agg2, NT);

    // 3) conv1
    node_gemm<true,false,false><<<NG_GRID, 256, NG2>>>(
        agg1, c1_rel_w, xh, c1_root_w, c1_rel_b, nullptr, tmp, NN);
    node_gemm<false,true,false><<<NG_GRID, 256, NG1>>>(
        tmp, lin1_w, nullptr, nullptr, lin1_b, nullptr, h1, NN);

    // 4) conv2
    node_gemm<true,false,false><<<NG_GRID, 256, NG2>>>(
        agg2, c2_rel_w, xh, c2_root_w, c2_rel_b, nullptr, tmp, NN);
    node_gemm<false,true,false><<<NG_GRID, 256, NG1>>>(
        tmp, lin2_w, nullptr, nullptr, lin2_b, nullptr, h2, NN);

    // 5) hA = h1@Wtop + h2@Wbot + lincat_b + xh
    node_gemm<true,false,true><<<NG_GRID, 256, NG2>>>(
        h1, lincat_w, h2, lincat_w + 128*128, lincat_b, xh, hA, NN);

    // 6) residual stack
    node_gemm<false,true,true><<<NG_GRID, 256, NG1>>>(
        hA, lins_w + 0*16384, nullptr, nullptr, lins_b + 0*128, hA, hB, NN);
    node_gemm<false,true,true><<<NG_GRID, 256, NG1>>>(
        hB, lins_w + 1*16384, nullptr, nullptr, lins_b + 1*128, hB, hA, NN);
    node_gemm<false,true,true><<<NG_GRID, 256, NG1>>>(
        hA, lins_w + 2*16384, nullptr, nullptr, lins_b + 2*128, hA, hB, NN);

    // 7) GraphNorm on hB
    gn_accum <<<EL_GRID, 256>>>(hB, batch);
    gn_mean  <<<GH_GRID, 256>>>();
    gn_center<<<EL_GRID, 256>>>(hB, batch, norm_ms, h1);
    gn_inv   <<<GH_GRID, 256>>>();
    gn_apply <<<EL_GRID, 256>>>(h1, batch, norm_w, norm_b, hA);

    // 8) out = hA @ final_w + final_b
    node_gemm<false,false,false><<<NG_GRID, 256, NG1>>>(
        hA, final_w, nullptr, nullptr, final_b, nullptr, out, NN);
}

// round 7
// speedup vs baseline: 2.2417x; 2.2417x over previous
#include <cuda_runtime.h>
#include <cuda_bf16.h>
#include <math.h>
#include <stdint.h>

// ---------------- problem constants ----------------
#define NN    50000
#define HH    128
#define EE    1000000
#define FF1   147
#define FF2   21
#define GG    512
#define EPSV  1e-5f

// ---------------- device scratch (no allocs allowed) ----------------
__device__ float g_xh  [NN*HH];
__device__ float g_agg1[NN*HH];
__device__ float g_agg2[NN*HH];
__device__ float g_tmp [NN*HH];
__device__ float g_h1  [NN*HH];
__device__ float g_h2  [NN*HH];
__device__ float g_hA  [NN*HH];
__device__ float g_hB  [NN*HH];
__device__ float g_gsum[GG*HH];
__device__ float g_gvar[GG*HH];
__device__ float g_gcnt[GG];

// ================= warp-MMA helpers (baseline PTX, sm_80+) =================
__device__ __forceinline__ void mma_bf16(float d[4], const uint32_t a[4], const uint32_t b[2]) {
    asm volatile(
        "mma.sync.aligned.m16n8k16.row.col.f32.bf16.bf16.f32 "
        "{%0,%1,%2,%3}, {%4,%5,%6,%7}, {%8,%9}, {%0,%1,%2,%3};"
        : "+f"(d[0]), "+f"(d[1]), "+f"(d[2]), "+f"(d[3])
        : "r"(a[0]), "r"(a[1]), "r"(a[2]), "r"(a[3]), "r"(b[0]), "r"(b[1]));
}

__device__ __forceinline__ void split_bf16(float f, __nv_bfloat16& h, __nv_bfloat16& l) {
    h = __float2bfloat16_rn(f);
    l = __float2bfloat16_rn(f - __bfloat162float(h));
}

__device__ __forceinline__ void split_pack2(float f0, float f1, uint32_t& hi, uint32_t& lo) {
    __nv_bfloat16 h0, l0, h1, l1;
    split_bf16(f0, h0, l0);
    split_bf16(f1, h1, l1);
    hi = (uint32_t)__bfloat16_as_ushort(h0) | ((uint32_t)__bfloat16_as_ushort(h1) << 16);
    lo = (uint32_t)__bfloat16_as_ushort(l0) | ((uint32_t)__bfloat16_as_ushort(l1) << 16);
}

// A fragment (16x16) from row-major bf16 smem [row][k]
__device__ __forceinline__ void ldfrag4(const __nv_bfloat16* base, int stride,
                                        int row, int ko, int g, int tq, uint32_t a[4]) {
    a[0] = *reinterpret_cast<const uint32_t*>(&base[(row + g    ) * stride + ko     + tq*2]);
    a[1] = *reinterpret_cast<const uint32_t*>(&base[(row + g + 8) * stride + ko     + tq*2]);
    a[2] = *reinterpret_cast<const uint32_t*>(&base[(row + g    ) * stride + ko + 8 + tq*2]);
    a[3] = *reinterpret_cast<const uint32_t*>(&base[(row + g + 8) * stride + ko + 8 + tq*2]);
}
// B fragment (16x8) from W^T stored row-major [n][k]
__device__ __forceinline__ void ldfrag2(const __nv_bfloat16* base, int stride,
                                        int n0, int ko, int g, int tq, uint32_t b[2]) {
    b[0] = *reinterpret_cast<const uint32_t*>(&base[(n0 + g) * stride + ko     + tq*2]);
    b[1] = *reinterpret_cast<const uint32_t*>(&base[(n0 + g) * stride + ko + 8 + tq*2]);
}

// ---------------- edge kernel smem layout ----------------
template<int F> struct EL {
    static constexpr int KP  = (F + 15) & ~15;
    static constexpr int SA  = KP + 8;                 // bf16 elems/row (A, W1T)
    static constexpr int W1H = 0;
    static constexpr int W1L = W1H + 64 * SA * 2;
    static constexpr int W2H = W1L + 64 * SA * 2;
    static constexpr int W2L = W2H + 128 * 72 * 2;
    static constexpr int MIH = W2L + 128 * 72 * 2;     // mid hi; o-halves alias here
    static constexpr int MIL = MIH + 128 * 72 * 2;
    static constexpr int A1H = MIL + 128 * 72 * 2;
    static constexpr int A1L = A1H + 128 * SA * 2;
    static constexpr int IDX = A1L + 128 * SA * 2;
    static constexpr int TOT = IDX + 1024;
};

// ================= fused edge kernel =================
// mid[128,64] = feat[128,F] @ w1 ; o[128,128] = mid @ w2 ;
// agg[dst[e],c] += o[e,c] * xh[src[e],c]
// o staged in two 64-row halves into the dead MI region.
template<int F, int MINB>
__global__ void __launch_bounds__(256, MINB) edge_fused(
    const float* __restrict__ feat, const float* __restrict__ w1,
    const float* __restrict__ w2,   const float* __restrict__ xh,
    const int* __restrict__ src,    const int* __restrict__ dst,
    float* __restrict__ agg, int ntiles)
{
    using L = EL<F>;
    extern __shared__ char smem[];
    __nv_bfloat16* w1h = (__nv_bfloat16*)(smem + L::W1H);
    __nv_bfloat16* w1l = (__nv_bfloat16*)(smem + L::W1L);
    __nv_bfloat16* w2h = (__nv_bfloat16*)(smem + L::W2H);
    __nv_bfloat16* w2l = (__nv_bfloat16*)(smem + L::W2L);
    __nv_bfloat16* mih = (__nv_bfloat16*)(smem + L::MIH);
    __nv_bfloat16* mil = (__nv_bfloat16*)(smem + L::MIL);
    __nv_bfloat16* a1h = (__nv_bfloat16*)(smem + L::A1H);
    __nv_bfloat16* a1l = (__nv_bfloat16*)(smem + L::A1L);
    float*         ob  = (float*)        (smem + L::MIH);   // 64 x 132 f32 (aliases MI)
    int*           sidx= (int*)          (smem + L::IDX);

    const int tid  = threadIdx.x;
    const int wid  = tid >> 5, lane = tid & 31;
    const int g    = lane >> 2, tq = lane & 3;
    const int wm   = wid & 3, wn = wid >> 2;

    // zero once: weight pads + A pads must be 0 (never clobbered afterwards)
    for (int i = tid; i < L::TOT / 4; i += 256)
        reinterpret_cast<uint32_t*>(smem)[i] = 0;
    __syncthreads();

    // stage weights transposed + split. w1 gmem [F][64], w2 gmem [64][128]
    for (int i = tid; i < F * 64; i += 256) {
        int k = i >> 6, n = i & 63;
        __nv_bfloat16 h, l; split_bf16(w1[i], h, l);
        w1h[n * L::SA + k] = h;  w1l[n * L::SA + k] = l;
    }
    for (int i = tid; i < 64 * 128; i += 256) {
        int k = i >> 7, n = i & 127;
        __nv_bfloat16 h, l; split_bf16(w2[i], h, l);
        w2h[n * 72 + k] = h;  w2l[n * 72 + k] = l;
    }
    __syncthreads();

    for (int t = blockIdx.x; t < ntiles; t += gridDim.x) {
        const int e0  = t * 128;
        const int cnt = min(128, EE - e0);

        // ---- stage A split (k<F only; pads stay zero) ----
        {
            const float* fb = feat + (size_t)e0 * F;
            for (int i = tid; i < cnt * F; i += 256) {
                int e = i / F, k = i - e * F;
                __nv_bfloat16 h, l; split_bf16(fb[i], h, l);
                a1h[e * L::SA + k] = h;  a1l[e * L::SA + k] = l;
            }
            if (tid < cnt) { sidx[tid] = src[e0 + tid]; sidx[128 + tid] = dst[e0 + tid]; }
        }
        __syncthreads();

        // ---- GEMM1 ----
        {
            const int mo = wm * 32, no = wn * 32;
            float acc[2][4][4];
            #pragma unroll
            for (int a = 0; a < 2; ++a)
                #pragma unroll
                for (int b = 0; b < 4; ++b)
                    #pragma unroll
                    for (int c = 0; c < 4; ++c) acc[a][b][c] = 0.f;

            #pragma unroll
            for (int ko = 0; ko < L::KP; ko += 16) {
                uint32_t Ah[2][4], Al[2][4];
                #pragma unroll
                for (int mt = 0; mt < 2; ++mt) {
                    ldfrag4(a1h, L::SA, mo + mt*16, ko, g, tq, Ah[mt]);
                    ldfrag4(a1l, L::SA, mo + mt*16, ko, g, tq, Al[mt]);
                }
                #pragma unroll
                for (int nt = 0; nt < 4; ++nt) {
                    uint32_t Bh[2], Bl[2];
                    ldfrag2(w1h, L::SA, no + nt*8, ko, g, tq, Bh);
                    ldfrag2(w1l, L::SA, no + nt*8, ko, g, tq, Bl);
                    #pragma unroll
                    for (int mt = 0; mt < 2; ++mt) {
                        mma_bf16(acc[mt][nt], Ah[mt], Bh);
                        mma_bf16(acc[mt][nt], Ah[mt], Bl);
                        mma_bf16(acc[mt][nt], Al[mt], Bh);
                    }
                }
            }
            #pragma unroll
            for (int mt = 0; mt < 2; ++mt)
                #pragma unroll
                for (int nt = 0; nt < 4; ++nt) {
                    int r0 = mo + mt*16 + g, col = no + nt*8 + tq*2;
                    uint32_t hi, lo;
                    split_pack2(acc[mt][nt][0], acc[mt][nt][1], hi, lo);
                    *reinterpret_cast<uint32_t*>(&mih[r0*72 + col]) = hi;
                    *reinterpret_cast<uint32_t*>(&mil[r0*72 + col]) = lo;
                    split_pack2(acc[mt][nt][2], acc[mt][nt][3], hi, lo);
                    *reinterpret_cast<uint32_t*>(&mih[(r0+8)*72 + col]) = hi;
                    *reinterpret_cast<uint32_t*>(&mil[(r0+8)*72 + col]) = lo;
                }
        }
        __syncthreads();

        // ---- GEMM2 (K=64) ----
        float acc[2][8][4];
        {
            const int mo = wm * 32, no = wn * 64;
            #pragma unroll
            for (int a = 0; a < 2; ++a)
                #pragma unroll
                for (int b = 0; b < 8; ++b)
                    #pragma unroll
                    for (int c = 0; c < 4; ++c) acc[a][b][c] = 0.f;

            #pragma unroll
            for (int ko = 0; ko < 64; ko += 16) {
                uint32_t Ah[2][4], Al[2][4];
                #pragma unroll
                for (int mt = 0; mt < 2; ++mt) {
                    ldfrag4(mih, 72, mo + mt*16, ko, g, tq, Ah[mt]);
                    ldfrag4(mil, 72, mo + mt*16, ko, g, tq, Al[mt]);
                }
                #pragma unroll
                for (int nt = 0; nt < 8; ++nt) {
                    uint32_t Bh[2], Bl[2];
                    ldfrag2(w2h, 72, no + nt*8, ko, g, tq, Bh);
                    ldfrag2(w2l, 72, no + nt*8, ko, g, tq, Bl);
                    #pragma unroll
                    for (int mt = 0; mt < 2; ++mt) {
                        mma_bf16(acc[mt][nt], Ah[mt], Bh);
                        mma_bf16(acc[mt][nt], Ah[mt], Bl);
                        mma_bf16(acc[mt][nt], Al[mt], Bh);
                    }
                }
            }
        }
        __syncthreads();   // all MI reads done -> MI region reusable as o-buffer

        // ---- per half: store o rows into ob, then coalesced epilogue ----
        #pragma unroll
        for (int half = 0; half < 2; ++half) {
            if ((wm >> 1) == half) {          // wm 0,1 own rows 0..63; wm 2,3 rows 64..127
                const int mo = wm * 32, no = wn * 64;
                #pragma unroll
                for (int mt = 0; mt < 2; ++mt)
                    #pragma unroll
                    for (int nt = 0; nt < 8; ++nt) {
                        int rl = mo + mt*16 + g - half*64, col = no + nt*8 + tq*2;
                        *reinterpret_cast<float2*>(&ob[rl*132 + col]) =
                            make_float2(acc[mt][nt][0], acc[mt][nt][1]);
                        *reinterpret_cast<float2*>(&ob[(rl+8)*132 + col]) =
                            make_float2(acc[mt][nt][2], acc[mt][nt][3]);
                    }
            }
            __syncthreads();
            const int c = tid & 127, eh = tid >> 7;
            const int lim = min(cnt - half*64, 64);
            for (int e = eh; e < lim; e += 2) {
                int eg = half*64 + e;
                int s = sidx[eg], d = sidx[128 + eg];
                float v = ob[e * 132 + c] * xh[(size_t)s * 128 + c];
                atomicAdd(&agg[(size_t)d * 128 + c], v);
            }
            __syncthreads();
        }
    }
}

// ================= node GEMM on HMMA =================
// out[r,c] = epi( A[r,:]@W[:,c] (+ A2[r,:]@W2[:,c]) + bias[c] ), 512 thr, persistent
// smem planes: w1h, w1l, [w2h, w2l], ah, al  (+ bias) -> 4 or 6 planes of WS bytes.
template<bool HAS_A2, bool ACT, bool HAS_RES>
__global__ void __launch_bounds__(512) node_hmma(
    const float* __restrict__ A,  const float* __restrict__ W,
    const float* __restrict__ A2, const float* __restrict__ W2,
    const float* __restrict__ bias, const float* __restrict__ res,
    float* __restrict__ out, int nrows, int ntiles)
{
    constexpr int WS  = 128 * 136 * 2;     // 34816 bytes (one split plane)
    constexpr int W1H = 0;
    constexpr int W1L = WS;
    constexpr int W2Ho = 2 * WS;           // only if HAS_A2
    constexpr int W2Lo = 3 * WS;
    constexpr int AH  = HAS_A2 ? 4 * WS : 2 * WS;
    constexpr int ALo = AH + WS;
    constexpr int BI  = ALo + WS;
    extern __shared__ char smem[];
    __nv_bfloat16* wh  = (__nv_bfloat16*)(smem + W1H);
    __nv_bfloat16* wl  = (__nv_bfloat16*)(smem + W1L);
    __nv_bfloat16* w2h = (__nv_bfloat16*)(smem + W2Ho);
    __nv_bfloat16* w2l = (__nv_bfloat16*)(smem + W2Lo);
    __nv_bfloat16* ah  = (__nv_bfloat16*)(smem + AH);
    __nv_bfloat16* al  = (__nv_bfloat16*)(smem + ALo);
    float*         bs  = (float*)        (smem + BI);

    const int tid = threadIdx.x;
    const int wid = tid >> 5, lane = tid & 31;
    const int g = lane >> 2, tq = lane & 3;
    const int wm = wid & 7, wn = wid >> 3;       // rows wm*16.. ; cols wn*64..

    // stage weights (transposed, split) + bias
    for (int i = tid; i < 128 * 128; i += 512) {
        int k = i >> 7, n = i & 127;
        __nv_bfloat16 h, l; split_bf16(W[i], h, l);
        wh[n * 136 + k] = h;  wl[n * 136 + k] = l;
        if (HAS_A2) {
            split_bf16(W2[i], h, l);
            w2h[n * 136 + k] = h;  w2l[n * 136 + k] = l;
        }
    }
    if (tid < 128) bs[tid] = bias[tid];
    __syncthreads();

    const int mo = wm * 16, no = wn * 64;

    for (int t = blockIdx.x; t < ntiles; t += gridDim.x) {
        const int rb = t * 128;

        // stage A tile (zeros for rows beyond nrows)
        for (int i = tid; i < 128 * 128; i += 512) {
            int e = i >> 7, k = i & 127;
            int r = rb + e;
            float v = (r < nrows) ? A[(size_t)r * 128 + k] : 0.f;
            __nv_bfloat16 h, l; split_bf16(v, h, l);
            ah[e * 136 + k] = h;  al[e * 136 + k] = l;
        }
        __syncthreads();

        float acc[8][4];
        #pragma unroll
        for (int b = 0; b < 8; ++b)
            #pragma unroll
            for (int c = 0; c < 4; ++c) acc[b][c] = 0.f;

        #pragma unroll
        for (int ko = 0; ko < 128; ko += 16) {
            uint32_t Ah[4], Al[4];
            ldfrag4(ah, 136, mo, ko, g, tq, Ah);
            ldfrag4(al, 136, mo, ko, g, tq, Al);
            #pragma unroll
            for (int nt = 0; nt < 8; ++nt) {
                uint32_t Bh[2], Bl[2];
                ldfrag2(wh, 136, no + nt*8, ko, g, tq, Bh);
                ldfrag2(wl, 136, no + nt*8, ko, g, tq, Bl);
                mma_bf16(acc[nt], Ah, Bh);
                mma_bf16(acc[nt], Ah, Bl);
                mma_bf16(acc[nt], Al, Bh);
            }
        }

        if (HAS_A2) {
            __syncthreads();
            for (int i = tid; i < 128 * 128; i += 512) {
                int e = i >> 7, k = i & 127;
                int r = rb + e;
                float v = (r < nrows) ? A2[(size_t)r * 128 + k] : 0.f;
                __nv_bfloat16 h, l; split_bf16(v, h, l);
                ah[e * 136 + k] = h;  al[e * 136 + k] = l;
            }
            __syncthreads();
            #pragma unroll
            for (int ko = 0; ko < 128; ko += 16) {
                uint32_t Ah[4], Al[4];
                ldfrag4(ah, 136, mo, ko, g, tq, Ah);
                ldfrag4(al, 136, mo, ko, g, tq, Al);
                #pragma unroll
                for (int nt = 0; nt < 8; ++nt) {
                    uint32_t Bh[2], Bl[2];
                    ldfrag2(w2h, 136, no + nt*8, ko, g, tq, Bh);
                    ldfrag2(w2l, 136, no + nt*8, ko, g, tq, Bl);
                    mma_bf16(acc[nt], Ah, Bh);
                    mma_bf16(acc[nt], Ah, Bl);
                    mma_bf16(acc[nt], Al, Bh);
                }
            }
        }

        // epilogue: bias (+swish) (+res), direct store
        #pragma unroll
        for (int nt = 0; nt < 8; ++nt) {
            const int c = no + nt*8 + tq*2;
            const float b0 = bs[c], b1 = bs[c + 1];
            #pragma unroll
            for (int half = 0; half < 2; ++half) {
                int r = rb + mo + g + half*8;
                if (r < nrows) {
                    float v0 = acc[nt][half*2]     + b0;
                    float v1 = acc[nt][half*2 + 1] + b1;
                    if (ACT) { v0 = v0 / (1.f + expf(-v0)); v1 = v1 / (1.f + expf(-v1)); }
                    if (HAS_RES) {
                        float2 rr = *reinterpret_cast<const float2*>(&res[(size_t)r*128 + c]);
                        v0 += rr.x; v1 += rr.y;
                    }
                    *reinterpret_cast<float2*>(&out[(size_t)r*128 + c]) = make_float2(v0, v1);
                }
            }
        }
        __syncthreads();   // A reads done before next tile staging
    }
}

// ---------------- zero init ----------------
__global__ void zero_bufs_kernel() {
    int idx = blockIdx.x * blockDim.x + threadIdx.x;
    if (idx < NN*HH) { g_agg1[idx] = 0.f; g_agg2[idx] = 0.f; }
    if (idx < GG*HH) { g_gsum[idx] = 0.f; g_gvar[idx] = 0.f; }
    if (idx < GG)    { g_gcnt[idx] = 0.f; }
}

// ---------------- GraphNorm kernels ----------------
__global__ void gn_accum(const float* __restrict__ h, const int* __restrict__ batch) {
    int idx = blockIdx.x * blockDim.x + threadIdx.x;
    if (idx >= NN*HH) return;
    int n = idx >> 7, c = idx & 127;
    int b = batch[n];
    atomicAdd(&g_gsum[b*128 + c], h[idx]);
    if (c == 0) atomicAdd(&g_gcnt[b], 1.f);
}
__global__ void gn_mean() {
    int idx = blockIdx.x * blockDim.x + threadIdx.x;
    if (idx >= GG*HH) return;
    int g = idx >> 7;
    g_gsum[idx] /= fmaxf(g_gcnt[g], 1.f);
}
__global__ void gn_center(const float* __restrict__ h, const int* __restrict__ batch,
                          const float* __restrict__ ms, float* __restrict__ out) {
    int idx = blockIdx.x * blockDim.x + threadIdx.x;
    if (idx >= NN*HH) return;
    int n = idx >> 7, c = idx & 127;
    int b = batch[n];
    float o = h[idx] - g_gsum[b*128 + c] * ms[c];
    out[idx] = o;
    atomicAdd(&g_gvar[b*128 + c], o*o);
}
__global__ void gn_inv() {
    int idx = blockIdx.x * blockDim.x + threadIdx.x;
    if (idx >= GG*HH) return;
    int g = idx >> 7;
    g_gvar[idx] = rsqrtf(g_gvar[idx] / fmaxf(g_gcnt[g], 1.f) + EPSV);
}
__global__ void gn_apply(const float* __restrict__ cent, const int* __restrict__ batch,
                         const float* __restrict__ nw, const float* __restrict__ nb,
                         float* __restrict__ out) {
    int idx = blockIdx.x * blockDim.x + threadIdx.x;
    if (idx >= NN*HH) return;
    int n = idx >> 7, c = idx & 127;
    int b = batch[n];
    out[idx] = nw[c] * cent[idx] * g_gvar[b*128 + c] + nb[c];
}

// ---------------- host launcher ----------------
static inline void set_smem(const void* f, int bytes) {
    cudaFuncSetAttribute(f, cudaFuncAttributeMaxDynamicSharedMemorySize, bytes);
}

extern "C" void kernel_launch(void* const* d_in, const int* in_sizes, int n_in,
                              void* d_out, int out_size) {
    (void)in_sizes; (void)n_in; (void)out_size;

    const float* x          = (const float*)d_in[0];
    const float* feature1   = (const float*)d_in[1];
    const float* feature2   = (const float*)d_in[2];
    const int*   edge_index = (const int*)  d_in[3];
    const int*   batch      = (const int*)  d_in[4];
    const float* lin_w      = (const float*)d_in[5];
    const float* lin_b      = (const float*)d_in[6];
    const float* f1_w1      = (const float*)d_in[7];
    const float* f1_w2      = (const float*)d_in[8];
    const float* f2_w1      = (const float*)d_in[9];
    const float* f2_w2      = (const float*)d_in[10];
    const float* c1_rel_w   = (const float*)d_in[11];
    const float* c1_rel_b   = (const float*)d_in[12];
    const float* c1_root_w  = (const float*)d_in[13];
    const float* c2_rel_w   = (const float*)d_in[14];
    const float* c2_rel_b   = (const float*)d_in[15];
    const float* c2_root_w  = (const float*)d_in[16];
    const float* lin1_w     = (const float*)d_in[17];
    const float* lin1_b     = (const float*)d_in[18];
    const float* lin2_w     = (const float*)d_in[19];
    const float* lin2_b     = (const float*)d_in[20];
    const float* lincat_w   = (const float*)d_in[21];
    const float* lincat_b   = (const float*)d_in[22];
    const float* norm_w     = (const float*)d_in[23];
    const float* norm_b     = (const float*)d_in[24];
    const float* norm_ms    = (const float*)d_in[25];
    const float* lins_w     = (const float*)d_in[26];
    const float* lins_b     = (const float*)d_in[27];
    const float* final_w    = (const float*)d_in[28];
    const float* final_b    = (const float*)d_in[29];
    float* out = (float*)d_out;

    const int* src = edge_index;
    const int* dst = edge_index + EE;

    float *xh, *agg1, *agg2, *tmp, *h1, *h2, *hA, *hB;
    cudaGetSymbolAddress((void**)&xh,   g_xh);
    cudaGetSymbolAddress((void**)&agg1, g_agg1);
    cudaGetSymbolAddress((void**)&agg2, g_agg2);
    cudaGetSymbolAddress((void**)&tmp,  g_tmp);
    cudaGetSymbolAddress((void**)&h1,   g_h1);
    cudaGetSymbolAddress((void**)&h2,   g_h2);
    cudaGetSymbolAddress((void**)&hA,   g_hA);
    cudaGetSymbolAddress((void**)&hB,   g_hB);

    constexpr int WS = 128 * 136 * 2;
    const int N1 = 4 * WS + 512;   // w1h,w1l,ah,al + bias          = 139,776 B
    const int N2 = 6 * WS + 512;   // w1h,w1l,w2h,w2l,ah,al + bias  = 209,408 B

    set_smem((const void*)node_hmma<false,true ,false>, N1);
    set_smem((const void*)node_hmma<false,true ,true >, N1);
    set_smem((const void*)node_hmma<false,false,false>, N1);
    set_smem((const void*)node_hmma<true ,false,false>, N2);
    set_smem((const void*)node_hmma<true ,false,true >, N2);
    set_smem((const void*)edge_fused<FF1,1>, EL<FF1>::TOT);
    set_smem((const void*)edge_fused<FF2,2>, EL<FF2>::TOT);

    const int EL_GRID = (NN*HH + 255) / 256;
    const int GH_GRID = (GG*HH + 255) / 256;
    const int NT      = (EE + 127) / 128;   // 7813
    const int NTN     = (NN + 127) / 128;   // 391

    // 0) zero accumulators
    zero_bufs_kernel<<<EL_GRID, 256>>>();

    // 1) xh = swish(x @ lin_w + lin_b)
    node_hmma<false,true,false><<<148, 512, N1>>>(
        x, lin_w, nullptr, nullptr, lin_b, nullptr, xh, NN, NTN);

    // 2) fused edge messages (HMMA)
    edge_fused<FF1,1><<<148, 256, EL<FF1>::TOT>>>(feature1, f1_w1, f1_w2, xh, src, dst, agg1, NT);
    edge_fused<FF2,2><<<296, 256, EL<FF2>::TOT>>>(feature2, f2_w1, f2_w2, xh, src, dst, agg2, NT);

    // 3) conv1
    node_hmma<true,false,false><<<148, 512, N2>>>(
        agg1, c1_rel_w, xh, c1_root_w, c1_rel_b, nullptr, tmp, NN, NTN);
    node_hmma<false,true,false><<<148, 512, N1>>>(
        tmp, lin1_w, nullptr, nullptr, lin1_b, nullptr, h1, NN, NTN);

    // 4) conv2
    node_hmma<true,false,false><<<148, 512, N2>>>(
        agg2, c2_rel_w, xh, c2_root_w, c2_rel_b, nullptr, tmp, NN, NTN);
    node_hmma<false,true,false><<<148, 512, N1>>>(
        tmp, lin2_w, nullptr, nullptr, lin2_b, nullptr, h2, NN, NTN);

    // 5) hA = h1@Wtop + h2@Wbot + lincat_b + xh
    node_hmma<true,false,true><<<148, 512, N2>>>(
        h1, lincat_w, h2, lincat_w + 128*128, lincat_b, xh, hA, NN, NTN);

    // 6) residual stack: h = swish(h@Wi + bi) + h
    node_hmma<false,true,true><<<148, 512, N1>>>(
        hA, lins_w + 0*16384, nullptr, nullptr, lins_b + 0*128, hA, hB, NN, NTN);
    node_hmma<false,true,true><<<148, 512, N1>>>(
        hB, lins_w + 1*16384, nullptr, nullptr, lins_b + 1*128, hB, hA, NN, NTN);
    node_hmma<false,true,true><<<148, 512, N1>>>(
        hA, lins_w + 2*16384, nullptr, nullptr, lins_b + 2*128, hA, hB, NN, NTN);

    // 7) GraphNorm on hB
    gn_accum <<<EL_GRID, 256>>>(hB, batch);
    gn_mean  <<<GH_GRID, 256>>>();
    gn_center<<<EL_GRID, 256>>>(hB, batch, norm_ms, h1);
    gn_inv   <<<GH_GRID, 256>>>();
    gn_apply <<<EL_GRID, 256>>>(h1, batch, norm_w, norm_b, hA);

    // 8) out = hA @ final_w + final_b
    node_hmma<false,false,false><<<148, 512, N1>>>(
        hA, final_w, nullptr, nullptr, final_b, nullptr, out, NN, NTN);
}

// round 8
// speedup vs baseline: 2.3029x; 1.0273x over previous
#include <cuda_runtime.h>
#include <cuda_bf16.h>
#include <math.h>
#include <stdint.h>

// ---------------- problem constants ----------------
#define NN    50000
#define HH    128
#define EE    1000000
#define FF1   147
#define FF2   21
#define GG    512
#define EPSV  1e-5f

// ---------------- device scratch (no allocs allowed) ----------------
__device__ float g_xh  [NN*HH];
__device__ float g_agg1[NN*HH];
__device__ float g_agg2[NN*HH];
__device__ float g_tmp [NN*HH];
__device__ float g_h1  [NN*HH];
__device__ float g_h2  [NN*HH];
__device__ float g_hA  [NN*HH];
__device__ float g_hB  [NN*HH];
__device__ float g_gsum[GG*HH];
__device__ float g_gvar[GG*HH];
__device__ float g_gcnt[GG];

// ================= warp-MMA helpers (baseline PTX, sm_80+) =================
__device__ __forceinline__ void mma_bf16(float d[4], const uint32_t a[4], const uint32_t b[2]) {
    asm volatile(
        "mma.sync.aligned.m16n8k16.row.col.f32.bf16.bf16.f32 "
        "{%0,%1,%2,%3}, {%4,%5,%6,%7}, {%8,%9}, {%0,%1,%2,%3};"
        : "+f"(d[0]), "+f"(d[1]), "+f"(d[2]), "+f"(d[3])
        : "r"(a[0]), "r"(a[1]), "r"(a[2]), "r"(a[3]), "r"(b[0]), "r"(b[1]));
}

__device__ __forceinline__ void split_bf16(float f, __nv_bfloat16& h, __nv_bfloat16& l) {
    h = __float2bfloat16_rn(f);
    l = __float2bfloat16_rn(f - __bfloat162float(h));
}

__device__ __forceinline__ void split_pack2(float f0, float f1, uint32_t& hi, uint32_t& lo) {
    __nv_bfloat16 h0, l0, h1, l1;
    split_bf16(f0, h0, l0);
    split_bf16(f1, h1, l1);
    hi = (uint32_t)__bfloat16_as_ushort(h0) | ((uint32_t)__bfloat16_as_ushort(h1) << 16);
    lo = (uint32_t)__bfloat16_as_ushort(l0) | ((uint32_t)__bfloat16_as_ushort(l1) << 16);
}

// A fragment (16x16) from row-major bf16 smem [row][k]
__device__ __forceinline__ void ldfrag4(const __nv_bfloat16* base, int stride,
                                        int row, int ko, int g, int tq, uint32_t a[4]) {
    a[0] = *reinterpret_cast<const uint32_t*>(&base[(row + g    ) * stride + ko     + tq*2]);
    a[1] = *reinterpret_cast<const uint32_t*>(&base[(row + g + 8) * stride + ko     + tq*2]);
    a[2] = *reinterpret_cast<const uint32_t*>(&base[(row + g    ) * stride + ko + 8 + tq*2]);
    a[3] = *reinterpret_cast<const uint32_t*>(&base[(row + g + 8) * stride + ko + 8 + tq*2]);
}
// B fragment (16x8) from W^T stored row-major [n][k]
__device__ __forceinline__ void ldfrag2(const __nv_bfloat16* base, int stride,
                                        int n0, int ko, int g, int tq, uint32_t b[2]) {
    b[0] = *reinterpret_cast<const uint32_t*>(&base[(n0 + g) * stride + ko     + tq*2]);
    b[1] = *reinterpret_cast<const uint32_t*>(&base[(n0 + g) * stride + ko + 8 + tq*2]);
}

// ---------------- edge kernel smem layout ----------------
template<int F> struct EL {
    static constexpr int KP  = (F + 15) & ~15;
    static constexpr int SA  = KP + 8;                 // bf16 elems/row (A, W1T)
    static constexpr int W1H = 0;
    static constexpr int W1L = W1H + 64 * SA * 2;
    static constexpr int W2H = W1L + 64 * SA * 2;
    static constexpr int W2L = W2H + 128 * 72 * 2;
    static constexpr int MIH = W2L + 128 * 72 * 2;     // mid hi; o-halves alias here
    static constexpr int MIL = MIH + 128 * 72 * 2;
    static constexpr int A1H = MIL + 128 * 72 * 2;
    static constexpr int A1L = A1H + 128 * SA * 2;
    static constexpr int IDX = A1L + 128 * SA * 2;     // 2 x 256 ints (double-buffered)
    static constexpr int TOT = IDX + 2048;
};

// ================= fused edge kernel (pipelined) =================
// mid[128,64] = feat[128,F] @ w1 ; o[128,128] = mid @ w2 ;
// agg[dst[e],c] += o[e,c] * xh[src[e],c]
// Next tile's A staging overlaps this tile's epilogue (A is dead after GEMM1).
template<int F, int MINB>
__global__ void __launch_bounds__(256, MINB) edge_fused(
    const float* __restrict__ feat, const float* __restrict__ w1,
    const float* __restrict__ w2,   const float* __restrict__ xh,
    const int* __restrict__ src,    const int* __restrict__ dst,
    float* __restrict__ agg, int ntiles)
{
    using L = EL<F>;
    extern __shared__ char smem[];
    __nv_bfloat16* w1h = (__nv_bfloat16*)(smem + L::W1H);
    __nv_bfloat16* w1l = (__nv_bfloat16*)(smem + L::W1L);
    __nv_bfloat16* w2h = (__nv_bfloat16*)(smem + L::W2H);
    __nv_bfloat16* w2l = (__nv_bfloat16*)(smem + L::W2L);
    __nv_bfloat16* mih = (__nv_bfloat16*)(smem + L::MIH);
    __nv_bfloat16* mil = (__nv_bfloat16*)(smem + L::MIL);
    __nv_bfloat16* a1h = (__nv_bfloat16*)(smem + L::A1H);
    __nv_bfloat16* a1l = (__nv_bfloat16*)(smem + L::A1L);
    float*         ob  = (float*)        (smem + L::MIH);   // 64 x 132 f32 (aliases MI)
    int*           sidx= (int*)          (smem + L::IDX);   // 2 buffers x 256

    const int tid  = threadIdx.x;
    const int wid  = tid >> 5, lane = tid & 31;
    const int g    = lane >> 2, tq = lane & 3;
    const int wm   = wid & 3, wn = wid >> 2;

    // zero once: weight pads + A pads must be 0 (never clobbered afterwards)
    for (int i = tid; i < L::TOT / 4; i += 256)
        reinterpret_cast<uint32_t*>(smem)[i] = 0;
    __syncthreads();

    // stage weights transposed + split. w1 gmem [F][64], w2 gmem [64][128]
    for (int i = tid; i < F * 64; i += 256) {
        int k = i >> 6, n = i & 63;
        __nv_bfloat16 h, l; split_bf16(w1[i], h, l);
        w1h[n * L::SA + k] = h;  w1l[n * L::SA + k] = l;
    }
    for (int i = tid; i < 64 * 128; i += 256) {
        int k = i >> 7, n = i & 127;
        __nv_bfloat16 h, l; split_bf16(w2[i], h, l);
        w2h[n * 72 + k] = h;  w2l[n * 72 + k] = l;
    }

    // tile stager: writes a1h/a1l (k<F; pads stay zero) + sidx[parity]
    auto stage = [&](int tt, int parity) {
        if (tt >= ntiles) return;
        const int se0 = tt * 128;
        const int scnt = min(128, EE - se0);
        const float* fb = feat + (size_t)se0 * F;
        for (int i = tid; i < scnt * F; i += 256) {
            int e = i / F, k = i - e * F;
            __nv_bfloat16 h, l; split_bf16(fb[i], h, l);
            a1h[e * L::SA + k] = h;  a1l[e * L::SA + k] = l;
        }
        int* sx = sidx + parity * 256;
        if (tid < scnt) { sx[tid] = src[se0 + tid]; sx[128 + tid] = dst[se0 + tid]; }
    };

    int t = blockIdx.x, pb = 0;
    stage(t, 0);
    __syncthreads();

    for (; t < ntiles; t += gridDim.x) {
        const int cnt = min(128, EE - t * 128);
        const int* sx = sidx + pb * 256;

        // ---- GEMM1 ----
        {
            const int mo = wm * 32, no = wn * 32;
            float acc[2][4][4];
            #pragma unroll
            for (int a = 0; a < 2; ++a)
                #pragma unroll
                for (int b = 0; b < 4; ++b)
                    #pragma unroll
                    for (int c = 0; c < 4; ++c) acc[a][b][c] = 0.f;

            #pragma unroll
            for (int ko = 0; ko < L::KP; ko += 16) {
                uint32_t Ah[2][4], Al[2][4];
                #pragma unroll
                for (int mt = 0; mt < 2; ++mt) {
                    ldfrag4(a1h, L::SA, mo + mt*16, ko, g, tq, Ah[mt]);
                    ldfrag4(a1l, L::SA, mo + mt*16, ko, g, tq, Al[mt]);
                }
                #pragma unroll
                for (int nt = 0; nt < 4; ++nt) {
                    uint32_t Bh[2], Bl[2];
                    ldfrag2(w1h, L::SA, no + nt*8, ko, g, tq, Bh);
                    ldfrag2(w1l, L::SA, no + nt*8, ko, g, tq, Bl);
                    #pragma unroll
                    for (int mt = 0; mt < 2; ++mt) {
                        mma_bf16(acc[mt][nt], Ah[mt], Bh);
                        mma_bf16(acc[mt][nt], Ah[mt], Bl);
                        mma_bf16(acc[mt][nt], Al[mt], Bh);
                    }
                }
            }
            #pragma unroll
            for (int mt = 0; mt < 2; ++mt)
                #pragma unroll
                for (int nt = 0; nt < 4; ++nt) {
                    int r0 = mo + mt*16 + g, col = no + nt*8 + tq*2;
                    uint32_t hi, lo;
                    split_pack2(acc[mt][nt][0], acc[mt][nt][1], hi, lo);
                    *reinterpret_cast<uint32_t*>(&mih[r0*72 + col]) = hi;
                    *reinterpret_cast<uint32_t*>(&mil[r0*72 + col]) = lo;
                    split_pack2(acc[mt][nt][2], acc[mt][nt][3], hi, lo);
                    *reinterpret_cast<uint32_t*>(&mih[(r0+8)*72 + col]) = hi;
                    *reinterpret_cast<uint32_t*>(&mil[(r0+8)*72 + col]) = lo;
                }
        }
        __syncthreads();   // mid visible; A now dead (stageable)

        // ---- GEMM2 (K=64) ----
        float acc[2][8][4];
        {
            const int mo = wm * 32, no = wn * 64;
            #pragma unroll
            for (int a = 0; a < 2; ++a)
                #pragma unroll
                for (int b = 0; b < 8; ++b)
                    #pragma unroll
                    for (int c = 0; c < 4; ++c) acc[a][b][c] = 0.f;

            #pragma unroll
            for (int ko = 0; ko < 64; ko += 16) {
                uint32_t Ah[2][4], Al[2][4];
                #pragma unroll
                for (int mt = 0; mt < 2; ++mt) {
                    ldfrag4(mih, 72, mo + mt*16, ko, g, tq, Ah[mt]);
                    ldfrag4(mil, 72, mo + mt*16, ko, g, tq, Al[mt]);
                }
                #pragma unroll
                for (int nt = 0; nt < 8; ++nt) {
                    uint32_t Bh[2], Bl[2];
                    ldfrag2(w2h, 72, no + nt*8, ko, g, tq, Bh);
                    ldfrag2(w2l, 72, no + nt*8, ko, g, tq, Bl);
                    #pragma unroll
                    for (int mt = 0; mt < 2; ++mt) {
                        mma_bf16(acc[mt][nt], Ah[mt], Bh);
                        mma_bf16(acc[mt][nt], Ah[mt], Bl);
                        mma_bf16(acc[mt][nt], Al[mt], Bh);
                    }
                }
            }
        }
        __syncthreads();   // MI reads done -> ob region writable

        // ---- per half: store o rows into ob, then epilogue;
        //      next tile's A staging rides in the half-0 epilogue phase ----
        #pragma unroll
        for (int half = 0; half < 2; ++half) {
            if ((wm >> 1) == half) {          // wm 0,1 own rows 0..63; wm 2,3 rows 64..127
                const int mo = wm * 32, no = wn * 64;
                #pragma unroll
                for (int mt = 0; mt < 2; ++mt)
                    #pragma unroll
                    for (int nt = 0; nt < 8; ++nt) {
                        int rl = mo + mt*16 + g - half*64, col = no + nt*8 + tq*2;
                        *reinterpret_cast<float2*>(&ob[rl*132 + col]) =
                            make_float2(acc[mt][nt][0], acc[mt][nt][1]);
                        *reinterpret_cast<float2*>(&ob[(rl+8)*132 + col]) =
                            make_float2(acc[mt][nt][2], acc[mt][nt][3]);
                    }
            }
            __syncthreads();
            {
                const int c = tid & 127, eh = tid >> 7;
                const int lim = min(cnt - half*64, 64);
                for (int e = eh; e < lim; e += 2) {
                    int eg = half*64 + e;
                    int s = sx[eg], d = sx[128 + eg];
                    float v = ob[e * 132 + c] * xh[(size_t)s * 128 + c];
                    atomicAdd(&agg[(size_t)d * 128 + c], v);
                }
            }
            if (half == 0) stage(t + gridDim.x, pb ^ 1);   // overlap staging w/ epilogue
            __syncthreads();
        }
        pb ^= 1;
    }
}

// ================= node GEMM on HMMA =================
// out[r,c] = epi( A[r,:]@W[:,c] (+ A2[r,:]@W2[:,c]) + bias[c] ), 512 thr, persistent.
// DB: double-buffered A (only valid with !HAS_A2) -> 1 sync/tile, staging overlaps epilogue.
template<bool HAS_A2, bool ACT, bool HAS_RES, bool DB>
__global__ void __launch_bounds__(512) node_hmma(
    const float* __restrict__ A,  const float* __restrict__ W,
    const float* __restrict__ A2, const float* __restrict__ W2,
    const float* __restrict__ bias, const float* __restrict__ res,
    float* __restrict__ out, int nrows, int ntiles)
{
    static_assert(!(HAS_A2 && DB), "DB only for single-A variant");
    constexpr int WS = 128 * 136 * 2;      // 34816 bytes per plane
    constexpr int NWP = HAS_A2 ? 4 : 2;    // weight planes
    constexpr int NAP = DB ? 4 : 2;        // A planes
    extern __shared__ char smem[];
    __nv_bfloat16* wh  = (__nv_bfloat16*)(smem);
    __nv_bfloat16* wl  = (__nv_bfloat16*)(smem + WS);
    __nv_bfloat16* w2h = (__nv_bfloat16*)(smem + 2 * WS);
    __nv_bfloat16* w2l = (__nv_bfloat16*)(smem + 3 * WS);
    float*         bs  = (float*)        (smem + (NWP + NAP) * WS);

    const int tid = threadIdx.x;
    const int wid = tid >> 5, lane = tid & 31;
    const int g = lane >> 2, tq = lane & 3;
    const int wm = wid & 7, wn = wid >> 3;
    const int mo = wm * 16, no = wn * 64;

    // stage weights (transposed, split) + bias
    for (int i = tid; i < 128 * 128; i += 512) {
        int k = i >> 7, n = i & 127;
        __nv_bfloat16 h, l; split_bf16(W[i], h, l);
        wh[n * 136 + k] = h;  wl[n * 136 + k] = l;
        if (HAS_A2) {
            split_bf16(W2[i], h, l);
            w2h[n * 136 + k] = h;  w2l[n * 136 + k] = l;
        }
    }
    if (tid < 128) bs[tid] = bias[tid];

    auto a_hi = [&](int p) { return (__nv_bfloat16*)(smem + (NWP + p * 2) * WS); };
    auto a_lo = [&](int p) { return (__nv_bfloat16*)(smem + (NWP + p * 2 + 1) * WS); };

    auto stageA = [&](const float* __restrict__ src_, int tt, int p) {
        if (tt >= ntiles) return;
        const int rb = tt * 128;
        __nv_bfloat16* dh = a_hi(p);
        __nv_bfloat16* dl = a_lo(p);
        for (int i = tid; i < 128 * 128; i += 512) {
            int e = i >> 7, k = i & 127;
            int r = rb + e;
            float v = (r < nrows) ? src_[(size_t)r * 128 + k] : 0.f;
            __nv_bfloat16 h, l; split_bf16(v, h, l);
            dh[e * 136 + k] = h;  dl[e * 136 + k] = l;
        }
    };

    auto run_mma = [&](float acc[8][4], const __nv_bfloat16* ah, const __nv_bfloat16* al,
                       const __nv_bfloat16* bh, const __nv_bfloat16* bl) {
        #pragma unroll
        for (int ko = 0; ko < 128; ko += 16) {
            uint32_t Ah[4], Al[4];
            ldfrag4(ah, 136, mo, ko, g, tq, Ah);
            ldfrag4(al, 136, mo, ko, g, tq, Al);
            #pragma unroll
            for (int nt = 0; nt < 8; ++nt) {
                uint32_t Bh[2], Bl[2];
                ldfrag2(bh, 136, no + nt*8, ko, g, tq, Bh);
                ldfrag2(bl, 136, no + nt*8, ko, g, tq, Bl);
                mma_bf16(acc[nt], Ah, Bh);
                mma_bf16(acc[nt], Ah, Bl);
                mma_bf16(acc[nt], Al, Bh);
            }
        }
    };

    auto epilogue = [&](float acc[8][4], int rb) {
        #pragma unroll
        for (int nt = 0; nt < 8; ++nt) {
            const int c = no + nt*8 + tq*2;
            const float b0 = bs[c], b1 = bs[c + 1];
            #pragma unroll
            for (int half = 0; half < 2; ++half) {
                int r = rb + mo + g + half*8;
                if (r < nrows) {
                    float v0 = acc[nt][half*2]     + b0;
                    float v1 = acc[nt][half*2 + 1] + b1;
                    if (ACT) { v0 = v0 / (1.f + expf(-v0)); v1 = v1 / (1.f + expf(-v1)); }
                    if (HAS_RES) {
                        float2 rr = *reinterpret_cast<const float2*>(&res[(size_t)r*128 + c]);
                        v0 += rr.x; v1 += rr.y;
                    }
                    *reinterpret_cast<float2*>(&out[(size_t)r*128 + c]) = make_float2(v0, v1);
                }
            }
        }
    };

    if (DB) {
        int t = blockIdx.x, pb = 0;
        stageA(A, t, 0);
        __syncthreads();
        for (; t < ntiles; t += gridDim.x) {
            float acc[8][4];
            #pragma unroll
            for (int b = 0; b < 8; ++b)
                #pragma unroll
                for (int c = 0; c < 4; ++c) acc[b][c] = 0.f;
            run_mma(acc, a_hi(pb), a_lo(pb), wh, wl);
            stageA(A, t + gridDim.x, pb ^ 1);   // overlap w/ epilogue + MMA tails
            epilogue(acc, t * 128);
            pb ^= 1;
            __syncthreads();
        }
    } else {
        __syncthreads();   // weights ready
        for (int t = blockIdx.x; t < ntiles; t += gridDim.x) {
            stageA(A, t, 0);
            __syncthreads();
            float acc[8][4];
            #pragma unroll
            for (int b = 0; b < 8; ++b)
                #pragma unroll
                for (int c = 0; c < 4; ++c) acc[b][c] = 0.f;
            run_mma(acc, a_hi(0), a_lo(0), wh, wl);
            if (HAS_A2) {
                __syncthreads();
                stageA(A2, t, 0);
                __syncthreads();
                run_mma(acc, a_hi(0), a_lo(0), w2h, w2l);
            }
            epilogue(acc, t * 128);
            __syncthreads();
        }
    }
}

// ---------------- zero init ----------------
__global__ void zero_bufs_kernel() {
    int idx = blockIdx.x * blockDim.x + threadIdx.x;
    if (idx < NN*HH) { g_agg1[idx] = 0.f; g_agg2[idx] = 0.f; }
    if (idx < GG*HH) { g_gsum[idx] = 0.f; g_gvar[idx] = 0.f; }
    if (idx < GG)    { g_gcnt[idx] = 0.f; }
}

// ---------------- GraphNorm kernels ----------------
__global__ void gn_accum(const float* __restrict__ h, const int* __restrict__ batch) {
    int idx = blockIdx.x * blockDim.x + threadIdx.x;
    if (idx >= NN*HH) return;
    int n = idx >> 7, c = idx & 127;
    int b = batch[n];
    atomicAdd(&g_gsum[b*128 + c], h[idx]);
    if (c == 0) atomicAdd(&g_gcnt[b], 1.f);
}
__global__ void gn_mean() {
    int idx = blockIdx.x * blockDim.x + threadIdx.x;
    if (idx >= GG*HH) return;
    int g = idx >> 7;
    g_gsum[idx] /= fmaxf(g_gcnt[g], 1.f);
}
__global__ void gn_center(const float* __restrict__ h, const int* __restrict__ batch,
                          const float* __restrict__ ms, float* __restrict__ out) {
    int idx = blockIdx.x * blockDim.x + threadIdx.x;
    if (idx >= NN*HH) return;
    int n = idx >> 7, c = idx & 127;
    int b = batch[n];
    float o = h[idx] - g_gsum[b*128 + c] * ms[c];
    out[idx] = o;
    atomicAdd(&g_gvar[b*128 + c], o*o);
}
__global__ void gn_inv() {
    int idx = blockIdx.x * blockDim.x + threadIdx.x;
    if (idx >= GG*HH) return;
    int g = idx >> 7;
    g_gvar[idx] = rsqrtf(g_gvar[idx] / fmaxf(g_gcnt[g], 1.f) + EPSV);
}
__global__ void gn_apply(const float* __restrict__ cent, const int* __restrict__ batch,
                         const float* __restrict__ nw, const float* __restrict__ nb,
                         float* __restrict__ out) {
    int idx = blockIdx.x * blockDim.x + threadIdx.x;
    if (idx >= NN*HH) return;
    int n = idx >> 7, c = idx & 127;
    int b = batch[n];
    out[idx] = nw[c] * cent[idx] * g_gvar[b*128 + c] + nb[c];
}

// ---------------- host launcher ----------------
static inline void set_smem(const void* f, int bytes) {
    cudaFuncSetAttribute(f, cudaFuncAttributeMaxDynamicSharedMemorySize, bytes);
}

extern "C" void kernel_launch(void* const* d_in, const int* in_sizes, int n_in,
                              void* d_out, int out_size) {
    (void)in_sizes; (void)n_in; (void)out_size;

    const float* x          = (const float*)d_in[0];
    const float* feature1   = (const float*)d_in[1];
    const float* feature2   = (const float*)d_in[2];
    const int*   edge_index = (const int*)  d_in[3];
    const int*   batch      = (const int*)  d_in[4];
    const float* lin_w      = (const float*)d_in[5];
    const float* lin_b      = (const float*)d_in[6];
    const float* f1_w1      = (const float*)d_in[7];
    const float* f1_w2      = (const float*)d_in[8];
    const float* f2_w1      = (const float*)d_in[9];
    const float* f2_w2      = (const float*)d_in[10];
    const float* c1_rel_w   = (const float*)d_in[11];
    const float* c1_rel_b   = (const float*)d_in[12];
    const float* c1_root_w  = (const float*)d_in[13];
    const float* c2_rel_w   = (const float*)d_in[14];
    const float* c2_rel_b   = (const float*)d_in[15];
    const float* c2_root_w  = (const float*)d_in[16];
    const float* lin1_w     = (const float*)d_in[17];
    const float* lin1_b     = (const float*)d_in[18];
    const float* lin2_w     = (const float*)d_in[19];
    const float* lin2_b     = (const float*)d_in[20];
    const float* lincat_w   = (const float*)d_in[21];
    const float* lincat_b   = (const float*)d_in[22];
    const float* norm_w     = (const float*)d_in[23];
    const float* norm_b     = (const float*)d_in[24];
    const float* norm_ms    = (const float*)d_in[25];
    const float* lins_w     = (const float*)d_in[26];
    const float* lins_b     = (const float*)d_in[27];
    const float* final_w    = (const float*)d_in[28];
    const float* final_b    = (const float*)d_in[29];
    float* out = (float*)d_out;

    const int* src = edge_index;
    const int* dst = edge_index + EE;

    float *xh, *agg1, *agg2, *tmp, *h1, *h2, *hA, *hB;
    cudaGetSymbolAddress((void**)&xh,   g_xh);
    cudaGetSymbolAddress((void**)&agg1, g_agg1);
    cudaGetSymbolAddress((void**)&agg2, g_agg2);
    cudaGetSymbolAddress((void**)&tmp,  g_tmp);
    cudaGetSymbolAddress((void**)&h1,   g_h1);
    cudaGetSymbolAddress((void**)&h2,   g_h2);
    cudaGetSymbolAddress((void**)&hA,   g_hA);
    cudaGetSymbolAddress((void**)&hB,   g_hB);

    constexpr int WS = 128 * 136 * 2;
    const int N1 = 6 * WS + 512;   // DB: w(2) + a(4) + bias = 209,408 B
    const int N2 = 6 * WS + 512;   // A2: w(4) + a(2) + bias = 209,408 B

    set_smem((const void*)node_hmma<false,true ,false,true >, N1);
    set_smem((const void*)node_hmma<false,true ,true ,true >, N1);
    set_smem((const void*)node_hmma<false,false,false,true >, N1);
    set_smem((const void*)node_hmma<true ,false,false,false>, N2);
    set_smem((const void*)node_hmma<true ,false,true ,false>, N2);
    set_smem((const void*)edge_fused<FF1,1>, EL<FF1>::TOT);
    set_smem((const void*)edge_fused<FF2,2>, EL<FF2>::TOT);

    const int EL_GRID = (NN*HH + 255) / 256;
    const int GH_GRID = (GG*HH + 255) / 256;
    const int NT      = (EE + 127) / 128;   // 7813
    const int NTN     = (NN + 127) / 128;   // 391

    // 0) zero accumulators
    zero_bufs_kernel<<<EL_GRID, 256>>>();

    // 1) xh = swish(x @ lin_w + lin_b)
    node_hmma<false,true,false,true><<<148, 512, N1>>>(
        x, lin_w, nullptr, nullptr, lin_b, nullptr, xh, NN, NTN);

    // 2) fused edge messages (HMMA, pipelined)
    edge_fused<FF1,1><<<148, 256, EL<FF1>::TOT>>>(feature1, f1_w1, f1_w2, xh, src, dst, agg1, NT);
    edge_fused<FF2,2><<<296, 256, EL<FF2>::TOT>>>(feature2, f2_w1, f2_w2, xh, src, dst, agg2, NT);

    // 3) conv1
    node_hmma<true,false,false,false><<<148, 512, N2>>>(
        agg1, c1_rel_w, xh, c1_root_w, c1_rel_b, nullptr, tmp, NN, NTN);
    node_hmma<false,true,false,true><<<148, 512, N1>>>(
        tmp, lin1_w, nullptr, nullptr, lin1_b, nullptr, h1, NN, NTN);

    // 4) conv2
    node_hmma<true,false,false,false><<<148, 512, N2>>>(
        agg2, c2_rel_w, xh, c2_root_w, c2_rel_b, nullptr, tmp, NN, NTN);
    node_hmma<false,true,false,true><<<148, 512, N1>>>(
        tmp, lin2_w, nullptr, nullptr, lin2_b, nullptr, h2, NN, NTN);

    // 5) hA = h1@Wtop + h2@Wbot + lincat_b + xh
    node_hmma<true,false,true,false><<<148, 512, N2>>>(
        h1, lincat_w, h2, lincat_w + 128*128, lincat_b, xh, hA, NN, NTN);

    // 6) residual stack: h = swish(h@Wi + bi) + h
    node_hmma<false,true,true,true><<<148, 512, N1>>>(
        hA, lins_w + 0*16384, nullptr, nullptr, lins_b + 0*128, hA, hB, NN, NTN);
    node_hmma<false,true,true,true><<<148, 512, N1>>>(
        hB, lins_w + 1*16384, nullptr, nullptr, lins_b + 1*128, hB, hA, NN, NTN);
    node_hmma<false,true,true,true><<<148, 512, N1>>>(
        hA, lins_w + 2*16384, nullptr, nullptr, lins_b + 2*128, hA, hB, NN, NTN);

    // 7) GraphNorm on hB
    gn_accum <<<EL_GRID, 256>>>(hB, batch);
    gn_mean  <<<GH_GRID, 256>>>();
    gn_center<<<EL_GRID, 256>>>(hB, batch, norm_ms, h1);
    gn_inv   <<<GH_GRID, 256>>>();
    gn_apply <<<EL_GRID, 256>>>(h1, batch, norm_w, norm_b, hA);

    // 8) out = hA @ final_w + final_b
    node_hmma<false,false,false,true><<<148, 512, N1>>>(
        hA, final_w, nullptr, nullptr, final_b, nullptr, out, NN, NTN);
}

// round 9
// speedup vs baseline: 2.3360x; 1.0143x over previous
#include <cuda_runtime.h>
#include <cuda_bf16.h>
#include <math.h>
#include <stdint.h>

// ---------------- problem constants ----------------
#define NN    50000
#define HH    128
#define EE    1000000
#define FF1   147
#define FF2   21
#define GG    512
#define EPSV  1e-5f

// ---------------- device scratch (no allocs allowed) ----------------
__device__ float g_xh  [NN*HH];
__device__ float g_agg1[NN*HH];
__device__ float g_agg2[NN*HH];
__device__ float g_tmp [NN*HH];
__device__ float g_h1  [NN*HH];
__device__ float g_h2  [NN*HH];
__device__ float g_hA  [NN*HH];
__device__ float g_hB  [NN*HH];
__device__ float g_gsum[GG*HH];
__device__ float g_gvar[GG*HH];
__device__ float g_gcnt[GG];

// ================= warp-MMA helpers (baseline PTX, sm_80+) =================
__device__ __forceinline__ void mma_bf16(float d[4], const uint32_t a[4], const uint32_t b[2]) {
    asm volatile(
        "mma.sync.aligned.m16n8k16.row.col.f32.bf16.bf16.f32 "
        "{%0,%1,%2,%3}, {%4,%5,%6,%7}, {%8,%9}, {%0,%1,%2,%3};"
        : "+f"(d[0]), "+f"(d[1]), "+f"(d[2]), "+f"(d[3])
        : "r"(a[0]), "r"(a[1]), "r"(a[2]), "r"(a[3]), "r"(b[0]), "r"(b[1]));
}

__device__ __forceinline__ void ldsm4(uint32_t r[4], uint32_t addr) {
    asm volatile("ldmatrix.sync.aligned.m8n8.x4.shared.b16 {%0,%1,%2,%3}, [%4];"
        : "=r"(r[0]), "=r"(r[1]), "=r"(r[2]), "=r"(r[3]) : "r"(addr));
}

__device__ __forceinline__ uint32_t smaddr(const void* p) {
    return (uint32_t)__cvta_generic_to_shared(p);
}

__device__ __forceinline__ void split_bf16(float f, __nv_bfloat16& h, __nv_bfloat16& l) {
    h = __float2bfloat16_rn(f);
    l = __float2bfloat16_rn(f - __bfloat162float(h));
}

__device__ __forceinline__ void split_pack2(float f0, float f1, uint32_t& hi, uint32_t& lo) {
    __nv_bfloat16 h0, l0, h1, l1;
    split_bf16(f0, h0, l0);
    split_bf16(f1, h1, l1);
    hi = (uint32_t)__bfloat16_as_ushort(h0) | ((uint32_t)__bfloat16_as_ushort(h1) << 16);
    lo = (uint32_t)__bfloat16_as_ushort(l0) | ((uint32_t)__bfloat16_as_ushort(l1) << 16);
}

// ldmatrix per-lane address offsets (bytes), relative to (row0, ko) = (0, 0):
//  A-style x4: matrices (r0..r7,k0..7),(r8..15,k0..7),(r0..7,k8..15),(r8..15,k8..15)
//  B-style x4: two n8k16 fragments (n0..7) and (n8..15)
#define OFF_A(lane, stride) ((((lane) & 15) * (stride) + (((lane) >> 4) << 3)) * 2)
#define OFF_B(lane, stride) (((((lane) & 7) + (((lane) >> 4) << 3)) * (stride) + ((((lane) >> 3) & 1) << 3)) * 2)

// ---------------- edge kernel smem layout ----------------
template<int F> struct EL {
    static constexpr int KP  = (F + 15) & ~15;
    static constexpr int SA  = KP + 8;                 // bf16 elems/row (A, W1T)
    static constexpr int W1H = 0;
    static constexpr int W1L = W1H + 64 * SA * 2;
    static constexpr int W2H = W1L + 64 * SA * 2;
    static constexpr int W2L = W2H + 128 * 72 * 2;
    static constexpr int MIH = W2L + 128 * 72 * 2;     // mid hi; o-halves alias here
    static constexpr int MIL = MIH + 128 * 72 * 2;
    static constexpr int A1H = MIL + 128 * 72 * 2;
    static constexpr int A1L = A1H + 128 * SA * 2;
    static constexpr int IDX = A1L + 128 * SA * 2;     // 2 x 256 ints (double-buffered)
    static constexpr int TOT = IDX + 2048;
};

// ================= fused edge kernel (pipelined, ldmatrix) =================
template<int F, int MINB>
__global__ void __launch_bounds__(256, MINB) edge_fused(
    const float* __restrict__ feat, const float* __restrict__ w1,
    const float* __restrict__ w2,   const float* __restrict__ xh,
    const int* __restrict__ src,    const int* __restrict__ dst,
    float* __restrict__ agg, int ntiles)
{
    using L = EL<F>;
    extern __shared__ char smem[];
    __nv_bfloat16* w1h = (__nv_bfloat16*)(smem + L::W1H);
    __nv_bfloat16* w1l = (__nv_bfloat16*)(smem + L::W1L);
    __nv_bfloat16* w2h = (__nv_bfloat16*)(smem + L::W2H);
    __nv_bfloat16* w2l = (__nv_bfloat16*)(smem + L::W2L);
    __nv_bfloat16* mih = (__nv_bfloat16*)(smem + L::MIH);
    __nv_bfloat16* mil = (__nv_bfloat16*)(smem + L::MIL);
    __nv_bfloat16* a1h = (__nv_bfloat16*)(smem + L::A1H);
    __nv_bfloat16* a1l = (__nv_bfloat16*)(smem + L::A1L);
    float*         ob  = (float*)        (smem + L::MIH);   // 64 x 132 f32 (aliases MI)
    int*           sidx= (int*)          (smem + L::IDX);   // 2 buffers x 256

    const int tid  = threadIdx.x;
    const int wid  = tid >> 5, lane = tid & 31;
    const int g    = lane >> 2, tq = lane & 3;
    const int wm   = wid & 3, wn = wid >> 2;

    const uint32_t bA1h = smaddr(a1h), bA1l = smaddr(a1l);
    const uint32_t bW1h = smaddr(w1h), bW1l = smaddr(w1l);
    const uint32_t bW2h = smaddr(w2h), bW2l = smaddr(w2l);
    const uint32_t bMih = smaddr(mih), bMil = smaddr(mil);
    const int oA_SA = OFF_A(lane, L::SA), oB_SA = OFF_B(lane, L::SA);
    const int oA_72 = OFF_A(lane, 72),    oB_72 = OFF_B(lane, 72);

    // zero once: weight pads + A pads must be 0 (never clobbered afterwards)
    for (int i = tid; i < L::TOT / 4; i += 256)
        reinterpret_cast<uint32_t*>(smem)[i] = 0;
    __syncthreads();

    // stage weights transposed + split. w1 gmem [F][64], w2 gmem [64][128]
    for (int i = tid; i < F * 64; i += 256) {
        int k = i >> 6, n = i & 63;
        __nv_bfloat16 h, l; split_bf16(w1[i], h, l);
        w1h[n * L::SA + k] = h;  w1l[n * L::SA + k] = l;
    }
    for (int i = tid; i < 64 * 128; i += 256) {
        int k = i >> 7, n = i & 127;
        __nv_bfloat16 h, l; split_bf16(w2[i], h, l);
        w2h[n * 72 + k] = h;  w2l[n * 72 + k] = l;
    }

    auto stage = [&](int tt, int parity) {
        if (tt >= ntiles) return;
        const int se0 = tt * 128;
        const int scnt = min(128, EE - se0);
        const float* fb = feat + (size_t)se0 * F;
        for (int i = tid; i < scnt * F; i += 256) {
            int e = i / F, k = i - e * F;
            __nv_bfloat16 h, l; split_bf16(fb[i], h, l);
            a1h[e * L::SA + k] = h;  a1l[e * L::SA + k] = l;
        }
        int* sx = sidx + parity * 256;
        if (tid < scnt) { sx[tid] = src[se0 + tid]; sx[128 + tid] = dst[se0 + tid]; }
    };

    int t = blockIdx.x, pb = 0;
    stage(t, 0);
    __syncthreads();

    for (; t < ntiles; t += gridDim.x) {
        const int cnt = min(128, EE - t * 128);
        const int* sx = sidx + pb * 256;

        // ---- GEMM1: [128, KP] x [KP, 64] -> mid ----
        {
            const int mo = wm * 32, no = wn * 32;
            float acc[2][4][4];
            #pragma unroll
            for (int a = 0; a < 2; ++a)
                #pragma unroll
                for (int b = 0; b < 4; ++b)
                    #pragma unroll
                    for (int c = 0; c < 4; ++c) acc[a][b][c] = 0.f;

            #pragma unroll
            for (int ko = 0; ko < L::KP; ko += 16) {
                uint32_t Ah[2][4], Al[2][4];
                #pragma unroll
                for (int mt = 0; mt < 2; ++mt) {
                    const int rb2 = ((mo + mt*16) * L::SA + ko) * 2;
                    ldsm4(Ah[mt], bA1h + rb2 + oA_SA);
                    ldsm4(Al[mt], bA1l + rb2 + oA_SA);
                }
                uint32_t Bh[4][2], Bl[4][2];
                #pragma unroll
                for (int p = 0; p < 2; ++p) {
                    const int nb2 = ((no + p*16) * L::SA + ko) * 2;
                    uint32_t tr[4];
                    ldsm4(tr, bW1h + nb2 + oB_SA);
                    Bh[2*p][0]=tr[0]; Bh[2*p][1]=tr[1]; Bh[2*p+1][0]=tr[2]; Bh[2*p+1][1]=tr[3];
                    ldsm4(tr, bW1l + nb2 + oB_SA);
                    Bl[2*p][0]=tr[0]; Bl[2*p][1]=tr[1]; Bl[2*p+1][0]=tr[2]; Bl[2*p+1][1]=tr[3];
                }
                #pragma unroll
                for (int nt = 0; nt < 4; ++nt)
                    #pragma unroll
                    for (int mt = 0; mt < 2; ++mt) {
                        mma_bf16(acc[mt][nt], Ah[mt], Bh[nt]);
                        mma_bf16(acc[mt][nt], Ah[mt], Bl[nt]);
                        mma_bf16(acc[mt][nt], Al[mt], Bh[nt]);
                    }
            }
            #pragma unroll
            for (int mt = 0; mt < 2; ++mt)
                #pragma unroll
                for (int nt = 0; nt < 4; ++nt) {
                    int r0 = mo + mt*16 + g, col = no + nt*8 + tq*2;
                    uint32_t hi, lo;
                    split_pack2(acc[mt][nt][0], acc[mt][nt][1], hi, lo);
                    *reinterpret_cast<uint32_t*>(&mih[r0*72 + col]) = hi;
                    *reinterpret_cast<uint32_t*>(&mil[r0*72 + col]) = lo;
                    split_pack2(acc[mt][nt][2], acc[mt][nt][3], hi, lo);
                    *reinterpret_cast<uint32_t*>(&mih[(r0+8)*72 + col]) = hi;
                    *reinterpret_cast<uint32_t*>(&mil[(r0+8)*72 + col]) = lo;
                }
        }
        __syncthreads();   // mid visible; A now dead (stageable)

        // ---- GEMM2 (K=64) ----
        float acc[2][8][4];
        {
            const int mo = wm * 32, no = wn * 64;
            #pragma unroll
            for (int a = 0; a < 2; ++a)
                #pragma unroll
                for (int b = 0; b < 8; ++b)
                    #pragma unroll
                    for (int c = 0; c < 4; ++c) acc[a][b][c] = 0.f;

            #pragma unroll
            for (int ko = 0; ko < 64; ko += 16) {
                uint32_t Ah[2][4], Al[2][4];
                #pragma unroll
                for (int mt = 0; mt < 2; ++mt) {
                    const int rb2 = ((mo + mt*16) * 72 + ko) * 2;
                    ldsm4(Ah[mt], bMih + rb2 + oA_72);
                    ldsm4(Al[mt], bMil + rb2 + oA_72);
                }
                uint32_t Bh[8][2], Bl[8][2];
                #pragma unroll
                for (int p = 0; p < 4; ++p) {
                    const int nb2 = ((no + p*16) * 72 + ko) * 2;
                    uint32_t tr[4];
                    ldsm4(tr, bW2h + nb2 + oB_72);
                    Bh[2*p][0]=tr[0]; Bh[2*p][1]=tr[1]; Bh[2*p+1][0]=tr[2]; Bh[2*p+1][1]=tr[3];
                    ldsm4(tr, bW2l + nb2 + oB_72);
                    Bl[2*p][0]=tr[0]; Bl[2*p][1]=tr[1]; Bl[2*p+1][0]=tr[2]; Bl[2*p+1][1]=tr[3];
                }
                #pragma unroll
                for (int nt = 0; nt < 8; ++nt)
                    #pragma unroll
                    for (int mt = 0; mt < 2; ++mt) {
                        mma_bf16(acc[mt][nt], Ah[mt], Bh[nt]);
                        mma_bf16(acc[mt][nt], Ah[mt], Bl[nt]);
                        mma_bf16(acc[mt][nt], Al[mt], Bh[nt]);
                    }
            }
        }
        __syncthreads();   // MI reads done -> ob region writable

        // ---- per half: store o rows into ob, then epilogue;
        //      next tile's A staging rides in the half-0 epilogue phase ----
        #pragma unroll
        for (int half = 0; half < 2; ++half) {
            if ((wm >> 1) == half) {
                const int mo = wm * 32, no = wn * 64;
                #pragma unroll
                for (int mt = 0; mt < 2; ++mt)
                    #pragma unroll
                    for (int nt = 0; nt < 8; ++nt) {
                        int rl = mo + mt*16 + g - half*64, col = no + nt*8 + tq*2;
                        *reinterpret_cast<float2*>(&ob[rl*132 + col]) =
                            make_float2(acc[mt][nt][0], acc[mt][nt][1]);
                        *reinterpret_cast<float2*>(&ob[(rl+8)*132 + col]) =
                            make_float2(acc[mt][nt][2], acc[mt][nt][3]);
                    }
            }
            __syncthreads();
            {
                const int c = tid & 127, eh = tid >> 7;
                const int lim = min(cnt - half*64, 64);
                for (int e = eh; e < lim; e += 2) {
                    int eg = half*64 + e;
                    int s = sx[eg], d = sx[128 + eg];
                    float v = ob[e * 132 + c] * xh[(size_t)s * 128 + c];
                    atomicAdd(&agg[(size_t)d * 128 + c], v);
                }
            }
            if (half == 0) stage(t + gridDim.x, pb ^ 1);
            __syncthreads();
        }
        pb ^= 1;
    }
}

// ================= node GEMM on HMMA (ldmatrix) =================
template<bool HAS_A2, bool ACT, bool HAS_RES, bool DB>
__global__ void __launch_bounds__(512) node_hmma(
    const float* __restrict__ A,  const float* __restrict__ W,
    const float* __restrict__ A2, const float* __restrict__ W2,
    const float* __restrict__ bias, const float* __restrict__ res,
    float* __restrict__ out, int nrows, int ntiles)
{
    static_assert(!(HAS_A2 && DB), "DB only for single-A variant");
    constexpr int WS = 128 * 136 * 2;      // 34816 bytes per plane
    constexpr int NWP = HAS_A2 ? 4 : 2;
    constexpr int NAP = DB ? 4 : 2;
    extern __shared__ char smem[];
    __nv_bfloat16* wh  = (__nv_bfloat16*)(smem);
    __nv_bfloat16* wl  = (__nv_bfloat16*)(smem + WS);
    __nv_bfloat16* w2h = (__nv_bfloat16*)(smem + 2 * WS);
    __nv_bfloat16* w2l = (__nv_bfloat16*)(smem + 3 * WS);
    float*         bs  = (float*)        (smem + (NWP + NAP) * WS);

    const int tid = threadIdx.x;
    const int wid = tid >> 5, lane = tid & 31;
    const int g = lane >> 2, tq = lane & 3;
    const int wm = wid & 7, wn = wid >> 3;
    const int mo = wm * 16, no = wn * 64;
    const int oA = OFF_A(lane, 136), oB = OFF_B(lane, 136);

    // stage weights (transposed, split) + bias
    for (int i = tid; i < 128 * 128; i += 512) {
        int k = i >> 7, n = i & 127;
        __nv_bfloat16 h, l; split_bf16(W[i], h, l);
        wh[n * 136 + k] = h;  wl[n * 136 + k] = l;
        if (HAS_A2) {
            split_bf16(W2[i], h, l);
            w2h[n * 136 + k] = h;  w2l[n * 136 + k] = l;
        }
    }
    if (tid < 128) bs[tid] = bias[tid];

    auto a_hi = [&](int p) { return (__nv_bfloat16*)(smem + (NWP + p * 2) * WS); };
    auto a_lo = [&](int p) { return (__nv_bfloat16*)(smem + (NWP + p * 2 + 1) * WS); };

    auto stageA = [&](const float* __restrict__ src_, int tt, int p) {
        if (tt >= ntiles) return;
        const int rb = tt * 128;
        __nv_bfloat16* dh = a_hi(p);
        __nv_bfloat16* dl = a_lo(p);
        for (int i = tid; i < 128 * 128; i += 512) {
            int e = i >> 7, k = i & 127;
            int r = rb + e;
            float v = (r < nrows) ? src_[(size_t)r * 128 + k] : 0.f;
            __nv_bfloat16 h, l; split_bf16(v, h, l);
            dh[e * 136 + k] = h;  dl[e * 136 + k] = l;
        }
    };

    auto run_mma = [&](float acc[8][4], const __nv_bfloat16* ahp, const __nv_bfloat16* alp,
                       const __nv_bfloat16* bhp, const __nv_bfloat16* blp) {
        const uint32_t bAh = smaddr(ahp), bAl = smaddr(alp);
        const uint32_t bBh = smaddr(bhp), bBl = smaddr(blp);
        #pragma unroll
        for (int ko = 0; ko < 128; ko += 16) {
            uint32_t Ah[4], Al[4];
            const int rb2 = (mo * 136 + ko) * 2;
            ldsm4(Ah, bAh + rb2 + oA);
            ldsm4(Al, bAl + rb2 + oA);
            #pragma unroll
            for (int p = 0; p < 4; ++p) {
                const int nb2 = ((no + p*16) * 136 + ko) * 2;
                uint32_t th[4], tl[4];
                ldsm4(th, bBh + nb2 + oB);
                ldsm4(tl, bBl + nb2 + oB);
                uint32_t B0h[2] = {th[0], th[1]}, B1h[2] = {th[2], th[3]};
                uint32_t B0l[2] = {tl[0], tl[1]}, B1l[2] = {tl[2], tl[3]};
                mma_bf16(acc[2*p],   Ah, B0h);
                mma_bf16(acc[2*p],   Ah, B0l);
                mma_bf16(acc[2*p],   Al, B0h);
                mma_bf16(acc[2*p+1], Ah, B1h);
                mma_bf16(acc[2*p+1], Ah, B1l);
                mma_bf16(acc[2*p+1], Al, B1h);
            }
        }
    };

    auto epilogue = [&](float acc[8][4], int rb) {
        #pragma unroll
        for (int nt = 0; nt < 8; ++nt) {
            const int c = no + nt*8 + tq*2;
            const float b0 = bs[c], b1 = bs[c + 1];
            #pragma unroll
            for (int half = 0; half < 2; ++half) {
                int r = rb + mo + g + half*8;
                if (r < nrows) {
                    float v0 = acc[nt][half*2]     + b0;
                    float v1 = acc[nt][half*2 + 1] + b1;
                    if (ACT) { v0 = v0 / (1.f + expf(-v0)); v1 = v1 / (1.f + expf(-v1)); }
                    if (HAS_RES) {
                        float2 rr = *reinterpret_cast<const float2*>(&res[(size_t)r*128 + c]);
                        v0 += rr.x; v1 += rr.y;
                    }
                    *reinterpret_cast<float2*>(&out[(size_t)r*128 + c]) = make_float2(v0, v1);
                }
            }
        }
    };

    if (DB) {
        int t = blockIdx.x, pb = 0;
        stageA(A, t, 0);
        __syncthreads();
        for (; t < ntiles; t += gridDim.x) {
            float acc[8][4];
            #pragma unroll
            for (int b = 0; b < 8; ++b)
                #pragma unroll
                for (int c = 0; c < 4; ++c) acc[b][c] = 0.f;
            run_mma(acc, a_hi(pb), a_lo(pb), wh, wl);
            stageA(A, t + gridDim.x, pb ^ 1);
            epilogue(acc, t * 128);
            pb ^= 1;
            __syncthreads();
        }
    } else {
        __syncthreads();
        for (int t = blockIdx.x; t < ntiles; t += gridDim.x) {
            stageA(A, t, 0);
            __syncthreads();
            float acc[8][4];
            #pragma unroll
            for (int b = 0; b < 8; ++b)
                #pragma unroll
                for (int c = 0; c < 4; ++c) acc[b][c] = 0.f;
            run_mma(acc, a_hi(0), a_lo(0), wh, wl);
            if (HAS_A2) {
                __syncthreads();
                stageA(A2, t, 0);
                __syncthreads();
                run_mma(acc, a_hi(0), a_lo(0), w2h, w2l);
            }
            epilogue(acc, t * 128);
            __syncthreads();
        }
    }
}

// ---------------- zero init ----------------
__global__ void zero_bufs_kernel() {
    int idx = blockIdx.x * blockDim.x + threadIdx.x;
    if (idx < NN*HH) { g_agg1[idx] = 0.f; g_agg2[idx] = 0.f; }
    if (idx < GG*HH) { g_gsum[idx] = 0.f; g_gvar[idx] = 0.f; }
    if (idx < GG)    { g_gcnt[idx] = 0.f; }
}

// ---------------- GraphNorm kernels ----------------
__global__ void gn_accum(const float* __restrict__ h, const int* __restrict__ batch) {
    int idx = blockIdx.x * blockDim.x + threadIdx.x;
    if (idx >= NN*HH) return;
    int n = idx >> 7, c = idx & 127;
    int b = batch[n];
    atomicAdd(&g_gsum[b*128 + c], h[idx]);
    if (c == 0) atomicAdd(&g_gcnt[b], 1.f);
}
__global__ void gn_mean() {
    int idx = blockIdx.x * blockDim.x + threadIdx.x;
    if (idx >= GG*HH) return;
    int g = idx >> 7;
    g_gsum[idx] /= fmaxf(g_gcnt[g], 1.f);
}
__global__ void gn_center(const float* __restrict__ h, const int* __restrict__ batch,
                          const float* __restrict__ ms, float* __restrict__ out) {
    int idx = blockIdx.x * blockDim.x + threadIdx.x;
    if (idx >= NN*HH) return;
    int n = idx >> 7, c = idx & 127;
    int b = batch[n];
    float o = h[idx] - g_gsum[b*128 + c] * ms[c];
    out[idx] = o;
    atomicAdd(&g_gvar[b*128 + c], o*o);
}
__global__ void gn_inv() {
    int idx = blockIdx.x * blockDim.x + threadIdx.x;
    if (idx >= GG*HH) return;
    int g = idx >> 7;
    g_gvar[idx] = rsqrtf(g_gvar[idx] / fmaxf(g_gcnt[g], 1.f) + EPSV);
}
__global__ void gn_apply(const float* __restrict__ cent, const int* __restrict__ batch,
                         const float* __restrict__ nw, const float* __restrict__ nb,
                         float* __restrict__ out) {
    int idx = blockIdx.x * blockDim.x + threadIdx.x;
    if (idx >= NN*HH) return;
    int n = idx >> 7, c = idx & 127;
    int b = batch[n];
    out[idx] = nw[c] * cent[idx] * g_gvar[b*128 + c] + nb[c];
}

// ---------------- host launcher ----------------
static inline void set_smem(const void* f, int bytes) {
    cudaFuncSetAttribute(f, cudaFuncAttributeMaxDynamicSharedMemorySize, bytes);
}

extern "C" void kernel_launch(void* const* d_in, const int* in_sizes, int n_in,
                              void* d_out, int out_size) {
    (void)in_sizes; (void)n_in; (void)out_size;

    const float* x          = (const float*)d_in[0];
    const float* feature1   = (const float*)d_in[1];
    const float* feature2   = (const float*)d_in[2];
    const int*   edge_index = (const int*)  d_in[3];
    const int*   batch      = (const int*)  d_in[4];
    const float* lin_w      = (const float*)d_in[5];
    const float* lin_b      = (const float*)d_in[6];
    const float* f1_w1      = (const float*)d_in[7];
    const float* f1_w2      = (const float*)d_in[8];
    const float* f2_w1      = (const float*)d_in[9];
    const float* f2_w2      = (const float*)d_in[10];
    const float* c1_rel_w   = (const float*)d_in[11];
    const float* c1_rel_b   = (const float*)d_in[12];
    const float* c1_root_w  = (const float*)d_in[13];
    const float* c2_rel_w   = (const float*)d_in[14];
    const float* c2_rel_b   = (const float*)d_in[15];
    const float* c2_root_w  = (const float*)d_in[16];
    const float* lin1_w     = (const float*)d_in[17];
    const float* lin1_b     = (const float*)d_in[18];
    const float* lin2_w     = (const float*)d_in[19];
    const float* lin2_b     = (const float*)d_in[20];
    const float* lincat_w   = (const float*)d_in[21];
    const float* lincat_b   = (const float*)d_in[22];
    const float* norm_w     = (const float*)d_in[23];
    const float* norm_b     = (const float*)d_in[24];
    const float* norm_ms    = (const float*)d_in[25];
    const float* lins_w     = (const float*)d_in[26];
    const float* lins_b     = (const float*)d_in[27];
    const float* final_w    = (const float*)d_in[28];
    const float* final_b    = (const float*)d_in[29];
    float* out = (float*)d_out;

    const int* src = edge_index;
    const int* dst = edge_index + EE;

    float *xh, *agg1, *agg2, *tmp, *h1, *h2, *hA, *hB;
    cudaGetSymbolAddress((void**)&xh,   g_xh);
    cudaGetSymbolAddress((void**)&agg1, g_agg1);
    cudaGetSymbolAddress((void**)&agg2, g_agg2);
    cudaGetSymbolAddress((void**)&tmp,  g_tmp);
    cudaGetSymbolAddress((void**)&h1,   g_h1);
    cudaGetSymbolAddress((void**)&h2,   g_h2);
    cudaGetSymbolAddress((void**)&hA,   g_hA);
    cudaGetSymbolAddress((void**)&hB,   g_hB);

    constexpr int WS = 128 * 136 * 2;
    const int N1 = 6 * WS + 512;   // DB: w(2) + a(4) + bias = 209,408 B
    const int N2 = 6 * WS + 512;   // A2: w(4) + a(2) + bias = 209,408 B

    set_smem((const void*)node_hmma<false,true ,false,true >, N1);
    set_smem((const void*)node_hmma<false,true ,true ,true >, N1);
    set_smem((const void*)node_hmma<false,false,false,true >, N1);
    set_smem((const void*)node_hmma<true ,false,false,false>, N2);
    set_smem((const void*)node_hmma<true ,false,true ,false>, N2);
    set_smem((const void*)edge_fused<FF1,1>, EL<FF1>::TOT);
    set_smem((const void*)edge_fused<FF2,2>, EL<FF2>::TOT);

    const int EL_GRID = (NN*HH + 255) / 256;
    const int GH_GRID = (GG*HH + 255) / 256;
    const int NT      = (EE + 127) / 128;   // 7813
    const int NTN     = (NN + 127) / 128;   // 391

    // 0) zero accumulators
    zero_bufs_kernel<<<EL_GRID, 256>>>();

    // 1) xh = swish(x @ lin_w + lin_b)
    node_hmma<false,true,false,true><<<148, 512, N1>>>(
        x, lin_w, nullptr, nullptr, lin_b, nullptr, xh, NN, NTN);

    // 2) fused edge messages (HMMA + ldmatrix, pipelined)
    edge_fused<FF1,1><<<148, 256, EL<FF1>::TOT>>>(feature1, f1_w1, f1_w2, xh, src, dst, agg1, NT);
    edge_fused<FF2,2><<<296, 256, EL<FF2>::TOT>>>(feature2, f2_w1, f2_w2, xh, src, dst, agg2, NT);

    // 3) conv1
    node_hmma<true,false,false,false><<<148, 512, N2>>>(
        agg1, c1_rel_w, xh, c1_root_w, c1_rel_b, nullptr, tmp, NN, NTN);
    node_hmma<false,true,false,true><<<148, 512, N1>>>(
        tmp, lin1_w, nullptr, nullptr, lin1_b, nullptr, h1, NN, NTN);

    // 4) conv2
    node_hmma<true,false,false,false><<<148, 512, N2>>>(
        agg2, c2_rel_w, xh, c2_root_w, c2_rel_b, nullptr, tmp, NN, NTN);
    node_hmma<false,true,false,true><<<148, 512, N1>>>(
        tmp, lin2_w, nullptr, nullptr, lin2_b, nullptr, h2, NN, NTN);

    // 5) hA = h1@Wtop + h2@Wbot + lincat_b + xh
    node_hmma<true,false,true,false><<<148, 512, N2>>>(
        h1, lincat_w, h2, lincat_w + 128*128, lincat_b, xh, hA, NN, NTN);

    // 6) residual stack: h = swish(h@Wi + bi) + h
    node_hmma<false,true,true,true><<<148, 512, N1>>>(
        hA, lins_w + 0*16384, nullptr, nullptr, lins_b + 0*128, hA, hB, NN, NTN);
    node_hmma<false,true,true,true><<<148, 512, N1>>>(
        hB, lins_w + 1*16384, nullptr, nullptr, lins_b + 1*128, hB, hA, NN, NTN);
    node_hmma<false,true,true,true><<<148, 512, N1>>>(
        hA, lins_w + 2*16384, nullptr, nullptr, lins_b + 2*128, hA, hB, NN, NTN);

    // 7) GraphNorm on hB
    gn_accum <<<EL_GRID, 256>>>(hB, batch);
    gn_mean  <<<GH_GRID, 256>>>();
    gn_center<<<EL_GRID, 256>>>(hB, batch, norm_ms, h1);
    gn_inv   <<<GH_GRID, 256>>>();
    gn_apply <<<EL_GRID, 256>>>(h1, batch, norm_w, norm_b, hA);

    // 8) out = hA @ final_w + final_b
    node_hmma<false,false,false,true><<<148, 512, N1>>>(
        hA, final_w, nullptr, nullptr, final_b, nullptr, out, NN, NTN);
}

// round 11
// speedup vs baseline: 2.8909x; 1.2375x over previous
#include <cuda_runtime.h>
#include <cuda_bf16.h>
#include <math.h>
#include <stdint.h>

// ---------------- problem constants ----------------
#define NN    50000
#define HH    128
#define EE    1000000
#define FF1   147
#define FF2   21
#define GG    512
#define EPSV  1e-5f

// ---------------- device scratch (no allocs allowed) ----------------
__device__ float g_xh  [NN*HH];
__device__ float g_agg1[NN*HH];
__device__ float g_agg2[NN*HH];
__device__ float g_tmp [NN*HH];
__device__ float g_h1  [NN*HH];
__device__ float g_h2  [NN*HH];
__device__ float g_hA  [NN*HH];
__device__ float g_hB  [NN*HH];
__device__ float g_gsum[GG*HH];
__device__ float g_gvar[GG*HH];
__device__ float g_gcnt[GG];

// ================= warp-MMA helpers (baseline PTX, sm_80+) =================
__device__ __forceinline__ void mma_bf16(float d[4], const uint32_t a[4], const uint32_t b[2]) {
    asm volatile(
        "mma.sync.aligned.m16n8k16.row.col.f32.bf16.bf16.f32 "
        "{%0,%1,%2,%3}, {%4,%5,%6,%7}, {%8,%9}, {%0,%1,%2,%3};"
        : "+f"(d[0]), "+f"(d[1]), "+f"(d[2]), "+f"(d[3])
        : "r"(a[0]), "r"(a[1]), "r"(a[2]), "r"(a[3]), "r"(b[0]), "r"(b[1]));
}

__device__ __forceinline__ void ldsm4(uint32_t r[4], uint32_t addr) {
    asm volatile("ldmatrix.sync.aligned.m8n8.x4.shared.b16 {%0,%1,%2,%3}, [%4];"
        : "=r"(r[0]), "=r"(r[1]), "=r"(r[2]), "=r"(r[3]) : "r"(addr));
}

__device__ __forceinline__ uint32_t smaddr(const void* p) {
    return (uint32_t)__cvta_generic_to_shared(p);
}

// element-wise vector atomic add (sm_90+ baseline PTX)
__device__ __forceinline__ void red_add_v4(float* p, float4 v) {
    asm volatile("red.global.add.v4.f32 [%0], {%1,%2,%3,%4};"
        :: "l"(p), "f"(v.x), "f"(v.y), "f"(v.z), "f"(v.w) : "memory");
}

__device__ __forceinline__ void split_bf16(float f, __nv_bfloat16& h, __nv_bfloat16& l) {
    h = __float2bfloat16_rn(f);
    l = __float2bfloat16_rn(f - __bfloat162float(h));
}

__device__ __forceinline__ void split_pack2(float f0, float f1, uint32_t& hi, uint32_t& lo) {
    __nv_bfloat16 h0, l0, h1, l1;
    split_bf16(f0, h0, l0);
    split_bf16(f1, h1, l1);
    hi = (uint32_t)__bfloat16_as_ushort(h0) | ((uint32_t)__bfloat16_as_ushort(h1) << 16);
    lo = (uint32_t)__bfloat16_as_ushort(l0) | ((uint32_t)__bfloat16_as_ushort(l1) << 16);
}

// ldmatrix per-lane byte offsets relative to (row0, k0)
#define OFF_A(lane, stride) ((((lane) & 15) * (stride) + (((lane) >> 4) << 3)) * 2)
#define OFF_B(lane, stride) (((((lane) & 7) + (((lane) >> 4) << 3)) * (stride) + ((((lane) >> 3) & 1) << 3)) * 2)

// ---------------- edge kernel smem layout ----------------
template<int F> struct EL {
    static constexpr int KP  = (F + 15) & ~15;
    static constexpr int SA  = KP + 8;                 // bf16 elems/row (A, W1T)
    static constexpr int W1H = 0;
    static constexpr int W1L = W1H + 64 * SA * 2;
    static constexpr int W2H = W1L + 64 * SA * 2;
    static constexpr int W2L = W2H + 128 * 72 * 2;
    static constexpr int MIH = W2L + 128 * 72 * 2;     // mid hi; o-halves alias here
    static constexpr int MIL = MIH + 128 * 72 * 2;
    static constexpr int A1H = MIL + 128 * 72 * 2;
    static constexpr int A1L = A1H + 128 * SA * 2;
    static constexpr int IDX = A1L + 128 * SA * 2;     // 2 x 256 ints
    static constexpr int TOT = IDX + 2048;
};

// ================= fused edge kernel (pipelined, ldmatrix, templated width) ========
// NTHR=256: 8 warps (4 m-warps x 32 rows); NTHR=512: 16 warps (8 m-warps x 16 rows)
template<int F, int NTHR, int MINB>
__global__ void __launch_bounds__(NTHR, MINB) edge_fused(
    const float* __restrict__ feat, const float* __restrict__ w1,
    const float* __restrict__ w2,   const float* __restrict__ xh,
    const int* __restrict__ src,    const int* __restrict__ dst,
    float* __restrict__ agg, int ntiles)
{
    using L = EL<F>;
    constexpr int MW = NTHR / 64;      // # m-warps
    constexpr int RM = 128 / MW;       // rows per m-warp
    constexpr int MT = RM / 16;        // 16-row tiles per warp
    constexpr int ES = NTHR / 32;      // epilogue edge stride

    extern __shared__ char smem[];
    __nv_bfloat16* w1h = (__nv_bfloat16*)(smem + L::W1H);
    __nv_bfloat16* w1l = (__nv_bfloat16*)(smem + L::W1L);
    __nv_bfloat16* w2h = (__nv_bfloat16*)(smem + L::W2H);
    __nv_bfloat16* w2l = (__nv_bfloat16*)(smem + L::W2L);
    __nv_bfloat16* mih = (__nv_bfloat16*)(smem + L::MIH);
    __nv_bfloat16* mil = (__nv_bfloat16*)(smem + L::MIL);
    __nv_bfloat16* a1h = (__nv_bfloat16*)(smem + L::A1H);
    __nv_bfloat16* a1l = (__nv_bfloat16*)(smem + L::A1L);
    float*         ob  = (float*)        (smem + L::MIH);   // 64 x 132 f32 (aliases MI)
    int*           sidx= (int*)          (smem + L::IDX);

    const int tid  = threadIdx.x;
    const int wid  = tid >> 5, lane = tid & 31;
    const int g    = lane >> 2, tq = lane & 3;
    const int wm   = wid & (MW - 1), wn = wid / MW;

    const uint32_t bA1h = smaddr(a1h), bA1l = smaddr(a1l);
    const uint32_t bW1h = smaddr(w1h), bW1l = smaddr(w1l);
    const uint32_t bW2h = smaddr(w2h), bW2l = smaddr(w2l);
    const uint32_t bMih = smaddr(mih), bMil = smaddr(mil);
    const int oA_SA = OFF_A(lane, L::SA), oB_SA = OFF_B(lane, L::SA);
    const int oA_72 = OFF_A(lane, 72),    oB_72 = OFF_B(lane, 72);

    // zero once: weight pads + A pads must stay 0
    for (int i = tid; i < L::TOT / 4; i += NTHR)
        reinterpret_cast<uint32_t*>(smem)[i] = 0;
    __syncthreads();

    // stage weights transposed + split. w1 gmem [F][64], w2 gmem [64][128]
    for (int i = tid; i < F * 64; i += NTHR) {
        int k = i >> 6, n = i & 63;
        __nv_bfloat16 h, l; split_bf16(w1[i], h, l);
        w1h[n * L::SA + k] = h;  w1l[n * L::SA + k] = l;
    }
    for (int i = tid; i < 32 * 128; i += NTHR) {        // paired k/k+1 -> STS.32
        int n = i & 127, k = (i >> 7) * 2;
        __nv_bfloat16 h0, l0, h1, l1;
        split_bf16(w2[k * 128 + n], h0, l0);
        split_bf16(w2[(k + 1) * 128 + n], h1, l1);
        *reinterpret_cast<uint32_t*>(&w2h[n * 72 + k]) =
            (uint32_t)__bfloat16_as_ushort(h0) | ((uint32_t)__bfloat16_as_ushort(h1) << 16);
        *reinterpret_cast<uint32_t*>(&w2l[n * 72 + k]) =
            (uint32_t)__bfloat16_as_ushort(l0) | ((uint32_t)__bfloat16_as_ushort(l1) << 16);
    }

    auto stage = [&](int tt, int parity) {
        if (tt >= ntiles) return;
        const int se0 = tt * 128;
        const int scnt = min(128, EE - se0);
        const float* fb = feat + (size_t)se0 * F;
        for (int i = tid; i < scnt * F; i += NTHR) {
            int e = i / F, k = i - e * F;
            __nv_bfloat16 h, l; split_bf16(fb[i], h, l);
            a1h[e * L::SA + k] = h;  a1l[e * L::SA + k] = l;
        }
        int* sx = sidx + parity * 256;
        if (tid < scnt) { sx[tid] = src[se0 + tid]; sx[128 + tid] = dst[se0 + tid]; }
    };

    int t = blockIdx.x, pb = 0;
    stage(t, 0);
    __syncthreads();

    for (; t < ntiles; t += gridDim.x) {
        const int cnt = min(128, EE - t * 128);
        const int* sx = sidx + pb * 256;

        // ---- GEMM1: [128, KP] x [KP, 64] -> mid ----
        {
            const int mo = wm * RM, no = wn * 32;
            float acc[MT][4][4];
            #pragma unroll
            for (int a = 0; a < MT; ++a)
                #pragma unroll
                for (int b = 0; b < 4; ++b)
                    #pragma unroll
                    for (int c = 0; c < 4; ++c) acc[a][b][c] = 0.f;

            #pragma unroll
            for (int ko = 0; ko < L::KP; ko += 16) {
                uint32_t Ah[MT][4], Al[MT][4];
                #pragma unroll
                for (int mt = 0; mt < MT; ++mt) {
                    const int rb2 = ((mo + mt*16) * L::SA + ko) * 2;
                    ldsm4(Ah[mt], bA1h + rb2 + oA_SA);
                    ldsm4(Al[mt], bA1l + rb2 + oA_SA);
                }
                uint32_t Bh[4][2], Bl[4][2];
                #pragma unroll
                for (int p = 0; p < 2; ++p) {
                    const int nb2 = ((no + p*16) * L::SA + ko) * 2;
                    uint32_t tr[4];
                    ldsm4(tr, bW1h + nb2 + oB_SA);
                    Bh[2*p][0]=tr[0]; Bh[2*p][1]=tr[1]; Bh[2*p+1][0]=tr[2]; Bh[2*p+1][1]=tr[3];
                    ldsm4(tr, bW1l + nb2 + oB_SA);
                    Bl[2*p][0]=tr[0]; Bl[2*p][1]=tr[1]; Bl[2*p+1][0]=tr[2]; Bl[2*p+1][1]=tr[3];
                }
                #pragma unroll
                for (int nt = 0; nt < 4; ++nt)
                    #pragma unroll
                    for (int mt = 0; mt < MT; ++mt) {
                        mma_bf16(acc[mt][nt], Ah[mt], Bh[nt]);
                        mma_bf16(acc[mt][nt], Ah[mt], Bl[nt]);
                        mma_bf16(acc[mt][nt], Al[mt], Bh[nt]);
                    }
            }
            #pragma unroll
            for (int mt = 0; mt < MT; ++mt)
                #pragma unroll
                for (int nt = 0; nt < 4; ++nt) {
                    int r0 = mo + mt*16 + g, col = no + nt*8 + tq*2;
                    uint32_t hi, lo;
                    split_pack2(acc[mt][nt][0], acc[mt][nt][1], hi, lo);
                    *reinterpret_cast<uint32_t*>(&mih[r0*72 + col]) = hi;
                    *reinterpret_cast<uint32_t*>(&mil[r0*72 + col]) = lo;
                    split_pack2(acc[mt][nt][2], acc[mt][nt][3], hi, lo);
                    *reinterpret_cast<uint32_t*>(&mih[(r0+8)*72 + col]) = hi;
                    *reinterpret_cast<uint32_t*>(&mil[(r0+8)*72 + col]) = lo;
                }
        }
        __syncthreads();   // mid visible; A now dead (stageable)

        // ---- GEMM2 (K=64) ----
        float acc[MT][8][4];
        {
            const int mo = wm * RM, no = wn * 64;
            #pragma unroll
            for (int a = 0; a < MT; ++a)
                #pragma unroll
                for (int b = 0; b < 8; ++b)
                    #pragma unroll
                    for (int c = 0; c < 4; ++c) acc[a][b][c] = 0.f;

            #pragma unroll
            for (int ko = 0; ko < 64; ko += 16) {
                uint32_t Ah[MT][4], Al[MT][4];
                #pragma unroll
                for (int mt = 0; mt < MT; ++mt) {
                    const int rb2 = ((mo + mt*16) * 72 + ko) * 2;
                    ldsm4(Ah[mt], bMih + rb2 + oA_72);
                    ldsm4(Al[mt], bMil + rb2 + oA_72);
                }
                uint32_t Bh[8][2], Bl[8][2];
                #pragma unroll
                for (int p = 0; p < 4; ++p) {
                    const int nb2 = ((no + p*16) * 72 + ko) * 2;
                    uint32_t tr[4];
                    ldsm4(tr, bW2h + nb2 + oB_72);
                    Bh[2*p][0]=tr[0]; Bh[2*p][1]=tr[1]; Bh[2*p+1][0]=tr[2]; Bh[2*p+1][1]=tr[3];
                    ldsm4(tr, bW2l + nb2 + oB_72);
                    Bl[2*p][0]=tr[0]; Bl[2*p][1]=tr[1]; Bl[2*p+1][0]=tr[2]; Bl[2*p+1][1]=tr[3];
                }
                #pragma unroll
                for (int nt = 0; nt < 8; ++nt)
                    #pragma unroll
                    for (int mt = 0; mt < MT; ++mt) {
                        mma_bf16(acc[mt][nt], Ah[mt], Bh[nt]);
                        mma_bf16(acc[mt][nt], Ah[mt], Bl[nt]);
                        mma_bf16(acc[mt][nt], Al[mt], Bh[nt]);
                    }
            }
        }
        __syncthreads();   // MI reads done -> ob region writable

        // ---- per half: store o rows into ob, then vectorized epilogue ----
        #pragma unroll
        for (int half = 0; half < 2; ++half) {
            if (((wm * RM) >> 6) == half) {
                const int mo = wm * RM, no = wn * 64;
                #pragma unroll
                for (int mt = 0; mt < MT; ++mt)
                    #pragma unroll
                    for (int nt = 0; nt < 8; ++nt) {
                        int rl = mo + mt*16 + g - half*64, col = no + nt*8 + tq*2;
                        *reinterpret_cast<float2*>(&ob[rl*132 + col]) =
                            make_float2(acc[mt][nt][0], acc[mt][nt][1]);
                        *reinterpret_cast<float2*>(&ob[(rl+8)*132 + col]) =
                            make_float2(acc[mt][nt][2], acc[mt][nt][3]);
                    }
            }
            __syncthreads();
            {
                const int c4 = (tid & 31) << 2, eh = tid >> 5;
                const int lim = min(cnt - half*64, 64);
                for (int e = eh; e < lim; e += ES) {
                    int eg = half*64 + e;
                    int s = sx[eg], d = sx[128 + eg];
                    float4 ov = *reinterpret_cast<const float4*>(&ob[e*132 + c4]);
                    float4 xv = *reinterpret_cast<const float4*>(&xh[(size_t)s*128 + c4]);
                    red_add_v4(&agg[(size_t)d*128 + c4],
                        make_float4(ov.x*xv.x, ov.y*xv.y, ov.z*xv.z, ov.w*xv.w));
                }
            }
            if (half == 0) stage(t + gridDim.x, pb ^ 1);
            __syncthreads();
        }
        pb ^= 1;
    }
}

// ================= node GEMM on HMMA (ldmatrix, vectorized staging) =================
template<bool HAS_A2, bool ACT, bool HAS_RES, bool DB>
__global__ void __launch_bounds__(512) node_hmma(
    const float* __restrict__ A,  const float* __restrict__ W,
    const float* __restrict__ A2, const float* __restrict__ W2,
    const float* __restrict__ bias, const float* __restrict__ res,
    float* __restrict__ out, int nrows, int ntiles)
{
    static_assert(!(HAS_A2 && DB), "DB only for single-A variant");
    constexpr int WS = 128 * 136 * 2;
    constexpr int NWP = HAS_A2 ? 4 : 2;
    constexpr int NAP = DB ? 4 : 2;
    extern __shared__ char smem[];
    __nv_bfloat16* wh  = (__nv_bfloat16*)(smem);
    __nv_bfloat16* wl  = (__nv_bfloat16*)(smem + WS);
    __nv_bfloat16* w2h = (__nv_bfloat16*)(smem + 2 * WS);
    __nv_bfloat16* w2l = (__nv_bfloat16*)(smem + 3 * WS);
    float*         bs  = (float*)        (smem + (NWP + NAP) * WS);

    const int tid = threadIdx.x;
    const int wid = tid >> 5, lane = tid & 31;
    const int g = lane >> 2, tq = lane & 3;
    const int wm = wid & 7, wn = wid >> 3;
    const int mo = wm * 16, no = wn * 64;
    const int oA = OFF_A(lane, 136), oB = OFF_B(lane, 136);

    // stage weights (transposed, split), paired k/k+1 -> STS.32
    for (int i = tid; i < 64 * 128; i += 512) {
        int n = i & 127, k = (i >> 7) * 2;
        __nv_bfloat16 h0, l0, h1, l1;
        split_bf16(W[k * 128 + n], h0, l0);
        split_bf16(W[(k + 1) * 128 + n], h1, l1);
        *reinterpret_cast<uint32_t*>(&wh[n * 136 + k]) =
            (uint32_t)__bfloat16_as_ushort(h0) | ((uint32_t)__bfloat16_as_ushort(h1) << 16);
        *reinterpret_cast<uint32_t*>(&wl[n * 136 + k]) =
            (uint32_t)__bfloat16_as_ushort(l0) | ((uint32_t)__bfloat16_as_ushort(l1) << 16);
        if (HAS_A2) {
            split_bf16(W2[k * 128 + n], h0, l0);
            split_bf16(W2[(k + 1) * 128 + n], h1, l1);
            *reinterpret_cast<uint32_t*>(&w2h[n * 136 + k]) =
                (uint32_t)__bfloat16_as_ushort(h0) | ((uint32_t)__bfloat16_as_ushort(h1) << 16);
            *reinterpret_cast<uint32_t*>(&w2l[n * 136 + k]) =
                (uint32_t)__bfloat16_as_ushort(l0) | ((uint32_t)__bfloat16_as_ushort(l1) << 16);
        }
    }
    if (tid < 128) bs[tid] = bias[tid];

    auto a_hi = [&](int p) { return (__nv_bfloat16*)(smem + (NWP + p * 2) * WS); };
    auto a_lo = [&](int p) { return (__nv_bfloat16*)(smem + (NWP + p * 2 + 1) * WS); };

    auto stageA = [&](const float* __restrict__ src_, int tt, int p) {
        if (tt >= ntiles) return;
        const int rb = tt * 128;
        __nv_bfloat16* dh = a_hi(p);
        __nv_bfloat16* dl = a_lo(p);
        for (int i = tid; i < 128 * 64; i += 512) {
            int e = i >> 6, kp = (i & 63) * 2;
            int r = rb + e;
            float2 v = (r < nrows) ? *reinterpret_cast<const float2*>(&src_[(size_t)r * 128 + kp])
                                   : make_float2(0.f, 0.f);
            uint32_t hi, lo; split_pack2(v.x, v.y, hi, lo);
            *reinterpret_cast<uint32_t*>(&dh[e * 136 + kp]) = hi;
            *reinterpret_cast<uint32_t*>(&dl[e * 136 + kp]) = lo;
        }
    };

    auto run_mma = [&](float acc[8][4], const __nv_bfloat16* ahp, const __nv_bfloat16* alp,
                       const __nv_bfloat16* bhp, const __nv_bfloat16* blp) {
        const uint32_t bAh = smaddr(ahp), bAl = smaddr(alp);
        const uint32_t bBh = smaddr(bhp), bBl = smaddr(blp);
        #pragma unroll
        for (int ko = 0; ko < 128; ko += 16) {
            uint32_t Ah[4], Al[4];
            const int rb2 = (mo * 136 + ko) * 2;
            ldsm4(Ah, bAh + rb2 + oA);
            ldsm4(Al, bAl + rb2 + oA);
            #pragma unroll
            for (int p = 0; p < 4; ++p) {
                const int nb2 = ((no + p*16) * 136 + ko) * 2;
                uint32_t th[4], tl[4];
                ldsm4(th, bBh + nb2 + oB);
                ldsm4(tl, bBl + nb2 + oB);
                uint32_t B0h[2] = {th[0], th[1]}, B1h[2] = {th[2], th[3]};
                uint32_t B0l[2] = {tl[0], tl[1]}, B1l[2] = {tl[2], tl[3]};
                mma_bf16(acc[2*p],   Ah, B0h);
                mma_bf16(acc[2*p],   Ah, B0l);
                mma_bf16(acc[2*p],   Al, B0h);
                mma_bf16(acc[2*p+1], Ah, B1h);
                mma_bf16(acc[2*p+1], Ah, B1l);
                mma_bf16(acc[2*p+1], Al, B1h);
            }
        }
    };

    auto epilogue = [&](float acc[8][4], int rb) {
        #pragma unroll
        for (int nt = 0; nt < 8; ++nt) {
            const int c = no + nt*8 + tq*2;
            const float b0 = bs[c], b1 = bs[c + 1];
            #pragma unroll
            for (int half = 0; half < 2; ++half) {
                int r = rb + mo + g + half*8;
                if (r < nrows) {
                    float v0 = acc[nt][half*2]     + b0;
                    float v1 = acc[nt][half*2 + 1] + b1;
                    if (ACT) { v0 = v0 / (1.f + expf(-v0)); v1 = v1 / (1.f + expf(-v1)); }
                    if (HAS_RES) {
                        float2 rr = *reinterpret_cast<const float2*>(&res[(size_t)r*128 + c]);
                        v0 += rr.x; v1 += rr.y;
                    }
                    *reinterpret_cast<float2*>(&out[(size_t)r*128 + c]) = make_float2(v0, v1);
                }
            }
        }
    };

    if (DB) {
        int t = blockIdx.x, pb = 0;
        stageA(A, t, 0);
        __syncthreads();
        for (; t < ntiles; t += gridDim.x) {
            float acc[8][4];
            #pragma unroll
            for (int b = 0; b < 8; ++b)
                #pragma unroll
                for (int c = 0; c < 4; ++c) acc[b][c] = 0.f;
            run_mma(acc, a_hi(pb), a_lo(pb), wh, wl);
            stageA(A, t + gridDim.x, pb ^ 1);
            epilogue(acc, t * 128);
            pb ^= 1;
            __syncthreads();
        }
    } else {
        __syncthreads();
        for (int t = blockIdx.x; t < ntiles; t += gridDim.x) {
            stageA(A, t, 0);
            __syncthreads();
            float acc[8][4];
            #pragma unroll
            for (int b = 0; b < 8; ++b)
                #pragma unroll
                for (int c = 0; c < 4; ++c) acc[b][c] = 0.f;
            run_mma(acc, a_hi(0), a_lo(0), wh, wl);
            if (HAS_A2) {
                __syncthreads();
                stageA(A2, t, 0);
                __syncthreads();
                run_mma(acc, a_hi(0), a_lo(0), w2h, w2l);
            }
            epilogue(acc, t * 128);
            __syncthreads();
        }
    }
}

// ---------------- zero init ----------------
__global__ void zero_bufs_kernel() {
    int idx = blockIdx.x * blockDim.x + threadIdx.x;
    if (idx < NN*HH) { g_agg1[idx] = 0.f; g_agg2[idx] = 0.f; }
    if (idx < GG*HH) { g_gsum[idx] = 0.f; g_gvar[idx] = 0.f; }
    if (idx < GG)    { g_gcnt[idx] = 0.f; }
}

// ---------------- GraphNorm kernels ----------------
__global__ void gn_accum(const float* __restrict__ h, const int* __restrict__ batch) {
    int idx = blockIdx.x * blockDim.x + threadIdx.x;
    if (idx >= NN*HH) return;
    int n = idx >> 7, c = idx & 127;
    int b = batch[n];
    atomicAdd(&g_gsum[b*128 + c], h[idx]);
    if (c == 0) atomicAdd(&g_gcnt[b], 1.f);
}
__global__ void gn_mean() {
    int idx = blockIdx.x * blockDim.x + threadIdx.x;
    if (idx >= GG*HH) return;
    int g = idx >> 7;
    g_gsum[idx] /= fmaxf(g_gcnt[g], 1.f);
}
__global__ void gn_center(const float* __restrict__ h, const int* __restrict__ batch,
                          const float* __restrict__ ms, float* __restrict__ out) {
    int idx = blockIdx.x * blockDim.x + threadIdx.x;
    if (idx >= NN*HH) return;
    int n = idx >> 7, c = idx & 127;
    int b = batch[n];
    float o = h[idx] - g_gsum[b*128 + c] * ms[c];
    out[idx] = o;
    atomicAdd(&g_gvar[b*128 + c], o*o);
}
__global__ void gn_inv() {
    int idx = blockIdx.x * blockDim.x + threadIdx.x;
    if (idx >= GG*HH) return;
    int g = idx >> 7;
    g_gvar[idx] = rsqrtf(g_gvar[idx] / fmaxf(g_gcnt[g], 1.f) + EPSV);
}
__global__ void gn_apply(const float* __restrict__ cent, const int* __restrict__ batch,
                         const float* __restrict__ nw, const float* __restrict__ nb,
                         float* __restrict__ out) {
    int idx = blockIdx.x * blockDim.x + threadIdx.x;
    if (idx >= NN*HH) return;
    int n = idx >> 7, c = idx & 127;
    int b = batch[n];
    out[idx] = nw[c] * cent[idx] * g_gvar[b*128 + c] + nb[c];
}

// ---------------- host launcher ----------------
static inline void set_smem(const void* f, int bytes) {
    cudaFuncSetAttribute(f, cudaFuncAttributeMaxDynamicSharedMemorySize, bytes);
}

extern "C" void kernel_launch(void* const* d_in, const int* in_sizes, int n_in,
                              void* d_out, int out_size) {
    (void)in_sizes; (void)n_in; (void)out_size;

    const float* x          = (const float*)d_in[0];
    const float* feature1   = (const float*)d_in[1];
    const float* feature2   = (const float*)d_in[2];
    const int*   edge_index = (const int*)  d_in[3];
    const int*   batch      = (const int*)  d_in[4];
    const float* lin_w      = (const float*)d_in[5];
    const float* lin_b      = (const float*)d_in[6];
    const float* f1_w1      = (const float*)d_in[7];
    const float* f1_w2      = (const float*)d_in[8];
    const float* f2_w1      = (const float*)d_in[9];
    const float* f2_w2      = (const float*)d_in[10];
    const float* c1_rel_w   = (const float*)d_in[11];
    const float* c1_rel_b   = (const float*)d_in[12];
    const float* c1_root_w  = (const float*)d_in[13];
    const float* c2_rel_w   = (const float*)d_in[14];
    const float* c2_rel_b   = (const float*)d_in[15];
    const float* c2_root_w  = (const float*)d_in[16];
    const float* lin1_w     = (const float*)d_in[17];
    const float* lin1_b     = (const float*)d_in[18];
    const float* lin2_w     = (const float*)d_in[19];
    const float* lin2_b     = (const float*)d_in[20];
    const float* lincat_w   = (const float*)d_in[21];
    const float* lincat_b   = (const float*)d_in[22];
    const float* norm_w     = (const float*)d_in[23];
    const float* norm_b     = (const float*)d_in[24];
    const float* norm_ms    = (const float*)d_in[25];
    const float* lins_w     = (const float*)d_in[26];
    const float* lins_b     = (const float*)d_in[27];
    const float* final_w    = (const float*)d_in[28];
    const float* final_b    = (const float*)d_in[29];
    float* out = (float*)d_out;

    const int* src = edge_index;
    const int* dst = edge_index + EE;

    float *xh, *agg1, *agg2, *tmp, *h1, *h2, *hA, *hB;
    cudaGetSymbolAddress((void**)&xh,   g_xh);
    cudaGetSymbolAddress((void**)&agg1, g_agg1);
    cudaGetSymbolAddress((void**)&agg2, g_agg2);
    cudaGetSymbolAddress((void**)&tmp,  g_tmp);
    cudaGetSymbolAddress((void**)&h1,   g_h1);
    cudaGetSymbolAddress((void**)&h2,   g_h2);
    cudaGetSymbolAddress((void**)&hA,   g_hA);
    cudaGetSymbolAddress((void**)&hB,   g_hB);

    constexpr int WS = 128 * 136 * 2;
    const int N1 = 6 * WS + 512;   // DB: w(2) + a(4) + bias
    const int N2 = 6 * WS + 512;   // A2: w(4) + a(2) + bias

    set_smem((const void*)node_hmma<false,true ,false,true >, N1);
    set_smem((const void*)node_hmma<false,true ,true ,true >, N1);
    set_smem((const void*)node_hmma<false,false,false,true >, N1);
    set_smem((const void*)node_hmma<true ,false,false,false>, N2);
    set_smem((const void*)node_hmma<true ,false,true ,false>, N2);
    set_smem((const void*)edge_fused<FF1,512,1>, EL<FF1>::TOT);
    set_smem((const void*)edge_fused<FF2,256,2>, EL<FF2>::TOT);

    const int EL_GRID = (NN*HH + 255) / 256;
    const int GH_GRID = (GG*HH + 255) / 256;
    const int NT      = (EE + 127) / 128;   // 7813
    const int NTN     = (NN + 127) / 128;   // 391

    // 0) zero accumulators
    zero_bufs_kernel<<<EL_GRID, 256>>>();

    // 1) xh = swish(x @ lin_w + lin_b)
    node_hmma<false,true,false,true><<<148, 512, N1>>>(
        x, lin_w, nullptr, nullptr, lin_b, nullptr, xh, NN, NTN);

    // 2) fused edge messages (HMMA + ldmatrix, pipelined)
    edge_fused<FF1,512,1><<<148, 512, EL<FF1>::TOT>>>(feature1, f1_w1, f1_w2, xh, src, dst, agg1, NT);
    edge_fused<FF2,256,2><<<296, 256, EL<FF2>::TOT>>>(feature2, f2_w1, f2_w2, xh, src, dst, agg2, NT);

    // 3) conv1
    node_hmma<true,false,false,false><<<148, 512, N2>>>(
        agg1, c1_rel_w, xh, c1_root_w, c1_rel_b, nullptr, tmp, NN, NTN);
    node_hmma<false,true,false,true><<<148, 512, N1>>>(
        tmp, lin1_w, nullptr, nullptr, lin1_b, nullptr, h1, NN, NTN);

    // 4) conv2
    node_hmma<true,false,false,false><<<148, 512, N2>>>(
        agg2, c2_rel_w, xh, c2_root_w, c2_rel_b, nullptr, tmp, NN, NTN);
    node_hmma<false,true,false,true><<<148, 512, N1>>>(
        tmp, lin2_w, nullptr, nullptr, lin2_b, nullptr, h2, NN, NTN);

    // 5) hA = h1@Wtop + h2@Wbot + lincat_b + xh
    node_hmma<true,false,true,false><<<148, 512, N2>>>(
        h1, lincat_w, h2, lincat_w + 128*128, lincat_b, xh, hA, NN, NTN);

    // 6) residual stack: h = swish(h@Wi + bi) + h
    node_hmma<false,true,true,true><<<148, 512, N1>>>(
        hA, lins_w + 0*16384, nullptr, nullptr, lins_b + 0*128, hA, hB, NN, NTN);
    node_hmma<false,true,true,true><<<148, 512, N1>>>(
        hB, lins_w + 1*16384, nullptr, nullptr, lins_b + 1*128, hB, hA, NN, NTN);
    node_hmma<false,true,true,true><<<148, 512, N1>>>(
        hA, lins_w + 2*16384, nullptr, nullptr, lins_b + 2*128, hA, hB, NN, NTN);

    // 7) GraphNorm on hB
    gn_accum <<<EL_GRID, 256>>>(hB, batch);
    gn_mean  <<<GH_GRID, 256>>>();
    gn_center<<<EL_GRID, 256>>>(hB, batch, norm_ms, h1);
    gn_inv   <<<GH_GRID, 256>>>();
    gn_apply <<<EL_GRID, 256>>>(h1, batch, norm_w, norm_b, hA);

    // 8) out = hA @ final_w + final_b
    node_hmma<false,false,false,true><<<148, 512, N1>>>(
        hA, final_w, nullptr, nullptr, final_b, nullptr, out, NN, NTN);
}

// round 12
// speedup vs baseline: 3.6952x; 1.2782x over previous
#include <cuda_runtime.h>
#include <cuda_bf16.h>
#include <math.h>
#include <stdint.h>

// ---------------- problem constants ----------------
#define NN    50000
#define HH    128
#define EE    1000000
#define FF1   147
#define FF2   21
#define GG    512
#define EPSV  1e-5f

// ---------------- device scratch (no allocs allowed) ----------------
__device__ float g_xh  [NN*HH];
__device__ float g_agg1[NN*HH];
__device__ float g_agg2[NN*HH];
__device__ float g_tmp [NN*HH];
__device__ float g_h1  [NN*HH];
__device__ float g_h2  [NN*HH];
__device__ float g_hA  [NN*HH];
__device__ float g_hB  [NN*HH];
__device__ float g_gsum[GG*HH];
__device__ float g_gvar[GG*HH];
__device__ float g_gcnt[GG];

// ================= warp-MMA helpers (baseline PTX, sm_80+) =================
__device__ __forceinline__ void mma_bf16(float d[4], const uint32_t a[4], const uint32_t b[2]) {
    asm volatile(
        "mma.sync.aligned.m16n8k16.row.col.f32.bf16.bf16.f32 "
        "{%0,%1,%2,%3}, {%4,%5,%6,%7}, {%8,%9}, {%0,%1,%2,%3};"
        : "+f"(d[0]), "+f"(d[1]), "+f"(d[2]), "+f"(d[3])
        : "r"(a[0]), "r"(a[1]), "r"(a[2]), "r"(a[3]), "r"(b[0]), "r"(b[1]));
}

__device__ __forceinline__ void ldsm4(uint32_t r[4], uint32_t addr) {
    asm volatile("ldmatrix.sync.aligned.m8n8.x4.shared.b16 {%0,%1,%2,%3}, [%4];"
        : "=r"(r[0]), "=r"(r[1]), "=r"(r[2]), "=r"(r[3]) : "r"(addr));
}

__device__ __forceinline__ uint32_t smaddr(const void* p) {
    return (uint32_t)__cvta_generic_to_shared(p);
}

// element-wise vector atomic add (sm_90+ baseline PTX)
__device__ __forceinline__ void red_add_v4(float* p, float4 v) {
    asm volatile("red.global.add.v4.f32 [%0], {%1,%2,%3,%4};"
        :: "l"(p), "f"(v.x), "f"(v.y), "f"(v.z), "f"(v.w) : "memory");
}

__device__ __forceinline__ void split_bf16(float f, __nv_bfloat16& h, __nv_bfloat16& l) {
    h = __float2bfloat16_rn(f);
    l = __float2bfloat16_rn(f - __bfloat162float(h));
}

__device__ __forceinline__ void split_pack2(float f0, float f1, uint32_t& hi, uint32_t& lo) {
    __nv_bfloat16 h0, l0, h1, l1;
    split_bf16(f0, h0, l0);
    split_bf16(f1, h1, l1);
    hi = (uint32_t)__bfloat16_as_ushort(h0) | ((uint32_t)__bfloat16_as_ushort(h1) << 16);
    lo = (uint32_t)__bfloat16_as_ushort(l0) | ((uint32_t)__bfloat16_as_ushort(l1) << 16);
}

// ldmatrix per-lane byte offsets relative to (row0, k0)
#define OFF_A(lane, stride) ((((lane) & 15) * (stride) + (((lane) >> 4) << 3)) * 2)
#define OFF_B(lane, stride) (((((lane) & 7) + (((lane) >> 4) << 3)) * (stride) + ((((lane) >> 3) & 1) << 3)) * 2)

// ---------------- edge kernel smem layout ----------------
template<int F> struct EL {
    static constexpr int KP  = (F + 15) & ~15;
    static constexpr int SA  = KP + 8;                 // bf16 elems/row (A, W1T)
    static constexpr int W1H = 0;
    static constexpr int W1L = W1H + 64 * SA * 2;
    static constexpr int W2H = W1L + 64 * SA * 2;
    static constexpr int W2L = W2H + 128 * 72 * 2;
    static constexpr int MIH = W2L + 128 * 72 * 2;     // mid hi; o-halves alias here
    static constexpr int MIL = MIH + 128 * 72 * 2;
    static constexpr int A1H = MIL + 128 * 72 * 2;
    static constexpr int A1L = A1H + 128 * SA * 2;
    static constexpr int IDX = A1L + 128 * SA * 2;     // 2 x 256 ints
    static constexpr int TOT = IDX + 2048;
};

// ================= fused edge kernel (pipelined, ldmatrix, fast paths) ========
// NTHR=256: 8 warps (4 m-warps x 32 rows); NTHR=512: 16 warps (8 m-warps x 16 rows)
template<int F, int NTHR, int MINB>
__global__ void __launch_bounds__(NTHR, MINB) edge_fused(
    const float* __restrict__ feat, const float* __restrict__ w1,
    const float* __restrict__ w2,   const float* __restrict__ xh,
    const int* __restrict__ src,    const int* __restrict__ dst,
    float* __restrict__ agg, int ntiles)
{
    using L = EL<F>;
    constexpr int MW = NTHR / 64;      // # m-warps
    constexpr int RM = 128 / MW;       // rows per m-warp
    constexpr int MT = RM / 16;        // 16-row tiles per warp
    constexpr int ES = NTHR / 32;      // epilogue edge stride
    constexpr int CH = 64 / ES;        // epilogue iterations per thread
    constexpr int BB = (NTHR == 256) ? 2 : 4;   // epilogue load batch

    extern __shared__ char smem[];
    __nv_bfloat16* w1h = (__nv_bfloat16*)(smem + L::W1H);
    __nv_bfloat16* w1l = (__nv_bfloat16*)(smem + L::W1L);
    __nv_bfloat16* w2h = (__nv_bfloat16*)(smem + L::W2H);
    __nv_bfloat16* w2l = (__nv_bfloat16*)(smem + L::W2L);
    __nv_bfloat16* mih = (__nv_bfloat16*)(smem + L::MIH);
    __nv_bfloat16* mil = (__nv_bfloat16*)(smem + L::MIL);
    __nv_bfloat16* a1h = (__nv_bfloat16*)(smem + L::A1H);
    __nv_bfloat16* a1l = (__nv_bfloat16*)(smem + L::A1L);
    float*         ob  = (float*)        (smem + L::MIH);   // 64 x 132 f32 (aliases MI)
    int*           sidx= (int*)          (smem + L::IDX);

    const int tid  = threadIdx.x;
    const int wid  = tid >> 5, lane = tid & 31;
    const int g    = lane >> 2, tq = lane & 3;
    const int wm   = wid & (MW - 1), wn = wid / MW;

    const uint32_t bA1h = smaddr(a1h), bA1l = smaddr(a1l);
    const uint32_t bW1h = smaddr(w1h), bW1l = smaddr(w1l);
    const uint32_t bW2h = smaddr(w2h), bW2l = smaddr(w2l);
    const uint32_t bMih = smaddr(mih), bMil = smaddr(mil);
    const int oA_SA = OFF_A(lane, L::SA), oB_SA = OFF_B(lane, L::SA);
    const int oA_72 = OFF_A(lane, 72),    oB_72 = OFF_B(lane, 72);

    // zero once: weight pads + A pads must stay 0
    for (int i = tid; i < L::TOT / 4; i += NTHR)
        reinterpret_cast<uint32_t*>(smem)[i] = 0;
    __syncthreads();

    // stage weights transposed + split. w1 gmem [F][64], w2 gmem [64][128]
    for (int i = tid; i < F * 64; i += NTHR) {
        int k = i >> 6, n = i & 63;
        __nv_bfloat16 h, l; split_bf16(w1[i], h, l);
        w1h[n * L::SA + k] = h;  w1l[n * L::SA + k] = l;
    }
    for (int i = tid; i < 32 * 128; i += NTHR) {        // paired k/k+1 -> STS.32
        int n = i & 127, k = (i >> 7) * 2;
        __nv_bfloat16 h0, l0, h1, l1;
        split_bf16(w2[k * 128 + n], h0, l0);
        split_bf16(w2[(k + 1) * 128 + n], h1, l1);
        *reinterpret_cast<uint32_t*>(&w2h[n * 72 + k]) =
            (uint32_t)__bfloat16_as_ushort(h0) | ((uint32_t)__bfloat16_as_ushort(h1) << 16);
        *reinterpret_cast<uint32_t*>(&w2l[n * 72 + k]) =
            (uint32_t)__bfloat16_as_ushort(l0) | ((uint32_t)__bfloat16_as_ushort(l1) << 16);
    }

    auto stage = [&](int tt, int parity) {
        if (tt >= ntiles) return;
        const int se0 = tt * 128;
        const int scnt = min(128, EE - se0);
        const float* fb = feat + (size_t)se0 * F;
        int* sx = sidx + parity * 256;
        if (scnt == 128) {
            // fast path: constant trip count, unrolled -> high MLP
            constexpr int NIT = (128 * F + NTHR - 1) / NTHR;
            #pragma unroll
            for (int j = 0; j < NIT; ++j) {
                int i = tid + j * NTHR;
                if (128 * F % NTHR == 0 || i < 128 * F) {
                    int e = i / F, k = i - e * F;
                    __nv_bfloat16 h, l; split_bf16(fb[i], h, l);
                    a1h[e * L::SA + k] = h;  a1l[e * L::SA + k] = l;
                }
            }
            if (tid < 128) { sx[tid] = src[se0 + tid]; sx[128 + tid] = dst[se0 + tid]; }
        } else {
            for (int i = tid; i < scnt * F; i += NTHR) {
                int e = i / F, k = i - e * F;
                __nv_bfloat16 h, l; split_bf16(fb[i], h, l);
                a1h[e * L::SA + k] = h;  a1l[e * L::SA + k] = l;
            }
            if (tid < scnt) { sx[tid] = src[se0 + tid]; sx[128 + tid] = dst[se0 + tid]; }
        }
    };

    int t = blockIdx.x, pb = 0;
    stage(t, 0);
    __syncthreads();

    for (; t < ntiles; t += gridDim.x) {
        const int cnt = min(128, EE - t * 128);
        const int* sx = sidx + pb * 256;

        // ---- GEMM1: [128, KP] x [KP, 64] -> mid ----
        {
            const int mo = wm * RM, no = wn * 32;
            float acc[MT][4][4];
            #pragma unroll
            for (int a = 0; a < MT; ++a)
                #pragma unroll
                for (int b = 0; b < 4; ++b)
                    #pragma unroll
                    for (int c = 0; c < 4; ++c) acc[a][b][c] = 0.f;

            #pragma unroll
            for (int ko = 0; ko < L::KP; ko += 16) {
                uint32_t Ah[MT][4], Al[MT][4];
                #pragma unroll
                for (int mt = 0; mt < MT; ++mt) {
                    const int rb2 = ((mo + mt*16) * L::SA + ko) * 2;
                    ldsm4(Ah[mt], bA1h + rb2 + oA_SA);
                    ldsm4(Al[mt], bA1l + rb2 + oA_SA);
                }
                uint32_t Bh[4][2], Bl[4][2];
                #pragma unroll
                for (int p = 0; p < 2; ++p) {
                    const int nb2 = ((no + p*16) * L::SA + ko) * 2;
                    uint32_t tr[4];
                    ldsm4(tr, bW1h + nb2 + oB_SA);
                    Bh[2*p][0]=tr[0]; Bh[2*p][1]=tr[1]; Bh[2*p+1][0]=tr[2]; Bh[2*p+1][1]=tr[3];
                    ldsm4(tr, bW1l + nb2 + oB_SA);
                    Bl[2*p][0]=tr[0]; Bl[2*p][1]=tr[1]; Bl[2*p+1][0]=tr[2]; Bl[2*p+1][1]=tr[3];
                }
                #pragma unroll
                for (int nt = 0; nt < 4; ++nt)
                    #pragma unroll
                    for (int mt = 0; mt < MT; ++mt) {
                        mma_bf16(acc[mt][nt], Ah[mt], Bh[nt]);
                        mma_bf16(acc[mt][nt], Ah[mt], Bl[nt]);
                        mma_bf16(acc[mt][nt], Al[mt], Bh[nt]);
                    }
            }
            #pragma unroll
            for (int mt = 0; mt < MT; ++mt)
                #pragma unroll
                for (int nt = 0; nt < 4; ++nt) {
                    int r0 = mo + mt*16 + g, col = no + nt*8 + tq*2;
                    uint32_t hi, lo;
                    split_pack2(acc[mt][nt][0], acc[mt][nt][1], hi, lo);
                    *reinterpret_cast<uint32_t*>(&mih[r0*72 + col]) = hi;
                    *reinterpret_cast<uint32_t*>(&mil[r0*72 + col]) = lo;
                    split_pack2(acc[mt][nt][2], acc[mt][nt][3], hi, lo);
                    *reinterpret_cast<uint32_t*>(&mih[(r0+8)*72 + col]) = hi;
                    *reinterpret_cast<uint32_t*>(&mil[(r0+8)*72 + col]) = lo;
                }
        }
        __syncthreads();   // mid visible; A now dead (stageable)

        // ---- GEMM2 (K=64) ----
        float acc[MT][8][4];
        {
            const int mo = wm * RM, no = wn * 64;
            #pragma unroll
            for (int a = 0; a < MT; ++a)
                #pragma unroll
                for (int b = 0; b < 8; ++b)
                    #pragma unroll
                    for (int c = 0; c < 4; ++c) acc[a][b][c] = 0.f;

            #pragma unroll
            for (int ko = 0; ko < 64; ko += 16) {
                uint32_t Ah[MT][4], Al[MT][4];
                #pragma unroll
                for (int mt = 0; mt < MT; ++mt) {
                    const int rb2 = ((mo + mt*16) * 72 + ko) * 2;
                    ldsm4(Ah[mt], bMih + rb2 + oA_72);
                    ldsm4(Al[mt], bMil + rb2 + oA_72);
                }
                uint32_t Bh[8][2], Bl[8][2];
                #pragma unroll
                for (int p = 0; p < 4; ++p) {
                    const int nb2 = ((no + p*16) * 72 + ko) * 2;
                    uint32_t tr[4];
                    ldsm4(tr, bW2h + nb2 + oB_72);
                    Bh[2*p][0]=tr[0]; Bh[2*p][1]=tr[1]; Bh[2*p+1][0]=tr[2]; Bh[2*p+1][1]=tr[3];
                    ldsm4(tr, bW2l + nb2 + oB_72);
                    Bl[2*p][0]=tr[0]; Bl[2*p][1]=tr[1]; Bl[2*p+1][0]=tr[2]; Bl[2*p+1][1]=tr[3];
                }
                #pragma unroll
                for (int nt = 0; nt < 8; ++nt)
                    #pragma unroll
                    for (int mt = 0; mt < MT; ++mt) {
                        mma_bf16(acc[mt][nt], Ah[mt], Bh[nt]);
                        mma_bf16(acc[mt][nt], Ah[mt], Bl[nt]);
                        mma_bf16(acc[mt][nt], Al[mt], Bh[nt]);
                    }
            }
        }
        __syncthreads();   // MI reads done -> ob region writable

        // ---- per half: store o rows into ob, then batched/unrolled epilogue ----
        #pragma unroll
        for (int half = 0; half < 2; ++half) {
            if (((wm * RM) >> 6) == half) {
                const int mo = wm * RM, no = wn * 64;
                #pragma unroll
                for (int mt = 0; mt < MT; ++mt)
                    #pragma unroll
                    for (int nt = 0; nt < 8; ++nt) {
                        int rl = mo + mt*16 + g - half*64, col = no + nt*8 + tq*2;
                        *reinterpret_cast<float2*>(&ob[rl*132 + col]) =
                            make_float2(acc[mt][nt][0], acc[mt][nt][1]);
                        *reinterpret_cast<float2*>(&ob[(rl+8)*132 + col]) =
                            make_float2(acc[mt][nt][2], acc[mt][nt][3]);
                    }
            }
            __syncthreads();
            {
                const int c4 = (tid & 31) << 2, eh = tid >> 5;
                const int lim = min(cnt - half*64, 64);
                if (lim == 64) {
                    // fast path: constant trips, batched loads -> MLP
                    #pragma unroll
                    for (int jb = 0; jb < CH; jb += BB) {
                        float4 ov[BB], xv[BB]; int dd[BB];
                        #pragma unroll
                        for (int j = 0; j < BB; ++j) {
                            int e = eh + (jb + j) * ES;
                            int eg = half*64 + e;
                            int s = sx[eg]; dd[j] = sx[128 + eg];
                            ov[j] = *reinterpret_cast<const float4*>(&ob[e*132 + c4]);
                            xv[j] = *reinterpret_cast<const float4*>(&xh[(size_t)s*128 + c4]);
                        }
                        #pragma unroll
                        for (int j = 0; j < BB; ++j)
                            red_add_v4(&agg[(size_t)dd[j]*128 + c4],
                                make_float4(ov[j].x*xv[j].x, ov[j].y*xv[j].y,
                                            ov[j].z*xv[j].z, ov[j].w*xv[j].w));
                    }
                } else {
                    for (int e = eh; e < lim; e += ES) {
                        int eg = half*64 + e;
                        int s = sx[eg], d = sx[128 + eg];
                        float4 ov = *reinterpret_cast<const float4*>(&ob[e*132 + c4]);
                        float4 xv = *reinterpret_cast<const float4*>(&xh[(size_t)s*128 + c4]);
                        red_add_v4(&agg[(size_t)d*128 + c4],
                            make_float4(ov.x*xv.x, ov.y*xv.y, ov.z*xv.z, ov.w*xv.w));
                    }
                }
            }
            if (half == 0) stage(t + gridDim.x, pb ^ 1);
            __syncthreads();
        }
        pb ^= 1;
    }
}

// ================= node GEMM on HMMA (ldmatrix, vectorized staging) =================
template<bool HAS_A2, bool ACT, bool HAS_RES, bool DB>
__global__ void __launch_bounds__(512) node_hmma(
    const float* __restrict__ A,  const float* __restrict__ W,
    const float* __restrict__ A2, const float* __restrict__ W2,
    const float* __restrict__ bias, const float* __restrict__ res,
    float* __restrict__ out, int nrows, int ntiles)
{
    static_assert(!(HAS_A2 && DB), "DB only for single-A variant");
    constexpr int WS = 128 * 136 * 2;
    constexpr int NWP = HAS_A2 ? 4 : 2;
    constexpr int NAP = DB ? 4 : 2;
    extern __shared__ char smem[];
    __nv_bfloat16* wh  = (__nv_bfloat16*)(smem);
    __nv_bfloat16* wl  = (__nv_bfloat16*)(smem + WS);
    __nv_bfloat16* w2h = (__nv_bfloat16*)(smem + 2 * WS);
    __nv_bfloat16* w2l = (__nv_bfloat16*)(smem + 3 * WS);
    float*         bs  = (float*)        (smem + (NWP + NAP) * WS);

    const int tid = threadIdx.x;
    const int wid = tid >> 5, lane = tid & 31;
    const int g = lane >> 2, tq = lane & 3;
    const int wm = wid & 7, wn = wid >> 3;
    const int mo = wm * 16, no = wn * 64;
    const int oA = OFF_A(lane, 136), oB = OFF_B(lane, 136);

    // stage weights (transposed, split), paired k/k+1 -> STS.32
    for (int i = tid; i < 64 * 128; i += 512) {
        int n = i & 127, k = (i >> 7) * 2;
        __nv_bfloat16 h0, l0, h1, l1;
        split_bf16(W[k * 128 + n], h0, l0);
        split_bf16(W[(k + 1) * 128 + n], h1, l1);
        *reinterpret_cast<uint32_t*>(&wh[n * 136 + k]) =
            (uint32_t)__bfloat16_as_ushort(h0) | ((uint32_t)__bfloat16_as_ushort(h1) << 16);
        *reinterpret_cast<uint32_t*>(&wl[n * 136 + k]) =
            (uint32_t)__bfloat16_as_ushort(l0) | ((uint32_t)__bfloat16_as_ushort(l1) << 16);
        if (HAS_A2) {
            split_bf16(W2[k * 128 + n], h0, l0);
            split_bf16(W2[(k + 1) * 128 + n], h1, l1);
            *reinterpret_cast<uint32_t*>(&w2h[n * 136 + k]) =
                (uint32_t)__bfloat16_as_ushort(h0) | ((uint32_t)__bfloat16_as_ushort(h1) << 16);
            *reinterpret_cast<uint32_t*>(&w2l[n * 136 + k]) =
                (uint32_t)__bfloat16_as_ushort(l0) | ((uint32_t)__bfloat16_as_ushort(l1) << 16);
        }
    }
    if (tid < 128) bs[tid] = bias[tid];

    auto a_hi = [&](int p) { return (__nv_bfloat16*)(smem + (NWP + p * 2) * WS); };
    auto a_lo = [&](int p) { return (__nv_bfloat16*)(smem + (NWP + p * 2 + 1) * WS); };

    auto stageA = [&](const float* __restrict__ src_, int tt, int p) {
        if (tt >= ntiles) return;
        const int rb = tt * 128;
        __nv_bfloat16* dh = a_hi(p);
        __nv_bfloat16* dl = a_lo(p);
        #pragma unroll 8
        for (int i = tid; i < 128 * 64; i += 512) {
            int e = i >> 6, kp = (i & 63) * 2;
            int r = rb + e;
            float2 v = (r < nrows) ? *reinterpret_cast<const float2*>(&src_[(size_t)r * 128 + kp])
                                   : make_float2(0.f, 0.f);
            uint32_t hi, lo; split_pack2(v.x, v.y, hi, lo);
            *reinterpret_cast<uint32_t*>(&dh[e * 136 + kp]) = hi;
            *reinterpret_cast<uint32_t*>(&dl[e * 136 + kp]) = lo;
        }
    };

    auto run_mma = [&](float acc[8][4], const __nv_bfloat16* ahp, const __nv_bfloat16* alp,
                       const __nv_bfloat16* bhp, const __nv_bfloat16* blp) {
        const uint32_t bAh = smaddr(ahp), bAl = smaddr(alp);
        const uint32_t bBh = smaddr(bhp), bBl = smaddr(blp);
        #pragma unroll
        for (int ko = 0; ko < 128; ko += 16) {
            uint32_t Ah[4], Al[4];
            const int rb2 = (mo * 136 + ko) * 2;
            ldsm4(Ah, bAh + rb2 + oA);
            ldsm4(Al, bAl + rb2 + oA);
            #pragma unroll
            for (int p = 0; p < 4; ++p) {
                const int nb2 = ((no + p*16) * 136 + ko) * 2;
                uint32_t th[4], tl[4];
                ldsm4(th, bBh + nb2 + oB);
                ldsm4(tl, bBl + nb2 + oB);
                uint32_t B0h[2] = {th[0], th[1]}, B1h[2] = {th[2], th[3]};
                uint32_t B0l[2] = {tl[0], tl[1]}, B1l[2] = {tl[2], tl[3]};
                mma_bf16(acc[2*p],   Ah, B0h);
                mma_bf16(acc[2*p],   Ah, B0l);
                mma_bf16(acc[2*p],   Al, B0h);
                mma_bf16(acc[2*p+1], Ah, B1h);
                mma_bf16(acc[2*p+1], Ah, B1l);
                mma_bf16(acc[2*p+1], Al, B1h);
            }
        }
    };

    auto epilogue = [&](float acc[8][4], int rb) {
        #pragma unroll
        for (int nt = 0; nt < 8; ++nt) {
            const int c = no + nt*8 + tq*2;
            const float b0 = bs[c], b1 = bs[c + 1];
            #pragma unroll
            for (int half = 0; half < 2; ++half) {
                int r = rb + mo + g + half*8;
                if (r < nrows) {
                    float v0 = acc[nt][half*2]     + b0;
                    float v1 = acc[nt][half*2 + 1] + b1;
                    if (ACT) { v0 = v0 / (1.f + expf(-v0)); v1 = v1 / (1.f + expf(-v1)); }
                    if (HAS_RES) {
                        float2 rr = *reinterpret_cast<const float2*>(&res[(size_t)r*128 + c]);
                        v0 += rr.x; v1 += rr.y;
                    }
                    *reinterpret_cast<float2*>(&out[(size_t)r*128 + c]) = make_float2(v0, v1);
                }
            }
        }
    };

    if (DB) {
        int t = blockIdx.x, pb = 0;
        stageA(A, t, 0);
        __syncthreads();
        for (; t < ntiles; t += gridDim.x) {
            float acc[8][4];
            #pragma unroll
            for (int b = 0; b < 8; ++b)
                #pragma unroll
                for (int c = 0; c < 4; ++c) acc[b][c] = 0.f;
            run_mma(acc, a_hi(pb), a_lo(pb), wh, wl);
            stageA(A, t + gridDim.x, pb ^ 1);
            epilogue(acc, t * 128);
            pb ^= 1;
            __syncthreads();
        }
    } else {
        __syncthreads();
        for (int t = blockIdx.x; t < ntiles; t += gridDim.x) {
            stageA(A, t, 0);
            __syncthreads();
            float acc[8][4];
            #pragma unroll
            for (int b = 0; b < 8; ++b)
                #pragma unroll
                for (int c = 0; c < 4; ++c) acc[b][c] = 0.f;
            run_mma(acc, a_hi(0), a_lo(0), wh, wl);
            if (HAS_A2) {
                __syncthreads();
                stageA(A2, t, 0);
                __syncthreads();
                run_mma(acc, a_hi(0), a_lo(0), w2h, w2l);
            }
            epilogue(acc, t * 128);
            __syncthreads();
        }
    }
}

// ---------------- zero init ----------------
__global__ void zero_bufs_kernel() {
    int idx = blockIdx.x * blockDim.x + threadIdx.x;
    if (idx < NN*HH) { g_agg1[idx] = 0.f; g_agg2[idx] = 0.f; }
    if (idx < GG*HH) { g_gsum[idx] = 0.f; g_gvar[idx] = 0.f; }
    if (idx < GG)    { g_gcnt[idx] = 0.f; }
}

// ---------------- GraphNorm kernels ----------------
__global__ void gn_accum(const float* __restrict__ h, const int* __restrict__ batch) {
    int idx = blockIdx.x * blockDim.x + threadIdx.x;
    if (idx >= NN*HH) return;
    int n = idx >> 7, c = idx & 127;
    int b = batch[n];
    atomicAdd(&g_gsum[b*128 + c], h[idx]);
    if (c == 0) atomicAdd(&g_gcnt[b], 1.f);
}
__global__ void gn_mean() {
    int idx = blockIdx.x * blockDim.x + threadIdx.x;
    if (idx >= GG*HH) return;
    int g = idx >> 7;
    g_gsum[idx] /= fmaxf(g_gcnt[g], 1.f);
}
__global__ void gn_center(const float* __restrict__ h, const int* __restrict__ batch,
                          const float* __restrict__ ms, float* __restrict__ out) {
    int idx = blockIdx.x * blockDim.x + threadIdx.x;
    if (idx >= NN*HH) return;
    int n = idx >> 7, c = idx & 127;
    int b = batch[n];
    float o = h[idx] - g_gsum[b*128 + c] * ms[c];
    out[idx] = o;
    atomicAdd(&g_gvar[b*128 + c], o*o);
}
__global__ void gn_inv() {
    int idx = blockIdx.x * blockDim.x + threadIdx.x;
    if (idx >= GG*HH) return;
    int g = idx >> 7;
    g_gvar[idx] = rsqrtf(g_gvar[idx] / fmaxf(g_gcnt[g], 1.f) + EPSV);
}
__global__ void gn_apply(const float* __restrict__ cent, const int* __restrict__ batch,
                         const float* __restrict__ nw, const float* __restrict__ nb,
                         float* __restrict__ out) {
    int idx = blockIdx.x * blockDim.x + threadIdx.x;
    if (idx >= NN*HH) return;
    int n = idx >> 7, c = idx & 127;
    int b = batch[n];
    out[idx] = nw[c] * cent[idx] * g_gvar[b*128 + c] + nb[c];
}

// ---------------- host launcher ----------------
static inline void set_smem(const void* f, int bytes) {
    cudaFuncSetAttribute(f, cudaFuncAttributeMaxDynamicSharedMemorySize, bytes);
}

extern "C" void kernel_launch(void* const* d_in, const int* in_sizes, int n_in,
                              void* d_out, int out_size) {
    (void)in_sizes; (void)n_in; (void)out_size;

    const float* x          = (const float*)d_in[0];
    const float* feature1   = (const float*)d_in[1];
    const float* feature2   = (const float*)d_in[2];
    const int*   edge_index = (const int*)  d_in[3];
    const int*   batch      = (const int*)  d_in[4];
    const float* lin_w      = (const float*)d_in[5];
    const float* lin_b      = (const float*)d_in[6];
    const float* f1_w1      = (const float*)d_in[7];
    const float* f1_w2      = (const float*)d_in[8];
    const float* f2_w1      = (const float*)d_in[9];
    const float* f2_w2      = (const float*)d_in[10];
    const float* c1_rel_w   = (const float*)d_in[11];
    const float* c1_rel_b   = (const float*)d_in[12];
    const float* c1_root_w  = (const float*)d_in[13];
    const float* c2_rel_w   = (const float*)d_in[14];
    const float* c2_rel_b   = (const float*)d_in[15];
    const float* c2_root_w  = (const float*)d_in[16];
    const float* lin1_w     = (const float*)d_in[17];
    const float* lin1_b     = (const float*)d_in[18];
    const float* lin2_w     = (const float*)d_in[19];
    const float* lin2_b     = (const float*)d_in[20];
    const float* lincat_w   = (const float*)d_in[21];
    const float* lincat_b   = (const float*)d_in[22];
    const float* norm_w     = (const float*)d_in[23];
    const float* norm_b     = (const float*)d_in[24];
    const float* norm_ms    = (const float*)d_in[25];
    const float* lins_w     = (const float*)d_in[26];
    const float* lins_b     = (const float*)d_in[27];
    const float* final_w    = (const float*)d_in[28];
    const float* final_b    = (const float*)d_in[29];
    float* out = (float*)d_out;

    const int* src = edge_index;
    const int* dst = edge_index + EE;

    float *xh, *agg1, *agg2, *tmp, *h1, *h2, *hA, *hB;
    cudaGetSymbolAddress((void**)&xh,   g_xh);
    cudaGetSymbolAddress((void**)&agg1, g_agg1);
    cudaGetSymbolAddress((void**)&agg2, g_agg2);
    cudaGetSymbolAddress((void**)&tmp,  g_tmp);
    cudaGetSymbolAddress((void**)&h1,   g_h1);
    cudaGetSymbolAddress((void**)&h2,   g_h2);
    cudaGetSymbolAddress((void**)&hA,   g_hA);
    cudaGetSymbolAddress((void**)&hB,   g_hB);

    constexpr int WS = 128 * 136 * 2;
    const int N1 = 6 * WS + 512;   // DB: w(2) + a(4) + bias
    const int N2 = 6 * WS + 512;   // A2: w(4) + a(2) + bias

    set_smem((const void*)node_hmma<false,true ,false,true >, N1);
    set_smem((const void*)node_hmma<false,true ,true ,true >, N1);
    set_smem((const void*)node_hmma<false,false,false,true >, N1);
    set_smem((const void*)node_hmma<true ,false,false,false>, N2);
    set_smem((const void*)node_hmma<true ,false,true ,false>, N2);
    set_smem((const void*)edge_fused<FF1,512,1>, EL<FF1>::TOT);
    set_smem((const void*)edge_fused<FF2,256,2>, EL<FF2>::TOT);

    const int EL_GRID = (NN*HH + 255) / 256;
    const int GH_GRID = (GG*HH + 255) / 256;
    const int NT      = (EE + 127) / 128;   // 7813
    const int NTN     = (NN + 127) / 128;   // 391

    // 0) zero accumulators
    zero_bufs_kernel<<<EL_GRID, 256>>>();

    // 1) xh = swish(x @ lin_w + lin_b)
    node_hmma<false,true,false,true><<<148, 512, N1>>>(
        x, lin_w, nullptr, nullptr, lin_b, nullptr, xh, NN, NTN);

    // 2) fused edge messages (HMMA + ldmatrix, pipelined, fast paths)
    edge_fused<FF1,512,1><<<148, 512, EL<FF1>::TOT>>>(feature1, f1_w1, f1_w2, xh, src, dst, agg1, NT);
    edge_fused<FF2,256,2><<<296, 256, EL<FF2>::TOT>>>(feature2, f2_w1, f2_w2, xh, src, dst, agg2, NT);

    // 3) conv1
    node_hmma<true,false,false,false><<<148, 512, N2>>>(
        agg1, c1_rel_w, xh, c1_root_w, c1_rel_b, nullptr, tmp, NN, NTN);
    node_hmma<false,true,false,true><<<148, 512, N1>>>(
        tmp, lin1_w, nullptr, nullptr, lin1_b, nullptr, h1, NN, NTN);

    // 4) conv2
    node_hmma<true,false,false,false><<<148, 512, N2>>>(
        agg2, c2_rel_w, xh, c2_root_w, c2_rel_b, nullptr, tmp, NN, NTN);
    node_hmma<false,true,false,true><<<148, 512, N1>>>(
        tmp, lin2_w, nullptr, nullptr, lin2_b, nullptr, h2, NN, NTN);

    // 5) hA = h1@Wtop + h2@Wbot + lincat_b + xh
    node_hmma<true,false,true,false><<<148, 512, N2>>>(
        h1, lincat_w, h2, lincat_w + 128*128, lincat_b, xh, hA, NN, NTN);

    // 6) residual stack: h = swish(h@Wi + bi) + h
    node_hmma<false,true,true,true><<<148, 512, N1>>>(
        hA, lins_w + 0*16384, nullptr, nullptr, lins_b + 0*128, hA, hB, NN, NTN);
    node_hmma<false,true,true,true><<<148, 512, N1>>>(
        hB, lins_w + 1*16384, nullptr, nullptr, lins_b + 1*128, hB, hA, NN, NTN);
    node_hmma<false,true,true,true><<<148, 512, N1>>>(
        hA, lins_w + 2*16384, nullptr, nullptr, lins_b + 2*128, hA, hB, NN, NTN);

    // 7) GraphNorm on hB
    gn_accum <<<EL_GRID, 256>>>(hB, batch);
    gn_mean  <<<GH_GRID, 256>>>();
    gn_center<<<EL_GRID, 256>>>(hB, batch, norm_ms, h1);
    gn_inv   <<<GH_GRID, 256>>>();
    gn_apply <<<EL_GRID, 256>>>(h1, batch, norm_w, norm_b, hA);

    // 8) out = hA @ final_w + final_b
    node_hmma<false,false,false,true><<<148, 512, N1>>>(
        hA, final_w, nullptr, nullptr, final_b, nullptr, out, NN, NTN);
}

// round 13
// speedup vs baseline: 3.7300x; 1.0094x over previous
#include <cuda_runtime.h>
#include <cuda_bf16.h>
#include <math.h>
#include <stdint.h>

// ---------------- problem constants ----------------
#define NN    50000
#define HH    128
#define EE    1000000
#define FF1   147
#define FF2   21
#define GG    512
#define EPSV  1e-5f

// ---------------- device scratch (no allocs allowed) ----------------
__device__ float g_xh  [NN*HH];
__device__ float g_agg1[NN*HH];
__device__ float g_agg2[NN*HH];
__device__ float g_tmp [NN*HH];
__device__ float g_h1  [NN*HH];
__device__ float g_h2  [NN*HH];
__device__ float g_hA  [NN*HH];
__device__ float g_hB  [NN*HH];
__device__ float g_gsum[GG*HH];
__device__ float g_gvar[GG*HH];
__device__ float g_gcnt[GG];

// ================= warp-MMA helpers (baseline PTX, sm_80+) =================
__device__ __forceinline__ void mma_bf16(float d[4], const uint32_t a[4], const uint32_t b[2]) {
    asm volatile(
        "mma.sync.aligned.m16n8k16.row.col.f32.bf16.bf16.f32 "
        "{%0,%1,%2,%3}, {%4,%5,%6,%7}, {%8,%9}, {%0,%1,%2,%3};"
        : "+f"(d[0]), "+f"(d[1]), "+f"(d[2]), "+f"(d[3])
        : "r"(a[0]), "r"(a[1]), "r"(a[2]), "r"(a[3]), "r"(b[0]), "r"(b[1]));
}

__device__ __forceinline__ void ldsm4(uint32_t r[4], uint32_t addr) {
    asm volatile("ldmatrix.sync.aligned.m8n8.x4.shared.b16 {%0,%1,%2,%3}, [%4];"
        : "=r"(r[0]), "=r"(r[1]), "=r"(r[2]), "=r"(r[3]) : "r"(addr));
}

__device__ __forceinline__ uint32_t smaddr(const void* p) {
    return (uint32_t)__cvta_generic_to_shared(p);
}

__device__ __forceinline__ void red_add_v2(float* p, float2 v) {
    asm volatile("red.global.add.v2.f32 [%0], {%1,%2};"
        :: "l"(p), "f"(v.x), "f"(v.y) : "memory");
}

__device__ __forceinline__ void split_bf16(float f, __nv_bfloat16& h, __nv_bfloat16& l) {
    h = __float2bfloat16_rn(f);
    l = __float2bfloat16_rn(f - __bfloat162float(h));
}

__device__ __forceinline__ void split_pack2(float f0, float f1, uint32_t& hi, uint32_t& lo) {
    __nv_bfloat16 h0, l0, h1, l1;
    split_bf16(f0, h0, l0);
    split_bf16(f1, h1, l1);
    hi = (uint32_t)__bfloat16_as_ushort(h0) | ((uint32_t)__bfloat16_as_ushort(h1) << 16);
    lo = (uint32_t)__bfloat16_as_ushort(l0) | ((uint32_t)__bfloat16_as_ushort(l1) << 16);
}

// ldmatrix per-lane byte offsets relative to (row0, k0)
#define OFF_A(lane, stride) ((((lane) & 15) * (stride) + (((lane) >> 4) << 3)) * 2)
#define OFF_B(lane, stride) (((((lane) & 7) + (((lane) >> 4) << 3)) * (stride) + ((((lane) >> 3) & 1) << 3)) * 2)

// ---------------- edge kernel smem layout ----------------
template<int F> struct EL {
    static constexpr int KP  = (F + 15) & ~15;
    static constexpr int SA  = KP + 8;
    static constexpr int W1H = 0;
    static constexpr int W1L = W1H + 64 * SA * 2;
    static constexpr int W2H = W1L + 64 * SA * 2;
    static constexpr int W2L = W2H + 128 * 72 * 2;
    static constexpr int MIH = W2L + 128 * 72 * 2;
    static constexpr int MIL = MIH + 128 * 72 * 2;
    static constexpr int A1H = MIL + 128 * 72 * 2;
    static constexpr int A1L = A1H + 128 * SA * 2;
    static constexpr int IDX = A1L + 128 * SA * 2;     // 2 x 256 ints
    static constexpr int TOT = IDX + 2048;
};

// ================= fused edge kernel (direct register epilogue, 2 syncs/tile) ======
template<int F, int NTHR, int MINB>
__global__ void __launch_bounds__(NTHR, MINB) edge_fused(
    const float* __restrict__ feat, const float* __restrict__ w1,
    const float* __restrict__ w2,   const float* __restrict__ xh,
    const int* __restrict__ src,    const int* __restrict__ dst,
    float* __restrict__ agg, int ntiles)
{
    using L = EL<F>;
    constexpr int MW = NTHR / 64;
    constexpr int RM = 128 / MW;
    constexpr int MT = RM / 16;

    extern __shared__ char smem[];
    __nv_bfloat16* w1h = (__nv_bfloat16*)(smem + L::W1H);
    __nv_bfloat16* w1l = (__nv_bfloat16*)(smem + L::W1L);
    __nv_bfloat16* w2h = (__nv_bfloat16*)(smem + L::W2H);
    __nv_bfloat16* w2l = (__nv_bfloat16*)(smem + L::W2L);
    __nv_bfloat16* mih = (__nv_bfloat16*)(smem + L::MIH);
    __nv_bfloat16* mil = (__nv_bfloat16*)(smem + L::MIL);
    __nv_bfloat16* a1h = (__nv_bfloat16*)(smem + L::A1H);
    __nv_bfloat16* a1l = (__nv_bfloat16*)(smem + L::A1L);
    int*           sidx= (int*)          (smem + L::IDX);

    const int tid  = threadIdx.x;
    const int wid  = tid >> 5, lane = tid & 31;
    const int g    = lane >> 2, tq = lane & 3;
    const int wm   = wid & (MW - 1), wn = wid / MW;

    const uint32_t bA1h = smaddr(a1h), bA1l = smaddr(a1l);
    const uint32_t bW1h = smaddr(w1h), bW1l = smaddr(w1l);
    const uint32_t bW2h = smaddr(w2h), bW2l = smaddr(w2l);
    const uint32_t bMih = smaddr(mih), bMil = smaddr(mil);
    const int oA_SA = OFF_A(lane, L::SA), oB_SA = OFF_B(lane, L::SA);
    const int oA_72 = OFF_A(lane, 72),    oB_72 = OFF_B(lane, 72);

    for (int i = tid; i < L::TOT / 4; i += NTHR)
        reinterpret_cast<uint32_t*>(smem)[i] = 0;
    __syncthreads();

    for (int i = tid; i < F * 64; i += NTHR) {
        int k = i >> 6, n = i & 63;
        __nv_bfloat16 h, l; split_bf16(w1[i], h, l);
        w1h[n * L::SA + k] = h;  w1l[n * L::SA + k] = l;
    }
    for (int i = tid; i < 32 * 128; i += NTHR) {
        int n = i & 127, k = (i >> 7) * 2;
        __nv_bfloat16 h0, l0, h1, l1;
        split_bf16(w2[k * 128 + n], h0, l0);
        split_bf16(w2[(k + 1) * 128 + n], h1, l1);
        *reinterpret_cast<uint32_t*>(&w2h[n * 72 + k]) =
            (uint32_t)__bfloat16_as_ushort(h0) | ((uint32_t)__bfloat16_as_ushort(h1) << 16);
        *reinterpret_cast<uint32_t*>(&w2l[n * 72 + k]) =
            (uint32_t)__bfloat16_as_ushort(l0) | ((uint32_t)__bfloat16_as_ushort(l1) << 16);
    }

    auto stage = [&](int tt, int parity) {
        if (tt >= ntiles) return;
        const int se0 = tt * 128;
        const int scnt = min(128, EE - se0);
        const float* fb = feat + (size_t)se0 * F;
        int* sx = sidx + parity * 256;
        if (scnt == 128) {
            constexpr int NIT = (128 * F + NTHR - 1) / NTHR;
            #pragma unroll
            for (int j = 0; j < NIT; ++j) {
                int i = tid + j * NTHR;
                if (128 * F % NTHR == 0 || i < 128 * F) {
                    int e = i / F, k = i - e * F;
                    __nv_bfloat16 h, l; split_bf16(fb[i], h, l);
                    a1h[e * L::SA + k] = h;  a1l[e * L::SA + k] = l;
                }
            }
            if (tid < 128) { sx[tid] = src[se0 + tid]; sx[128 + tid] = dst[se0 + tid]; }
        } else {
            for (int i = tid; i < scnt * F; i += NTHR) {
                int e = i / F, k = i - e * F;
                __nv_bfloat16 h, l; split_bf16(fb[i], h, l);
                a1h[e * L::SA + k] = h;  a1l[e * L::SA + k] = l;
            }
            if (tid < scnt) { sx[tid] = src[se0 + tid]; sx[128 + tid] = dst[se0 + tid]; }
        }
    };

    int t = blockIdx.x, pb = 0;
    stage(t, 0);
    __syncthreads();

    for (; t < ntiles; t += gridDim.x) {
        const int cnt = min(128, EE - t * 128);
        const int* sx = sidx + pb * 256;

        // ---- GEMM1: [128, KP] x [KP, 64] -> mid ----
        {
            const int mo = wm * RM, no = wn * 32;
            float acc[MT][4][4];
            #pragma unroll
            for (int a = 0; a < MT; ++a)
                #pragma unroll
                for (int b = 0; b < 4; ++b)
                    #pragma unroll
                    for (int c = 0; c < 4; ++c) acc[a][b][c] = 0.f;

            #pragma unroll
            for (int ko = 0; ko < L::KP; ko += 16) {
                uint32_t Ah[MT][4], Al[MT][4];
                #pragma unroll
                for (int mt = 0; mt < MT; ++mt) {
                    const int rb2 = ((mo + mt*16) * L::SA + ko) * 2;
                    ldsm4(Ah[mt], bA1h + rb2 + oA_SA);
                    ldsm4(Al[mt], bA1l + rb2 + oA_SA);
                }
                uint32_t Bh[4][2], Bl[4][2];
                #pragma unroll
                for (int p = 0; p < 2; ++p) {
                    const int nb2 = ((no + p*16) * L::SA + ko) * 2;
                    uint32_t tr[4];
                    ldsm4(tr, bW1h + nb2 + oB_SA);
                    Bh[2*p][0]=tr[0]; Bh[2*p][1]=tr[1]; Bh[2*p+1][0]=tr[2]; Bh[2*p+1][1]=tr[3];
                    ldsm4(tr, bW1l + nb2 + oB_SA);
                    Bl[2*p][0]=tr[0]; Bl[2*p][1]=tr[1]; Bl[2*p+1][0]=tr[2]; Bl[2*p+1][1]=tr[3];
                }
                #pragma unroll
                for (int nt = 0; nt < 4; ++nt)
                    #pragma unroll
                    for (int mt = 0; mt < MT; ++mt) {
                        mma_bf16(acc[mt][nt], Ah[mt], Bh[nt]);
                        mma_bf16(acc[mt][nt], Ah[mt], Bl[nt]);
                        mma_bf16(acc[mt][nt], Al[mt], Bh[nt]);
                    }
            }
            #pragma unroll
            for (int mt = 0; mt < MT; ++mt)
                #pragma unroll
                for (int nt = 0; nt < 4; ++nt) {
                    int r0 = mo + mt*16 + g, col = no + nt*8 + tq*2;
                    uint32_t hi, lo;
                    split_pack2(acc[mt][nt][0], acc[mt][nt][1], hi, lo);
                    *reinterpret_cast<uint32_t*>(&mih[r0*72 + col]) = hi;
                    *reinterpret_cast<uint32_t*>(&mil[r0*72 + col]) = lo;
                    split_pack2(acc[mt][nt][2], acc[mt][nt][3], hi, lo);
                    *reinterpret_cast<uint32_t*>(&mih[(r0+8)*72 + col]) = hi;
                    *reinterpret_cast<uint32_t*>(&mil[(r0+8)*72 + col]) = lo;
                }
        }
        __syncthreads();   // MI visible; A reads done (stage may rewrite A below)

        // ---- GEMM2 (K=64), acc stays in registers ----
        float acc[MT][8][4];
        {
            const int mo = wm * RM, no = wn * 64;
            #pragma unroll
            for (int a = 0; a < MT; ++a)
                #pragma unroll
                for (int b = 0; b < 8; ++b)
                    #pragma unroll
                    for (int c = 0; c < 4; ++c) acc[a][b][c] = 0.f;

            #pragma unroll
            for (int ko = 0; ko < 64; ko += 16) {
                uint32_t Ah[MT][4], Al[MT][4];
                #pragma unroll
                for (int mt = 0; mt < MT; ++mt) {
                    const int rb2 = ((mo + mt*16) * 72 + ko) * 2;
                    ldsm4(Ah[mt], bMih + rb2 + oA_72);
                    ldsm4(Al[mt], bMil + rb2 + oA_72);
                }
                uint32_t Bh[8][2], Bl[8][2];
                #pragma unroll
                for (int p = 0; p < 4; ++p) {
                    const int nb2 = ((no + p*16) * 72 + ko) * 2;
                    uint32_t tr[4];
                    ldsm4(tr, bW2h + nb2 + oB_72);
                    Bh[2*p][0]=tr[0]; Bh[2*p][1]=tr[1]; Bh[2*p+1][0]=tr[2]; Bh[2*p+1][1]=tr[3];
                    ldsm4(tr, bW2l + nb2 + oB_72);
                    Bl[2*p][0]=tr[0]; Bl[2*p][1]=tr[1]; Bl[2*p+1][0]=tr[2]; Bl[2*p+1][1]=tr[3];
                }
                #pragma unroll
                for (int nt = 0; nt < 8; ++nt)
                    #pragma unroll
                    for (int mt = 0; mt < MT; ++mt) {
                        mma_bf16(acc[mt][nt], Ah[mt], Bh[nt]);
                        mma_bf16(acc[mt][nt], Ah[mt], Bl[nt]);
                        mma_bf16(acc[mt][nt], Al[mt], Bh[nt]);
                    }
            }
        }

        // ---- direct register epilogue: agg[dst[e],c] += o[e,c]*xh[src[e],c] ----
        {
            const int no = wn * 64, cb = no + tq * 2;
            #pragma unroll
            for (int mt = 0; mt < MT; ++mt) {
                #pragma unroll
                for (int hf = 0; hf < 2; ++hf) {
                    int e = wm * RM + mt*16 + g + hf*8;
                    if (e < cnt) {
                        int s = sx[e], d = sx[128 + e];
                        const float* xrow = xh + (size_t)s * 128 + cb;
                        float* arow = agg + (size_t)d * 128 + cb;
                        float2 xv[8];
                        #pragma unroll
                        for (int nt = 0; nt < 8; ++nt)
                            xv[nt] = *reinterpret_cast<const float2*>(xrow + nt*8);
                        #pragma unroll
                        for (int nt = 0; nt < 8; ++nt)
                            red_add_v2(arow + nt*8,
                                make_float2(acc[mt][nt][hf*2] * xv[nt].x,
                                            acc[mt][nt][hf*2+1] * xv[nt].y));
                    }
                }
            }
        }

        // ---- stage next tile (overlaps epilogue latency across warps) ----
        stage(t + gridDim.x, pb ^ 1);
        __syncthreads();
        pb ^= 1;
    }
}

// ================= node GEMM on HMMA (ldmatrix; optional fused GraphNorm-apply) ====
template<bool HAS_A2, bool ACT, bool HAS_RES, bool DB, bool GN>
__global__ void __launch_bounds__(512) node_hmma(
    const float* __restrict__ A,  const float* __restrict__ W,
    const float* __restrict__ A2, const float* __restrict__ W2,
    const float* __restrict__ bias, const float* __restrict__ res,
    const int* __restrict__ batchv, const float* __restrict__ istd,
    const float* __restrict__ gnw,  const float* __restrict__ gnb,
    float* __restrict__ out, int nrows, int ntiles)
{
    static_assert(!(HAS_A2 && DB), "DB only for single-A variant");
    constexpr int WS = 128 * 136 * 2;
    constexpr int NWP = HAS_A2 ? 4 : 2;
    constexpr int NAP = DB ? 4 : 2;
    extern __shared__ char smem[];
    __nv_bfloat16* wh  = (__nv_bfloat16*)(smem);
    __nv_bfloat16* wl  = (__nv_bfloat16*)(smem + WS);
    __nv_bfloat16* w2h = (__nv_bfloat16*)(smem + 2 * WS);
    __nv_bfloat16* w2l = (__nv_bfloat16*)(smem + 3 * WS);
    float*         bs  = (float*)        (smem + (NWP + NAP) * WS);

    const int tid = threadIdx.x;
    const int wid = tid >> 5, lane = tid & 31;
    const int g = lane >> 2, tq = lane & 3;
    const int wm = wid & 7, wn = wid >> 3;
    const int mo = wm * 16, no = wn * 64;
    const int oA = OFF_A(lane, 136), oB = OFF_B(lane, 136);

    for (int i = tid; i < 64 * 128; i += 512) {
        int n = i & 127, k = (i >> 7) * 2;
        __nv_bfloat16 h0, l0, h1, l1;
        split_bf16(W[k * 128 + n], h0, l0);
        split_bf16(W[(k + 1) * 128 + n], h1, l1);
        *reinterpret_cast<uint32_t*>(&wh[n * 136 + k]) =
            (uint32_t)__bfloat16_as_ushort(h0) | ((uint32_t)__bfloat16_as_ushort(h1) << 16);
        *reinterpret_cast<uint32_t*>(&wl[n * 136 + k]) =
            (uint32_t)__bfloat16_as_ushort(l0) | ((uint32_t)__bfloat16_as_ushort(l1) << 16);
        if (HAS_A2) {
            split_bf16(W2[k * 128 + n], h0, l0);
            split_bf16(W2[(k + 1) * 128 + n], h1, l1);
            *reinterpret_cast<uint32_t*>(&w2h[n * 136 + k]) =
                (uint32_t)__bfloat16_as_ushort(h0) | ((uint32_t)__bfloat16_as_ushort(h1) << 16);
            *reinterpret_cast<uint32_t*>(&w2l[n * 136 + k]) =
                (uint32_t)__bfloat16_as_ushort(l0) | ((uint32_t)__bfloat16_as_ushort(l1) << 16);
        }
    }
    if (tid < 128) bs[tid] = bias[tid];

    auto a_hi = [&](int p) { return (__nv_bfloat16*)(smem + (NWP + p * 2) * WS); };
    auto a_lo = [&](int p) { return (__nv_bfloat16*)(smem + (NWP + p * 2 + 1) * WS); };

    auto stageA = [&](const float* __restrict__ src_, int tt, int p) {
        if (tt >= ntiles) return;
        const int rb = tt * 128;
        __nv_bfloat16* dh = a_hi(p);
        __nv_bfloat16* dl = a_lo(p);
        #pragma unroll 8
        for (int i = tid; i < 128 * 64; i += 512) {
            int e = i >> 6, kp = (i & 63) * 2;
            int r = rb + e;
            float2 v = (r < nrows) ? *reinterpret_cast<const float2*>(&src_[(size_t)r * 128 + kp])
                                   : make_float2(0.f, 0.f);
            if (GN) {
                if (r < nrows) {
                    int b = batchv[r];
                    float2 iv = *reinterpret_cast<const float2*>(&istd[b * 128 + kp]);
                    float2 wv = *reinterpret_cast<const float2*>(&gnw[kp]);
                    float2 bv = *reinterpret_cast<const float2*>(&gnb[kp]);
                    v.x = wv.x * v.x * iv.x + bv.x;
                    v.y = wv.y * v.y * iv.y + bv.y;
                }
            }
            uint32_t hi, lo; split_pack2(v.x, v.y, hi, lo);
            *reinterpret_cast<uint32_t*>(&dh[e * 136 + kp]) = hi;
            *reinterpret_cast<uint32_t*>(&dl[e * 136 + kp]) = lo;
        }
    };

    auto run_mma = [&](float acc[8][4], const __nv_bfloat16* ahp, const __nv_bfloat16* alp,
                       const __nv_bfloat16* bhp, const __nv_bfloat16* blp) {
        const uint32_t bAh = smaddr(ahp), bAl = smaddr(alp);
        const uint32_t bBh = smaddr(bhp), bBl = smaddr(blp);
        #pragma unroll
        for (int ko = 0; ko < 128; ko += 16) {
            uint32_t Ah[4], Al[4];
            const int rb2 = (mo * 136 + ko) * 2;
            ldsm4(Ah, bAh + rb2 + oA);
            ldsm4(Al, bAl + rb2 + oA);
            #pragma unroll
            for (int p = 0; p < 4; ++p) {
                const int nb2 = ((no + p*16) * 136 + ko) * 2;
                uint32_t th[4], tl[4];
                ldsm4(th, bBh + nb2 + oB);
                ldsm4(tl, bBl + nb2 + oB);
                uint32_t B0h[2] = {th[0], th[1]}, B1h[2] = {th[2], th[3]};
                uint32_t B0l[2] = {tl[0], tl[1]}, B1l[2] = {tl[2], tl[3]};
                mma_bf16(acc[2*p],   Ah, B0h);
                mma_bf16(acc[2*p],   Ah, B0l);
                mma_bf16(acc[2*p],   Al, B0h);
                mma_bf16(acc[2*p+1], Ah, B1h);
                mma_bf16(acc[2*p+1], Ah, B1l);
                mma_bf16(acc[2*p+1], Al, B1h);
            }
        }
    };

    auto epilogue = [&](float acc[8][4], int rb) {
        #pragma unroll
        for (int nt = 0; nt < 8; ++nt) {
            const int c = no + nt*8 + tq*2;
            const float b0 = bs[c], b1 = bs[c + 1];
            #pragma unroll
            for (int half = 0; half < 2; ++half) {
                int r = rb + mo + g + half*8;
                if (r < nrows) {
                    float v0 = acc[nt][half*2]     + b0;
                    float v1 = acc[nt][half*2 + 1] + b1;
                    if (ACT) { v0 = v0 / (1.f + expf(-v0)); v1 = v1 / (1.f + expf(-v1)); }
                    if (HAS_RES) {
                        float2 rr = *reinterpret_cast<const float2*>(&res[(size_t)r*128 + c]);
                        v0 += rr.x; v1 += rr.y;
                    }
                    *reinterpret_cast<float2*>(&out[(size_t)r*128 + c]) = make_float2(v0, v1);
                }
            }
        }
    };

    if (DB) {
        int t = blockIdx.x, pb = 0;
        stageA(A, t, 0);
        __syncthreads();
        for (; t < ntiles; t += gridDim.x) {
            float acc[8][4];
            #pragma unroll
            for (int b = 0; b < 8; ++b)
                #pragma unroll
                for (int c = 0; c < 4; ++c) acc[b][c] = 0.f;
            run_mma(acc, a_hi(pb), a_lo(pb), wh, wl);
            stageA(A, t + gridDim.x, pb ^ 1);
            epilogue(acc, t * 128);
            pb ^= 1;
            __syncthreads();
        }
    } else {
        __syncthreads();
        for (int t = blockIdx.x; t < ntiles; t += gridDim.x) {
            stageA(A, t, 0);
            __syncthreads();
            float acc[8][4];
            #pragma unroll
            for (int b = 0; b < 8; ++b)
                #pragma unroll
                for (int c = 0; c < 4; ++c) acc[b][c] = 0.f;
            run_mma(acc, a_hi(0), a_lo(0), wh, wl);
            if (HAS_A2) {
                __syncthreads();
                stageA(A2, t, 0);
                __syncthreads();
                run_mma(acc, a_hi(0), a_lo(0), w2h, w2l);
            }
            epilogue(acc, t * 128);
            __syncthreads();
        }
    }
}

// ---------------- zero init ----------------
__global__ void zero_bufs_kernel() {
    int idx = blockIdx.x * blockDim.x + threadIdx.x;
    if (idx < NN*HH) { g_agg1[idx] = 0.f; g_agg2[idx] = 0.f; }
    if (idx < GG*HH) { g_gsum[idx] = 0.f; g_gvar[idx] = 0.f; }
    if (idx < GG)    { g_gcnt[idx] = 0.f; }
}

// ---------------- GraphNorm kernels (mean fused into center) ----------------
__global__ void gn_accum(const float* __restrict__ h, const int* __restrict__ batch) {
    int idx = blockIdx.x * blockDim.x + threadIdx.x;
    if (idx >= NN*HH) return;
    int n = idx >> 7, c = idx & 127;
    int b = batch[n];
    atomicAdd(&g_gsum[b*128 + c], h[idx]);
    if (c == 0) atomicAdd(&g_gcnt[b], 1.f);
}
__global__ void gn_center(const float* __restrict__ h, const int* __restrict__ batch,
                          const float* __restrict__ ms, float* __restrict__ out) {
    int idx = blockIdx.x * blockDim.x + threadIdx.x;
    if (idx >= NN*HH) return;
    int n = idx >> 7, c = idx & 127;
    int b = batch[n];
    float mean = g_gsum[b*128 + c] / fmaxf(g_gcnt[b], 1.f);
    float o = h[idx] - mean * ms[c];
    out[idx] = o;
    atomicAdd(&g_gvar[b*128 + c], o*o);
}
__global__ void gn_inv() {
    int idx = blockIdx.x * blockDim.x + threadIdx.x;
    if (idx >= GG*HH) return;
    int g = idx >> 7;
    g_gvar[idx] = rsqrtf(g_gvar[idx] / fmaxf(g_gcnt[g], 1.f) + EPSV);
}

// ---------------- host launcher ----------------
static inline void set_smem(const void* f, int bytes) {
    cudaFuncSetAttribute(f, cudaFuncAttributeMaxDynamicSharedMemorySize, bytes);
}

extern "C" void kernel_launch(void* const* d_in, const int* in_sizes, int n_in,
                              void* d_out, int out_size) {
    (void)in_sizes; (void)n_in; (void)out_size;

    const float* x          = (const float*)d_in[0];
    const float* feature1   = (const float*)d_in[1];
    const float* feature2   = (const float*)d_in[2];
    const int*   edge_index = (const int*)  d_in[3];
    const int*   batch      = (const int*)  d_in[4];
    const float* lin_w      = (const float*)d_in[5];
    const float* lin_b      = (const float*)d_in[6];
    const float* f1_w1      = (const float*)d_in[7];
    const float* f1_w2      = (const float*)d_in[8];
    const float* f2_w1      = (const float*)d_in[9];
    const float* f2_w2      = (const float*)d_in[10];
    const float* c1_rel_w   = (const float*)d_in[11];
    const float* c1_rel_b   = (const float*)d_in[12];
    const float* c1_root_w  = (const float*)d_in[13];
    const float* c2_rel_w   = (const float*)d_in[14];
    const float* c2_rel_b   = (const float*)d_in[15];
    const float* c2_root_w  = (const float*)d_in[16];
    const float* lin1_w     = (const float*)d_in[17];
    const float* lin1_b     = (const float*)d_in[18];
    const float* lin2_w     = (const float*)d_in[19];
    const float* lin2_b     = (const float*)d_in[20];
    const float* lincat_w   = (const float*)d_in[21];
    const float* lincat_b   = (const float*)d_in[22];
    const float* norm_w     = (const float*)d_in[23];
    const float* norm_b     = (const float*)d_in[24];
    const float* norm_ms    = (const float*)d_in[25];
    const float* lins_w     = (const float*)d_in[26];
    const float* lins_b     = (const float*)d_in[27];
    const float* final_w    = (const float*)d_in[28];
    const float* final_b    = (const float*)d_in[29];
    float* out = (float*)d_out;

    const int* src = edge_index;
    const int* dst = edge_index + EE;

    float *xh, *agg1, *agg2, *tmp, *h1, *h2, *hA, *hB, *gvar;
    cudaGetSymbolAddress((void**)&xh,   g_xh);
    cudaGetSymbolAddress((void**)&agg1, g_agg1);
    cudaGetSymbolAddress((void**)&agg2, g_agg2);
    cudaGetSymbolAddress((void**)&tmp,  g_tmp);
    cudaGetSymbolAddress((void**)&h1,   g_h1);
    cudaGetSymbolAddress((void**)&h2,   g_h2);
    cudaGetSymbolAddress((void**)&hA,   g_hA);
    cudaGetSymbolAddress((void**)&hB,   g_hB);
    cudaGetSymbolAddress((void**)&gvar, g_gvar);

    constexpr int WS = 128 * 136 * 2;
    const int N1 = 6 * WS + 512;
    const int N2 = 6 * WS + 512;

    set_smem((const void*)node_hmma<false,true ,false,true ,false>, N1);
    set_smem((const void*)node_hmma<false,true ,true ,true ,false>, N1);
    set_smem((const void*)node_hmma<false,false,false,true ,true >, N1);
    set_smem((const void*)node_hmma<true ,false,false,false,false>, N2);
    set_smem((const void*)node_hmma<true ,false,true ,false,false>, N2);
    set_smem((const void*)edge_fused<FF1,512,1>, EL<FF1>::TOT);
    set_smem((const void*)edge_fused<FF2,256,2>, EL<FF2>::TOT);

    const int EL_GRID = (NN*HH + 255) / 256;
    const int GH_GRID = (GG*HH + 255) / 256;
    const int NT      = (EE + 127) / 128;
    const int NTN     = (NN + 127) / 128;

    // 0) zero accumulators
    zero_bufs_kernel<<<EL_GRID, 256>>>();

    // 1) xh = swish(x @ lin_w + lin_b)
    node_hmma<false,true,false,true,false><<<148, 512, N1>>>(
        x, lin_w, nullptr, nullptr, lin_b, nullptr,
        nullptr, nullptr, nullptr, nullptr, xh, NN, NTN);

    // 2) fused edge messages (direct register epilogue)
    edge_fused<FF1,512,1><<<148, 512, EL<FF1>::TOT>>>(feature1, f1_w1, f1_w2, xh, src, dst, agg1, NT);
    edge_fused<FF2,256,2><<<296, 256, EL<FF2>::TOT>>>(feature2, f2_w1, f2_w2, xh, src, dst, agg2, NT);

    // 3) conv1
    node_hmma<true,false,false,false,false><<<148, 512, N2>>>(
        agg1, c1_rel_w, xh, c1_root_w, c1_rel_b, nullptr,
        nullptr, nullptr, nullptr, nullptr, tmp, NN, NTN);
    node_hmma<false,true,false,true,false><<<148, 512, N1>>>(
        tmp, lin1_w, nullptr, nullptr, lin1_b, nullptr,
        nullptr, nullptr, nullptr, nullptr, h1, NN, NTN);

    // 4) conv2
    node_hmma<true,false,false,false,false><<<148, 512, N2>>>(
        agg2, c2_rel_w, xh, c2_root_w, c2_rel_b, nullptr,
        nullptr, nullptr, nullptr, nullptr, tmp, NN, NTN);
    node_hmma<false,true,false,true,false><<<148, 512, N1>>>(
        tmp, lin2_w, nullptr, nullptr, lin2_b, nullptr,
        nullptr, nullptr, nullptr, nullptr, h2, NN, NTN);

    // 5) hA = h1@Wtop + h2@Wbot + lincat_b + xh
    node_hmma<true,false,true,false,false><<<148, 512, N2>>>(
        h1, lincat_w, h2, lincat_w + 128*128, lincat_b, xh,
        nullptr, nullptr, nullptr, nullptr, hA, NN, NTN);

    // 6) residual stack: h = swish(h@Wi + bi) + h
    node_hmma<false,true,true,true,false><<<148, 512, N1>>>(
        hA, lins_w + 0*16384, nullptr, nullptr, lins_b + 0*128, hA,
        nullptr, nullptr, nullptr, nullptr, hB, NN, NTN);
    node_hmma<false,true,true,true,false><<<148, 512, N1>>>(
        hB, lins_w + 1*16384, nullptr, nullptr, lins_b + 1*128, hB,
        nullptr, nullptr, nullptr, nullptr, hA, NN, NTN);
    node_hmma<false,true,true,true,false><<<148, 512, N1>>>(
        hA, lins_w + 2*16384, nullptr, nullptr, lins_b + 2*128, hA,
        nullptr, nullptr, nullptr, nullptr, hB, NN, NTN);

    // 7) GraphNorm on hB (mean fused in center; apply fused into final GEMM)
    gn_accum <<<EL_GRID, 256>>>(hB, batch);
    gn_center<<<EL_GRID, 256>>>(hB, batch, norm_ms, h1);   // h1 := centered
    gn_inv   <<<GH_GRID, 256>>>();

    // 8) out = (nw*cent*inv_std + nb) @ final_w + final_b   (GN fused in staging)
    node_hmma<false,false,false,true,true><<<148, 512, N1>>>(
        h1, final_w, nullptr, nullptr, final_b, nullptr,
        batch, gvar, norm_w, norm_b, out, NN, NTN);
}

// round 14
// speedup vs baseline: 3.7910x; 1.0163x over previous
#include <cuda_runtime.h>
#include <cuda_bf16.h>
#include <math.h>
#include <stdint.h>

// ---------------- problem constants ----------------
#define NN    50000
#define HH    128
#define EE    1000000
#define FF1   147
#define FF2   21
#define GG    512
#define EPSV  1e-5f

// ---------------- device scratch (no allocs allowed) ----------------
__device__ float g_xh  [NN*HH];
__device__ float g_agg1[NN*HH];
__device__ float g_agg2[NN*HH];
__device__ float g_tmp [NN*HH];
__device__ float g_h1  [NN*HH];
__device__ float g_h2  [NN*HH];
__device__ float g_hA  [NN*HH];
__device__ float g_hB  [NN*HH];
__device__ float g_gsum[GG*HH];   // later: O plane
__device__ float g_gvar[GG*HH];   // later: S plane
__device__ float g_gcnt[GG];

// ================= warp-MMA helpers (baseline PTX, sm_80+) =================
__device__ __forceinline__ void mma_bf16(float d[4], const uint32_t a[4], const uint32_t b[2]) {
    asm volatile(
        "mma.sync.aligned.m16n8k16.row.col.f32.bf16.bf16.f32 "
        "{%0,%1,%2,%3}, {%4,%5,%6,%7}, {%8,%9}, {%0,%1,%2,%3};"
        : "+f"(d[0]), "+f"(d[1]), "+f"(d[2]), "+f"(d[3])
        : "r"(a[0]), "r"(a[1]), "r"(a[2]), "r"(a[3]), "r"(b[0]), "r"(b[1]));
}

__device__ __forceinline__ void ldsm4(uint32_t r[4], uint32_t addr) {
    asm volatile("ldmatrix.sync.aligned.m8n8.x4.shared.b16 {%0,%1,%2,%3}, [%4];"
        : "=r"(r[0]), "=r"(r[1]), "=r"(r[2]), "=r"(r[3]) : "r"(addr));
}

__device__ __forceinline__ uint32_t smaddr(const void* p) {
    return (uint32_t)__cvta_generic_to_shared(p);
}

__device__ __forceinline__ void red_add_v2(float* p, float2 v) {
    asm volatile("red.global.add.v2.f32 [%0], {%1,%2};"
        :: "l"(p), "f"(v.x), "f"(v.y) : "memory");
}

__device__ __forceinline__ void split_bf16(float f, __nv_bfloat16& h, __nv_bfloat16& l) {
    h = __float2bfloat16_rn(f);
    l = __float2bfloat16_rn(f - __bfloat162float(h));
}

__device__ __forceinline__ void split_pack2(float f0, float f1, uint32_t& hi, uint32_t& lo) {
    __nv_bfloat16 h0, l0, h1, l1;
    split_bf16(f0, h0, l0);
    split_bf16(f1, h1, l1);
    hi = (uint32_t)__bfloat16_as_ushort(h0) | ((uint32_t)__bfloat16_as_ushort(h1) << 16);
    lo = (uint32_t)__bfloat16_as_ushort(l0) | ((uint32_t)__bfloat16_as_ushort(l1) << 16);
}

#define OFF_A(lane, stride) ((((lane) & 15) * (stride) + (((lane) >> 4) << 3)) * 2)
#define OFF_B(lane, stride) (((((lane) & 7) + (((lane) >> 4) << 3)) * (stride) + ((((lane) >> 3) & 1) << 3)) * 2)

// ---------------- edge kernel smem layout ----------------
template<int F> struct EL {
    static constexpr int KP  = (F + 15) & ~15;
    static constexpr int SA  = KP + 8;
    static constexpr int W1H = 0;
    static constexpr int W1L = W1H + 64 * SA * 2;
    static constexpr int W2H = W1L + 64 * SA * 2;
    static constexpr int W2L = W2H + 128 * 72 * 2;
    static constexpr int MIH = W2L + 128 * 72 * 2;
    static constexpr int MIL = MIH + 128 * 72 * 2;
    static constexpr int A1H = MIL + 128 * 72 * 2;
    static constexpr int A1L = A1H + 128 * SA * 2;
    static constexpr int IDX = A1L + 128 * SA * 2;
    static constexpr int TOT = IDX + 2048;
};

// ================= fused edge kernel (unchanged from R13) =================
template<int F, int NTHR, int MINB>
__global__ void __launch_bounds__(NTHR, MINB) edge_fused(
    const float* __restrict__ feat, const float* __restrict__ w1,
    const float* __restrict__ w2,   const float* __restrict__ xh,
    const int* __restrict__ src,    const int* __restrict__ dst,
    float* __restrict__ agg, int ntiles)
{
    using L = EL<F>;
    constexpr int MW = NTHR / 64;
    constexpr int RM = 128 / MW;
    constexpr int MT = RM / 16;

    extern __shared__ char smem[];
    __nv_bfloat16* w1h = (__nv_bfloat16*)(smem + L::W1H);
    __nv_bfloat16* w1l = (__nv_bfloat16*)(smem + L::W1L);
    __nv_bfloat16* w2h = (__nv_bfloat16*)(smem + L::W2H);
    __nv_bfloat16* w2l = (__nv_bfloat16*)(smem + L::W2L);
    __nv_bfloat16* mih = (__nv_bfloat16*)(smem + L::MIH);
    __nv_bfloat16* mil = (__nv_bfloat16*)(smem + L::MIL);
    __nv_bfloat16* a1h = (__nv_bfloat16*)(smem + L::A1H);
    __nv_bfloat16* a1l = (__nv_bfloat16*)(smem + L::A1L);
    int*           sidx= (int*)          (smem + L::IDX);

    const int tid  = threadIdx.x;
    const int wid  = tid >> 5, lane = tid & 31;
    const int g    = lane >> 2, tq = lane & 3;
    const int wm   = wid & (MW - 1), wn = wid / MW;

    const uint32_t bA1h = smaddr(a1h), bA1l = smaddr(a1l);
    const uint32_t bW1h = smaddr(w1h), bW1l = smaddr(w1l);
    const uint32_t bW2h = smaddr(w2h), bW2l = smaddr(w2l);
    const uint32_t bMih = smaddr(mih), bMil = smaddr(mil);
    const int oA_SA = OFF_A(lane, L::SA), oB_SA = OFF_B(lane, L::SA);
    const int oA_72 = OFF_A(lane, 72),    oB_72 = OFF_B(lane, 72);

    for (int i = tid; i < L::TOT / 4; i += NTHR)
        reinterpret_cast<uint32_t*>(smem)[i] = 0;
    __syncthreads();

    for (int i = tid; i < F * 64; i += NTHR) {
        int k = i >> 6, n = i & 63;
        __nv_bfloat16 h, l; split_bf16(w1[i], h, l);
        w1h[n * L::SA + k] = h;  w1l[n * L::SA + k] = l;
    }
    for (int i = tid; i < 32 * 128; i += NTHR) {
        int n = i & 127, k = (i >> 7) * 2;
        __nv_bfloat16 h0, l0, h1, l1;
        split_bf16(w2[k * 128 + n], h0, l0);
        split_bf16(w2[(k + 1) * 128 + n], h1, l1);
        *reinterpret_cast<uint32_t*>(&w2h[n * 72 + k]) =
            (uint32_t)__bfloat16_as_ushort(h0) | ((uint32_t)__bfloat16_as_ushort(h1) << 16);
        *reinterpret_cast<uint32_t*>(&w2l[n * 72 + k]) =
            (uint32_t)__bfloat16_as_ushort(l0) | ((uint32_t)__bfloat16_as_ushort(l1) << 16);
    }

    auto stage = [&](int tt, int parity) {
        if (tt >= ntiles) return;
        const int se0 = tt * 128;
        const int scnt = min(128, EE - se0);
        const float* fb = feat + (size_t)se0 * F;
        int* sx = sidx + parity * 256;
        if (scnt == 128) {
            constexpr int NIT = (128 * F + NTHR - 1) / NTHR;
            #pragma unroll
            for (int j = 0; j < NIT; ++j) {
                int i = tid + j * NTHR;
                if (128 * F % NTHR == 0 || i < 128 * F) {
                    int e = i / F, k = i - e * F;
                    __nv_bfloat16 h, l; split_bf16(fb[i], h, l);
                    a1h[e * L::SA + k] = h;  a1l[e * L::SA + k] = l;
                }
            }
            if (tid < 128) { sx[tid] = src[se0 + tid]; sx[128 + tid] = dst[se0 + tid]; }
        } else {
            for (int i = tid; i < scnt * F; i += NTHR) {
                int e = i / F, k = i - e * F;
                __nv_bfloat16 h, l; split_bf16(fb[i], h, l);
                a1h[e * L::SA + k] = h;  a1l[e * L::SA + k] = l;
            }
            if (tid < scnt) { sx[tid] = src[se0 + tid]; sx[128 + tid] = dst[se0 + tid]; }
        }
    };

    int t = blockIdx.x, pb = 0;
    stage(t, 0);
    __syncthreads();

    for (; t < ntiles; t += gridDim.x) {
        const int cnt = min(128, EE - t * 128);
        const int* sx = sidx + pb * 256;

        // ---- GEMM1 ----
        {
            const int mo = wm * RM, no = wn * 32;
            float acc[MT][4][4];
            #pragma unroll
            for (int a = 0; a < MT; ++a)
                #pragma unroll
                for (int b = 0; b < 4; ++b)
                    #pragma unroll
                    for (int c = 0; c < 4; ++c) acc[a][b][c] = 0.f;

            #pragma unroll
            for (int ko = 0; ko < L::KP; ko += 16) {
                uint32_t Ah[MT][4], Al[MT][4];
                #pragma unroll
                for (int mt = 0; mt < MT; ++mt) {
                    const int rb2 = ((mo + mt*16) * L::SA + ko) * 2;
                    ldsm4(Ah[mt], bA1h + rb2 + oA_SA);
                    ldsm4(Al[mt], bA1l + rb2 + oA_SA);
                }
                uint32_t Bh[4][2], Bl[4][2];
                #pragma unroll
                for (int p = 0; p < 2; ++p) {
                    const int nb2 = ((no + p*16) * L::SA + ko) * 2;
                    uint32_t tr[4];
                    ldsm4(tr, bW1h + nb2 + oB_SA);
                    Bh[2*p][0]=tr[0]; Bh[2*p][1]=tr[1]; Bh[2*p+1][0]=tr[2]; Bh[2*p+1][1]=tr[3];
                    ldsm4(tr, bW1l + nb2 + oB_SA);
                    Bl[2*p][0]=tr[0]; Bl[2*p][1]=tr[1]; Bl[2*p+1][0]=tr[2]; Bl[2*p+1][1]=tr[3];
                }
                #pragma unroll
                for (int nt = 0; nt < 4; ++nt)
                    #pragma unroll
                    for (int mt = 0; mt < MT; ++mt) {
                        mma_bf16(acc[mt][nt], Ah[mt], Bh[nt]);
                        mma_bf16(acc[mt][nt], Ah[mt], Bl[nt]);
                        mma_bf16(acc[mt][nt], Al[mt], Bh[nt]);
                    }
            }
            #pragma unroll
            for (int mt = 0; mt < MT; ++mt)
                #pragma unroll
                for (int nt = 0; nt < 4; ++nt) {
                    int r0 = mo + mt*16 + g, col = no + nt*8 + tq*2;
                    uint32_t hi, lo;
                    split_pack2(acc[mt][nt][0], acc[mt][nt][1], hi, lo);
                    *reinterpret_cast<uint32_t*>(&mih[r0*72 + col]) = hi;
                    *reinterpret_cast<uint32_t*>(&mil[r0*72 + col]) = lo;
                    split_pack2(acc[mt][nt][2], acc[mt][nt][3], hi, lo);
                    *reinterpret_cast<uint32_t*>(&mih[(r0+8)*72 + col]) = hi;
                    *reinterpret_cast<uint32_t*>(&mil[(r0+8)*72 + col]) = lo;
                }
        }
        __syncthreads();

        // ---- GEMM2 (K=64) ----
        float acc[MT][8][4];
        {
            const int mo = wm * RM, no = wn * 64;
            #pragma unroll
            for (int a = 0; a < MT; ++a)
                #pragma unroll
                for (int b = 0; b < 8; ++b)
                    #pragma unroll
                    for (int c = 0; c < 4; ++c) acc[a][b][c] = 0.f;

            #pragma unroll
            for (int ko = 0; ko < 64; ko += 16) {
                uint32_t Ah[MT][4], Al[MT][4];
                #pragma unroll
                for (int mt = 0; mt < MT; ++mt) {
                    const int rb2 = ((mo + mt*16) * 72 + ko) * 2;
                    ldsm4(Ah[mt], bMih + rb2 + oA_72);
                    ldsm4(Al[mt], bMil + rb2 + oA_72);
                }
                uint32_t Bh[8][2], Bl[8][2];
                #pragma unroll
                for (int p = 0; p < 4; ++p) {
                    const int nb2 = ((no + p*16) * 72 + ko) * 2;
                    uint32_t tr[4];
                    ldsm4(tr, bW2h + nb2 + oB_72);
                    Bh[2*p][0]=tr[0]; Bh[2*p][1]=tr[1]; Bh[2*p+1][0]=tr[2]; Bh[2*p+1][1]=tr[3];
                    ldsm4(tr, bW2l + nb2 + oB_72);
                    Bl[2*p][0]=tr[0]; Bl[2*p][1]=tr[1]; Bl[2*p+1][0]=tr[2]; Bl[2*p+1][1]=tr[3];
                }
                #pragma unroll
                for (int nt = 0; nt < 8; ++nt)
                    #pragma unroll
                    for (int mt = 0; mt < MT; ++mt) {
                        mma_bf16(acc[mt][nt], Ah[mt], Bh[nt]);
                        mma_bf16(acc[mt][nt], Ah[mt], Bl[nt]);
                        mma_bf16(acc[mt][nt], Al[mt], Bh[nt]);
                    }
            }
        }

        // ---- direct register epilogue ----
        {
            const int no = wn * 64, cb = no + tq * 2;
            #pragma unroll
            for (int mt = 0; mt < MT; ++mt) {
                #pragma unroll
                for (int hf = 0; hf < 2; ++hf) {
                    int e = wm * RM + mt*16 + g + hf*8;
                    if (e < cnt) {
                        int s = sx[e], d = sx[128 + e];
                        const float* xrow = xh + (size_t)s * 128 + cb;
                        float* arow = agg + (size_t)d * 128 + cb;
                        float2 xv[8];
                        #pragma unroll
                        for (int nt = 0; nt < 8; ++nt)
                            xv[nt] = *reinterpret_cast<const float2*>(xrow + nt*8);
                        #pragma unroll
                        for (int nt = 0; nt < 8; ++nt)
                            red_add_v2(arow + nt*8,
                                make_float2(acc[mt][nt][hf*2] * xv[nt].x,
                                            acc[mt][nt][hf*2+1] * xv[nt].y));
                    }
                }
            }
        }

        stage(t + gridDim.x, pb ^ 1);
        __syncthreads();
        pb ^= 1;
    }
}

// ================= node GEMM on HMMA (GN = fused S*h+O affine in staging) ====
template<bool HAS_A2, bool ACT, bool HAS_RES, bool DB, bool GN>
__global__ void __launch_bounds__(512) node_hmma(
    const float* __restrict__ A,  const float* __restrict__ W,
    const float* __restrict__ A2, const float* __restrict__ W2,
    const float* __restrict__ bias, const float* __restrict__ res,
    const int* __restrict__ batchv, const float* __restrict__ Spl,
    const float* __restrict__ Opl,
    float* __restrict__ out, int nrows, int ntiles)
{
    static_assert(!(HAS_A2 && DB), "DB only for single-A variant");
    constexpr int WS = 128 * 136 * 2;
    constexpr int NWP = HAS_A2 ? 4 : 2;
    constexpr int NAP = DB ? 4 : 2;
    extern __shared__ char smem[];
    __nv_bfloat16* wh  = (__nv_bfloat16*)(smem);
    __nv_bfloat16* wl  = (__nv_bfloat16*)(smem + WS);
    __nv_bfloat16* w2h = (__nv_bfloat16*)(smem + 2 * WS);
    __nv_bfloat16* w2l = (__nv_bfloat16*)(smem + 3 * WS);
    float*         bs  = (float*)        (smem + (NWP + NAP) * WS);

    const int tid = threadIdx.x;
    const int wid = tid >> 5, lane = tid & 31;
    const int g = lane >> 2, tq = lane & 3;
    const int wm = wid & 7, wn = wid >> 3;
    const int mo = wm * 16, no = wn * 64;
    const int oA = OFF_A(lane, 136), oB = OFF_B(lane, 136);

    for (int i = tid; i < 64 * 128; i += 512) {
        int n = i & 127, k = (i >> 7) * 2;
        __nv_bfloat16 h0, l0, h1, l1;
        split_bf16(W[k * 128 + n], h0, l0);
        split_bf16(W[(k + 1) * 128 + n], h1, l1);
        *reinterpret_cast<uint32_t*>(&wh[n * 136 + k]) =
            (uint32_t)__bfloat16_as_ushort(h0) | ((uint32_t)__bfloat16_as_ushort(h1) << 16);
        *reinterpret_cast<uint32_t*>(&wl[n * 136 + k]) =
            (uint32_t)__bfloat16_as_ushort(l0) | ((uint32_t)__bfloat16_as_ushort(l1) << 16);
        if (HAS_A2) {
            split_bf16(W2[k * 128 + n], h0, l0);
            split_bf16(W2[(k + 1) * 128 + n], h1, l1);
            *reinterpret_cast<uint32_t*>(&w2h[n * 136 + k]) =
                (uint32_t)__bfloat16_as_ushort(h0) | ((uint32_t)__bfloat16_as_ushort(h1) << 16);
            *reinterpret_cast<uint32_t*>(&w2l[n * 136 + k]) =
                (uint32_t)__bfloat16_as_ushort(l0) | ((uint32_t)__bfloat16_as_ushort(l1) << 16);
        }
    }
    if (tid < 128) bs[tid] = bias[tid];

    auto a_hi = [&](int p) { return (__nv_bfloat16*)(smem + (NWP + p * 2) * WS); };
    auto a_lo = [&](int p) { return (__nv_bfloat16*)(smem + (NWP + p * 2 + 1) * WS); };

    auto stageA = [&](const float* __restrict__ src_, int tt, int p) {
        if (tt >= ntiles) return;
        const int rb = tt * 128;
        __nv_bfloat16* dh = a_hi(p);
        __nv_bfloat16* dl = a_lo(p);
        #pragma unroll 8
        for (int i = tid; i < 128 * 64; i += 512) {
            int e = i >> 6, kp = (i & 63) * 2;
            int r = rb + e;
            float2 v = (r < nrows) ? *reinterpret_cast<const float2*>(&src_[(size_t)r * 128 + kp])
                                   : make_float2(0.f, 0.f);
            if (GN) {
                if (r < nrows) {
                    int b = batchv[r];
                    float2 Sv = *reinterpret_cast<const float2*>(&Spl[b * 128 + kp]);
                    float2 Ov = *reinterpret_cast<const float2*>(&Opl[b * 128 + kp]);
                    v.x = Sv.x * v.x + Ov.x;
                    v.y = Sv.y * v.y + Ov.y;
                }
            }
            uint32_t hi, lo; split_pack2(v.x, v.y, hi, lo);
            *reinterpret_cast<uint32_t*>(&dh[e * 136 + kp]) = hi;
            *reinterpret_cast<uint32_t*>(&dl[e * 136 + kp]) = lo;
        }
    };

    auto run_mma = [&](float acc[8][4], const __nv_bfloat16* ahp, const __nv_bfloat16* alp,
                       const __nv_bfloat16* bhp, const __nv_bfloat16* blp) {
        const uint32_t bAh = smaddr(ahp), bAl = smaddr(alp);
        const uint32_t bBh = smaddr(bhp), bBl = smaddr(blp);
        #pragma unroll
        for (int ko = 0; ko < 128; ko += 16) {
            uint32_t Ah[4], Al[4];
            const int rb2 = (mo * 136 + ko) * 2;
            ldsm4(Ah, bAh + rb2 + oA);
            ldsm4(Al, bAl + rb2 + oA);
            #pragma unroll
            for (int p = 0; p < 4; ++p) {
                const int nb2 = ((no + p*16) * 136 + ko) * 2;
                uint32_t th[4], tl[4];
                ldsm4(th, bBh + nb2 + oB);
                ldsm4(tl, bBl + nb2 + oB);
                uint32_t B0h[2] = {th[0], th[1]}, B1h[2] = {th[2], th[3]};
                uint32_t B0l[2] = {tl[0], tl[1]}, B1l[2] = {tl[2], tl[3]};
                mma_bf16(acc[2*p],   Ah, B0h);
                mma_bf16(acc[2*p],   Ah, B0l);
                mma_bf16(acc[2*p],   Al, B0h);
                mma_bf16(acc[2*p+1], Ah, B1h);
                mma_bf16(acc[2*p+1], Ah, B1l);
                mma_bf16(acc[2*p+1], Al, B1h);
            }
        }
    };

    auto epilogue = [&](float acc[8][4], int rb) {
        #pragma unroll
        for (int nt = 0; nt < 8; ++nt) {
            const int c = no + nt*8 + tq*2;
            const float b0 = bs[c], b1 = bs[c + 1];
            #pragma unroll
            for (int half = 0; half < 2; ++half) {
                int r = rb + mo + g + half*8;
                if (r < nrows) {
                    float v0 = acc[nt][half*2]     + b0;
                    float v1 = acc[nt][half*2 + 1] + b1;
                    if (ACT) { v0 = v0 / (1.f + expf(-v0)); v1 = v1 / (1.f + expf(-v1)); }
                    if (HAS_RES) {
                        float2 rr = *reinterpret_cast<const float2*>(&res[(size_t)r*128 + c]);
                        v0 += rr.x; v1 += rr.y;
                    }
                    *reinterpret_cast<float2*>(&out[(size_t)r*128 + c]) = make_float2(v0, v1);
                }
            }
        }
    };

    if (DB) {
        int t = blockIdx.x, pb = 0;
        stageA(A, t, 0);
        __syncthreads();
        for (; t < ntiles; t += gridDim.x) {
            float acc[8][4];
            #pragma unroll
            for (int b = 0; b < 8; ++b)
                #pragma unroll
                for (int c = 0; c < 4; ++c) acc[b][c] = 0.f;
            run_mma(acc, a_hi(pb), a_lo(pb), wh, wl);
            stageA(A, t + gridDim.x, pb ^ 1);
            epilogue(acc, t * 128);
            pb ^= 1;
            __syncthreads();
        }
    } else {
        __syncthreads();
        for (int t = blockIdx.x; t < ntiles; t += gridDim.x) {
            stageA(A, t, 0);
            __syncthreads();
            float acc[8][4];
            #pragma unroll
            for (int b = 0; b < 8; ++b)
                #pragma unroll
                for (int c = 0; c < 4; ++c) acc[b][c] = 0.f;
            run_mma(acc, a_hi(0), a_lo(0), wh, wl);
            if (HAS_A2) {
                __syncthreads();
                stageA(A2, t, 0);
                __syncthreads();
                run_mma(acc, a_hi(0), a_lo(0), w2h, w2l);
            }
            epilogue(acc, t * 128);
            __syncthreads();
        }
    }
}

// ---------------- zero init ----------------
__global__ void zero_bufs_kernel() {
    int idx = blockIdx.x * blockDim.x + threadIdx.x;
    if (idx < NN*HH) { g_agg1[idx] = 0.f; g_agg2[idx] = 0.f; }
    if (idx < GG*HH) { g_gsum[idx] = 0.f; g_gvar[idx] = 0.f; }
    if (idx < GG)    { g_gcnt[idx] = 0.f; }
}

// ---------------- GraphNorm: segmented reductions (batch is sorted) ----------------
// pass 1: per-graph sums + counts. 128 threads = one column each; 64-row strips;
// running sum flushed once per segment boundary (~64x fewer atomics).
__global__ void __launch_bounds__(128) gn_accum_seg(
    const float* __restrict__ h, const int* __restrict__ batch)
{
    const int n0 = blockIdx.x * 64;
    const int c  = threadIdx.x;
    const int nend = min(n0 + 64, NN);
    int   cur = batch[n0];
    float run = 0.f, runc = 0.f;
    for (int n = n0; n < nend; ++n) {
        int b = batch[n];
        if (b != cur) {
            atomicAdd(&g_gsum[cur*128 + c], run);
            if (c == 0) atomicAdd(&g_gcnt[cur], runc);
            run = 0.f; runc = 0.f; cur = b;
        }
        run  += h[(size_t)n*128 + c];
        runc += 1.f;
    }
    atomicAdd(&g_gsum[cur*128 + c], run);
    if (c == 0) atomicAdd(&g_gcnt[cur], runc);
}

// pass 2: per-graph variance of (h - mean*ms); no centered tensor materialized.
__global__ void __launch_bounds__(128) gn_var_seg(
    const float* __restrict__ h, const int* __restrict__ batch,
    const float* __restrict__ ms)
{
    const int n0 = blockIdx.x * 64;
    const int c  = threadIdx.x;
    const int nend = min(n0 + 64, NN);
    const float msc = ms[c];
    int   cur = batch[n0];
    float mean = g_gsum[cur*128 + c] / fmaxf(g_gcnt[cur], 1.f);
    float run = 0.f;
    for (int n = n0; n < nend; ++n) {
        int b = batch[n];
        if (b != cur) {
            atomicAdd(&g_gvar[cur*128 + c], run);
            run = 0.f; cur = b;
            mean = g_gsum[cur*128 + c] / fmaxf(g_gcnt[cur], 1.f);
        }
        float o = h[(size_t)n*128 + c] - mean * msc;
        run += o * o;
    }
    atomicAdd(&g_gvar[cur*128 + c], run);
}

// pass 3: fold GraphNorm into per-(graph,col) affine: S = nw*istd, O = nb - S*mean*ms.
// S overwrites g_gvar, O overwrites g_gsum.
__global__ void gn_affine(const float* __restrict__ ms,
                          const float* __restrict__ nw, const float* __restrict__ nb)
{
    int idx = blockIdx.x * blockDim.x + threadIdx.x;
    if (idx >= GG*HH) return;
    int b = idx >> 7, c = idx & 127;
    float cnt  = fmaxf(g_gcnt[b], 1.f);
    float mean = g_gsum[idx] / cnt;
    float istd = rsqrtf(g_gvar[idx] / cnt + EPSV);
    float S = nw[c] * istd;
    g_gvar[idx] = S;
    g_gsum[idx] = nb[c] - S * mean * ms[c];
}

// ---------------- host launcher ----------------
static inline void set_smem(const void* f, int bytes) {
    cudaFuncSetAttribute(f, cudaFuncAttributeMaxDynamicSharedMemorySize, bytes);
}

extern "C" void kernel_launch(void* const* d_in, const int* in_sizes, int n_in,
                              void* d_out, int out_size) {
    (void)in_sizes; (void)n_in; (void)out_size;

    const float* x          = (const float*)d_in[0];
    const float* feature1   = (const float*)d_in[1];
    const float* feature2   = (const float*)d_in[2];
    const int*   edge_index = (const int*)  d_in[3];
    const int*   batch      = (const int*)  d_in[4];
    const float* lin_w      = (const float*)d_in[5];
    const float* lin_b      = (const float*)d_in[6];
    const float* f1_w1      = (const float*)d_in[7];
    const float* f1_w2      = (const float*)d_in[8];
    const float* f2_w1      = (const float*)d_in[9];
    const float* f2_w2      = (const float*)d_in[10];
    const float* c1_rel_w   = (const float*)d_in[11];
    const float* c1_rel_b   = (const float*)d_in[12];
    const float* c1_root_w  = (const float*)d_in[13];
    const float* c2_rel_w   = (const float*)d_in[14];
    const float* c2_rel_b   = (const float*)d_in[15];
    const float* c2_root_w  = (const float*)d_in[16];
    const float* lin1_w     = (const float*)d_in[17];
    const float* lin1_b     = (const float*)d_in[18];
    const float* lin2_w     = (const float*)d_in[19];
    const float* lin2_b     = (const float*)d_in[20];
    const float* lincat_w   = (const float*)d_in[21];
    const float* lincat_b   = (const float*)d_in[22];
    const float* norm_w     = (const float*)d_in[23];
    const float* norm_b     = (const float*)d_in[24];
    const float* norm_ms    = (const float*)d_in[25];
    const float* lins_w     = (const float*)d_in[26];
    const float* lins_b     = (const float*)d_in[27];
    const float* final_w    = (const float*)d_in[28];
    const float* final_b    = (const float*)d_in[29];
    float* out = (float*)d_out;

    const int* src = edge_index;
    const int* dst = edge_index + EE;

    float *xh, *agg1, *agg2, *tmp, *h1, *h2, *hA, *hB, *gvar, *gsum;
    cudaGetSymbolAddress((void**)&xh,   g_xh);
    cudaGetSymbolAddress((void**)&agg1, g_agg1);
    cudaGetSymbolAddress((void**)&agg2, g_agg2);
    cudaGetSymbolAddress((void**)&tmp,  g_tmp);
    cudaGetSymbolAddress((void**)&h1,   g_h1);
    cudaGetSymbolAddress((void**)&h2,   g_h2);
    cudaGetSymbolAddress((void**)&hA,   g_hA);
    cudaGetSymbolAddress((void**)&hB,   g_hB);
    cudaGetSymbolAddress((void**)&gvar, g_gvar);
    cudaGetSymbolAddress((void**)&gsum, g_gsum);

    constexpr int WS = 128 * 136 * 2;
    const int N1 = 6 * WS + 512;
    const int N2 = 6 * WS + 512;

    set_smem((const void*)node_hmma<false,true ,false,true ,false>, N1);
    set_smem((const void*)node_hmma<false,true ,true ,true ,false>, N1);
    set_smem((const void*)node_hmma<false,false,false,true ,true >, N1);
    set_smem((const void*)node_hmma<true ,false,false,false,false>, N2);
    set_smem((const void*)node_hmma<true ,false,true ,false,false>, N2);
    set_smem((const void*)edge_fused<FF1,512,1>, EL<FF1>::TOT);
    set_smem((const void*)edge_fused<FF2,256,2>, EL<FF2>::TOT);

    const int EL_GRID = (NN*HH + 255) / 256;
    const int GH_GRID = (GG*HH + 255) / 256;
    const int SEG_GRID = (NN + 63) / 64;    // 782
    const int NT      = (EE + 127) / 128;
    const int NTN     = (NN + 127) / 128;

    // 0) zero accumulators
    zero_bufs_kernel<<<EL_GRID, 256>>>();

    // 1) xh = swish(x @ lin_w + lin_b)
    node_hmma<false,true,false,true,false><<<148, 512, N1>>>(
        x, lin_w, nullptr, nullptr, lin_b, nullptr,
        nullptr, nullptr, nullptr, xh, NN, NTN);

    // 2) fused edge messages
    edge_fused<FF1,512,1><<<148, 512, EL<FF1>::TOT>>>(feature1, f1_w1, f1_w2, xh, src, dst, agg1, NT);
    edge_fused<FF2,256,2><<<296, 256, EL<FF2>::TOT>>>(feature2, f2_w1, f2_w2, xh, src, dst, agg2, NT);

    // 3) conv1
    node_hmma<true,false,false,false,false><<<148, 512, N2>>>(
        agg1, c1_rel_w, xh, c1_root_w, c1_rel_b, nullptr,
        nullptr, nullptr, nullptr, tmp, NN, NTN);
    node_hmma<false,true,false,true,false><<<148, 512, N1>>>(
        tmp, lin1_w, nullptr, nullptr, lin1_b, nullptr,
        nullptr, nullptr, nullptr, h1, NN, NTN);

    // 4) conv2
    node_hmma<true,false,false,false,false><<<148, 512, N2>>>(
        agg2, c2_rel_w, xh, c2_root_w, c2_rel_b, nullptr,
        nullptr, nullptr, nullptr, tmp, NN, NTN);
    node_hmma<false,true,false,true,false><<<148, 512, N1>>>(
        tmp, lin2_w, nullptr, nullptr, lin2_b, nullptr,
        nullptr, nullptr, nullptr, h2, NN, NTN);

    // 5) hA = h1@Wtop + h2@Wbot + lincat_b + xh
    node_hmma<true,false,true,false,false><<<148, 512, N2>>>(
        h1, lincat_w, h2, lincat_w + 128*128, lincat_b, xh,
        nullptr, nullptr, nullptr, hA, NN, NTN);

    // 6) residual stack
    node_hmma<false,true,true,true,false><<<148, 512, N1>>>(
        hA, lins_w + 0*16384, nullptr, nullptr, lins_b + 0*128, hA,
        nullptr, nullptr, nullptr, hB, NN, NTN);
    node_hmma<false,true,true,true,false><<<148, 512, N1>>>(
        hB, lins_w + 1*16384, nullptr, nullptr, lins_b + 1*128, hB,
        nullptr, nullptr, nullptr, hA, NN, NTN);
    node_hmma<false,true,true,true,false><<<148, 512, N1>>>(
        hA, lins_w + 2*16384, nullptr, nullptr, lins_b + 2*128, hA,
        nullptr, nullptr, nullptr, hB, NN, NTN);

    // 7) GraphNorm on hB (segmented; folded into per-(graph,col) affine)
    gn_accum_seg<<<SEG_GRID, 128>>>(hB, batch);
    gn_var_seg  <<<SEG_GRID, 128>>>(hB, batch, norm_ms);
    gn_affine   <<<GH_GRID, 256>>>(norm_ms, norm_w, norm_b);

    // 8) out = (S*hB + O) @ final_w + final_b   (GN affine fused in staging)
    node_hmma<false,false,false,true,true><<<148, 512, N1>>>(
        hB, final_w, nullptr, nullptr, final_b, nullptr,
        batch, gvar, gsum, out, NN, NTN);
}